// round 5
// baseline (speedup 1.0000x reference)
#include <cuda_runtime.h>
#include <cuda_bf16.h>
#include <math.h>
#include <stdint.h>

// ---------------------------------------------------------------------------
// GSDecoder round 5: round-4 architecture (pre-split bf16x3 weights +
// producer-split activations + pure-bf16 cp.async GEMM, BK=32) with the
// B-tile staging indexing bug fixed.
// ---------------------------------------------------------------------------

#define NTOK   4096
#define CDIM   512
#define HEADS  8
#define DHEAD  64
#define LAYERS 8
#define MLPDIM 2048
#define OUTC   56
#define NGAUSS 4

// ------------------------- scratch (device globals) ------------------------
__device__ float g_h   [NTOK * CDIM];
__device__ float g_a   [NTOK * CDIM];
__device__ float g_qkv [NTOK * 3 * CDIM];
__device__ float g_out [NTOK * OUTC];

__device__ __nv_bfloat16 g_ah[NTOK * CDIM],  g_al[NTOK * CDIM];    // LN out
__device__ __nv_bfloat16 g_oh[NTOK * CDIM],  g_ol[NTOK * CDIM];    // attn out
__device__ __nv_bfloat16 g_mh[NTOK * MLPDIM], g_ml[NTOK * MLPDIM]; // gelu out

__device__ __nv_bfloat16 g_wqkv_h[LAYERS * CDIM * 3 * CDIM];
__device__ __nv_bfloat16 g_wqkv_l[LAYERS * CDIM * 3 * CDIM];
__device__ __nv_bfloat16 g_wo_h  [LAYERS * CDIM * CDIM];
__device__ __nv_bfloat16 g_wo_l  [LAYERS * CDIM * CDIM];
__device__ __nv_bfloat16 g_wm1_h [LAYERS * CDIM * MLPDIM];
__device__ __nv_bfloat16 g_wm1_l [LAYERS * CDIM * MLPDIM];
__device__ __nv_bfloat16 g_wm2_h [LAYERS * MLPDIM * CDIM];
__device__ __nv_bfloat16 g_wm2_l [LAYERS * MLPDIM * CDIM];

// ------------------------------ helpers ------------------------------------
__device__ __forceinline__ float gelu_f(float x) {
    float x3 = x * x * x;
    return 0.5f * x * (1.0f + tanhf(0.7978845608028654f * (x + 0.044715f * x3)));
}

__device__ __forceinline__ void ldsm_x4(unsigned* r, unsigned addr) {
    asm volatile("ldmatrix.sync.aligned.m8n8.x4.shared.b16 {%0,%1,%2,%3}, [%4];"
                 : "=r"(r[0]), "=r"(r[1]), "=r"(r[2]), "=r"(r[3]) : "r"(addr));
}
__device__ __forceinline__ void ldsm_x4t(unsigned* r, unsigned addr) {
    asm volatile("ldmatrix.sync.aligned.m8n8.x4.trans.shared.b16 {%0,%1,%2,%3}, [%4];"
                 : "=r"(r[0]), "=r"(r[1]), "=r"(r[2]), "=r"(r[3]) : "r"(addr));
}
__device__ __forceinline__ void ldsm_x2t(unsigned* r, unsigned addr) {
    asm volatile("ldmatrix.sync.aligned.m8n8.x2.trans.shared.b16 {%0,%1}, [%2];"
                 : "=r"(r[0]), "=r"(r[1]) : "r"(addr));
}
__device__ __forceinline__ void mma16816(float* c, const unsigned* a, const unsigned* b) {
    asm volatile("mma.sync.aligned.m16n8k16.row.col.f32.bf16.bf16.f32 "
                 "{%0,%1,%2,%3}, {%4,%5,%6,%7}, {%8,%9}, {%0,%1,%2,%3};"
                 : "+f"(c[0]), "+f"(c[1]), "+f"(c[2]), "+f"(c[3])
                 : "r"(a[0]), "r"(a[1]), "r"(a[2]), "r"(a[3]),
                   "r"(b[0]), "r"(b[1]));
}
__device__ __forceinline__ void cpa16(unsigned dst, const void* src) {
    asm volatile("cp.async.cg.shared.global [%0], [%1], 16;" :: "r"(dst), "l"(src));
}
__device__ __forceinline__ void cpa_commit() {
    asm volatile("cp.async.commit_group;");
}
template <int NWAIT>
__device__ __forceinline__ void cpa_wait() {
    asm volatile("cp.async.wait_group %0;" :: "n"(NWAIT));
}

__device__ __forceinline__ void split4(float4 v, __nv_bfloat16* h, __nv_bfloat16* l) {
    float x0 = v.x, x1 = v.y, x2 = v.z, x3 = v.w;
    __nv_bfloat16 h0 = __float2bfloat16_rn(x0);
    __nv_bfloat16 h1 = __float2bfloat16_rn(x1);
    __nv_bfloat16 h2 = __float2bfloat16_rn(x2);
    __nv_bfloat16 h3 = __float2bfloat16_rn(x3);
    __nv_bfloat16 l0 = __float2bfloat16_rn(x0 - __bfloat162float(h0));
    __nv_bfloat16 l1 = __float2bfloat16_rn(x1 - __bfloat162float(h1));
    __nv_bfloat16 l2 = __float2bfloat16_rn(x2 - __bfloat162float(h2));
    __nv_bfloat16 l3 = __float2bfloat16_rn(x3 - __bfloat162float(h3));
    ((__nv_bfloat162*)h)[0] = __halves2bfloat162(h0, h1);
    ((__nv_bfloat162*)h)[1] = __halves2bfloat162(h2, h3);
    ((__nv_bfloat162*)l)[0] = __halves2bfloat162(l0, l1);
    ((__nv_bfloat162*)l)[1] = __halves2bfloat162(l2, l3);
}

__device__ __forceinline__ void pack_hl(float x, float y, unsigned& hi, unsigned& lo) {
    __nv_bfloat16 hx = __float2bfloat16_rn(x);
    __nv_bfloat16 hy = __float2bfloat16_rn(y);
    __nv_bfloat16 lx = __float2bfloat16_rn(x - __bfloat162float(hx));
    __nv_bfloat16 ly = __float2bfloat16_rn(y - __bfloat162float(hy));
    __nv_bfloat162 H = __halves2bfloat162(hx, hy);
    __nv_bfloat162 L = __halves2bfloat162(lx, ly);
    hi = *(unsigned*)&H;
    lo = *(unsigned*)&L;
}

// --------------------------- weight pre-split ------------------------------
__global__ void wsplit_kernel(const float* __restrict__ src,
                              __nv_bfloat16* __restrict__ h,
                              __nv_bfloat16* __restrict__ l, int n4)
{
    int i = blockIdx.x * 256 + threadIdx.x;
    if (i < n4) {
        float4 v = ((const float4*)src)[i];
        split4(v, h + (size_t)i * 4, l + (size_t)i * 4);
    }
}

// ------------------------------ embed + PE ---------------------------------
__global__ void embed_kernel(const float* __restrict__ feats,
                             const int*   __restrict__ coords,
                             const float* __restrict__ ex,
                             const float* __restrict__ ey,
                             const float* __restrict__ ez,
                             const float* __restrict__ w_in,
                             const float* __restrict__ b_in)
{
    int n = blockIdx.x;
    int c = threadIdx.x;
    const float* f = feats + (size_t)n * 8;
    float acc = b_in[c];
#pragma unroll
    for (int l = 0; l < 8; l++) acc += f[l] * w_in[l * CDIM + c];

    int cx = coords[n * 4 + 1];
    int cy = coords[n * 4 + 2];
    int cz = coords[n * 4 + 3];
    float pe;
    if (c < 170)      pe = ex[cx * 170 + c];
    else if (c < 340) pe = ey[cy * 170 + (c - 170)];
    else              pe = ez[cz * 172 + (c - 340)];
    g_h[(size_t)n * CDIM + c] = acc + pe;
}

// ------------------------------ layernorm ----------------------------------
__global__ void __launch_bounds__(256)
ln_kernel(const float* __restrict__ x,
          const float* __restrict__ g,
          const float* __restrict__ b,
          float* __restrict__ of,
          __nv_bfloat16* __restrict__ oh,
          __nv_bfloat16* __restrict__ ol,
          float eps, int has_gb)
{
    int n   = blockIdx.x;
    int tid = threadIdx.x;
    const float* xr = x + (size_t)n * CDIM;
    float v0 = xr[tid], v1 = xr[tid + 256];
    float s  = v0 + v1;
    float s2 = v0 * v0 + v1 * v1;
#pragma unroll
    for (int off = 16; off; off >>= 1) {
        s  += __shfl_xor_sync(0xffffffffu, s,  off);
        s2 += __shfl_xor_sync(0xffffffffu, s2, off);
    }
    __shared__ float sh[16];
    __shared__ float stats[2];
    int wid = tid >> 5, lane = tid & 31;
    if (lane == 0) { sh[wid] = s; sh[wid + 8] = s2; }
    __syncthreads();
    if (tid == 0) {
        float ts = 0.f, ts2 = 0.f;
#pragma unroll
        for (int i = 0; i < 8; i++) { ts += sh[i]; ts2 += sh[i + 8]; }
        float mean = ts * (1.0f / 512.0f);
        float var  = ts2 * (1.0f / 512.0f) - mean * mean;
        if (var < 0.f) var = 0.f;
        stats[0] = mean;
        stats[1] = rsqrtf(var + eps);
    }
    __syncthreads();
    float mean = stats[0], r = stats[1];
    float o0 = (v0 - mean) * r;
    float o1 = (v1 - mean) * r;
    if (has_gb) {
        o0 = o0 * g[tid]       + b[tid];
        o1 = o1 * g[tid + 256] + b[tid + 256];
    }
    size_t base = (size_t)n * CDIM;
    if (of) { of[base + tid] = o0; of[base + tid + 256] = o1; }
    if (oh) {
        __nv_bfloat16 h0 = __float2bfloat16_rn(o0);
        __nv_bfloat16 h1 = __float2bfloat16_rn(o1);
        oh[base + tid]       = h0;
        oh[base + tid + 256] = h1;
        ol[base + tid]       = __float2bfloat16_rn(o0 - __bfloat162float(h0));
        ol[base + tid + 256] = __float2bfloat16_rn(o1 - __bfloat162float(h1));
    }
}

// ----------------- pure-bf16 tensor-core GEMM (bf16x3) ---------------------
// C = epi( Ah@Bh + Al@Bh + Ah@Bl + bias )
// epi 0: store fp32 Cf; epi 1: Cf += residual; epi 2: gelu -> Ch/Cl bf16
#define BM 128
#define BN 128
#define BK2 32
#define ASTR2 40
#define BSTR2 136
#define A_PL (128 * ASTR2)
#define B_PL (32 * BSTR2)
#define STG  (2 * A_PL + 2 * B_PL)
#define GSMEM_BYTES (2 * STG * 2)

__global__ void __launch_bounds__(256, 1)
gemm_v2_kernel(const __nv_bfloat16* __restrict__ Ah, const __nv_bfloat16* __restrict__ Al,
               const __nv_bfloat16* __restrict__ Bh, const __nv_bfloat16* __restrict__ Bl,
               const float* __restrict__ bias, float* __restrict__ Cf,
               __nv_bfloat16* __restrict__ Ch, __nv_bfloat16* __restrict__ Cl,
               int M, int N, int K, int epi)
{
    extern __shared__ __align__(16) __nv_bfloat16 smem2[];

    const int tid  = threadIdx.x;
    const int wid  = tid >> 5;
    const int lane = tid & 31;
    const int n0 = blockIdx.x * BN;
    const int m0 = blockIdx.y * BM;
    const int wm = (wid >> 2) * 64;
    const int wn = (wid & 3) * 32;

    float acc[4][4][4];
#pragma unroll
    for (int i = 0; i < 4; i++)
#pragma unroll
        for (int j = 0; j < 4; j++)
#pragma unroll
            for (int k = 0; k < 4; k++) acc[i][j][k] = 0.f;

    // A: 128 rows x 32 elems (4 chunks/row); thread -> rows tid>>2, +64
    const int a_row = tid >> 2,  a_off = (tid & 3) << 3;
    // B (FIXED): 32 rows x 128 elems (16 chunks/row); thread -> row tid>>3,
    // columns (tid&7)*16 and (tid&7)*16+8
    const int b_row = tid >> 3,  b_c = (tid & 7) << 4;

    auto stage = [&](int s, int k0) {
        __nv_bfloat16* base = smem2 + s * STG;
#pragma unroll
        for (int p = 0; p < 2; p++) {
            const __nv_bfloat16* src = p ? Al : Ah;
            __nv_bfloat16* d = base + p * A_PL;
            cpa16((unsigned)__cvta_generic_to_shared(d + a_row * ASTR2 + a_off),
                  src + (size_t)(m0 + a_row) * K + k0 + a_off);
            cpa16((unsigned)__cvta_generic_to_shared(d + (a_row + 64) * ASTR2 + a_off),
                  src + (size_t)(m0 + a_row + 64) * K + k0 + a_off);
        }
#pragma unroll
        for (int p = 0; p < 2; p++) {
            const __nv_bfloat16* src = p ? Bl : Bh;
            __nv_bfloat16* d = base + 2 * A_PL + p * B_PL;
            cpa16((unsigned)__cvta_generic_to_shared(d + b_row * BSTR2 + b_c),
                  src + (size_t)(k0 + b_row) * N + n0 + b_c);
            cpa16((unsigned)__cvta_generic_to_shared(d + b_row * BSTR2 + b_c + 8),
                  src + (size_t)(k0 + b_row) * N + n0 + b_c + 8);
        }
        cpa_commit();
    };

    stage(0, 0);
    const int KT = K / BK2;
    for (int kt = 0; kt < KT; kt++) {
        int buf = kt & 1;
        if (kt + 1 < KT) { stage(buf ^ 1, (kt + 1) * BK2); cpa_wait<1>(); }
        else             { cpa_wait<0>(); }
        __syncthreads();

        __nv_bfloat16* base = smem2 + buf * STG;
        unsigned aH = (unsigned)__cvta_generic_to_shared(
            base + (wm + (lane & 15)) * ASTR2 + ((lane >> 4) << 3));
        unsigned aL = aH + A_PL * 2;
        unsigned bH = (unsigned)__cvta_generic_to_shared(
            base + 2 * A_PL + (lane & 15) * BSTR2 + wn);
        unsigned bL = bH + B_PL * 2;

#pragma unroll
        for (int ks = 0; ks < 2; ks++) {
            unsigned ah[4][4], al4[4][4], bh[4][2], bl4[4][2];
#pragma unroll
            for (int mb = 0; mb < 4; mb++) {
                unsigned off = (unsigned)(mb * 16 * ASTR2 + ks * 16) * 2;
                ldsm_x4(ah[mb],  aH + off);
                ldsm_x4(al4[mb], aL + off);
            }
#pragma unroll
            for (int nb = 0; nb < 4; nb++) {
                unsigned off = (unsigned)(ks * 16 * BSTR2) * 2 + nb * 16;
                ldsm_x2t(bh[nb],  bH + off);
                ldsm_x2t(bl4[nb], bL + off);
            }
#pragma unroll
            for (int mb = 0; mb < 4; mb++)
#pragma unroll
                for (int nb = 0; nb < 4; nb++)
                    mma16816(acc[mb][nb], ah[mb], bh[nb]);
#pragma unroll
            for (int mb = 0; mb < 4; mb++)
#pragma unroll
                for (int nb = 0; nb < 4; nb++)
                    mma16816(acc[mb][nb], al4[mb], bh[nb]);
#pragma unroll
            for (int mb = 0; mb < 4; mb++)
#pragma unroll
                for (int nb = 0; nb < 4; nb++)
                    mma16816(acc[mb][nb], ah[mb], bl4[nb]);
        }
        __syncthreads();
    }

    // ---- epilogue ----
#pragma unroll
    for (int mb = 0; mb < 4; mb++) {
        int m = m0 + wm + mb * 16 + (lane >> 2);
#pragma unroll
        for (int nb = 0; nb < 4; nb++) {
            int n = n0 + wn + nb * 8 + ((lane & 3) << 1);
            float2 bv = *(const float2*)(bias + n);
            float c0 = acc[mb][nb][0] + bv.x;
            float c1 = acc[mb][nb][1] + bv.y;
            float c2 = acc[mb][nb][2] + bv.x;
            float c3 = acc[mb][nb][3] + bv.y;
            if (epi == 2) {
                c0 = gelu_f(c0); c1 = gelu_f(c1);
                c2 = gelu_f(c2); c3 = gelu_f(c3);
                unsigned h0, l0, h1, l1;
                pack_hl(c0, c1, h0, l0);
                pack_hl(c2, c3, h1, l1);
                *(unsigned*)(Ch + (size_t)m * N + n)       = h0;
                *(unsigned*)(Cl + (size_t)m * N + n)       = l0;
                *(unsigned*)(Ch + (size_t)(m + 8) * N + n) = h1;
                *(unsigned*)(Cl + (size_t)(m + 8) * N + n) = l1;
            } else {
                float* p0 = Cf + (size_t)m * N + n;
                float* p1 = Cf + (size_t)(m + 8) * N + n;
                if (epi == 1) {
                    float2 r0 = *(float2*)p0;
                    float2 r1 = *(float2*)p1;
                    c0 += r0.x; c1 += r0.y; c2 += r1.x; c3 += r1.y;
                }
                *(float2*)p0 = make_float2(c0, c1);
                *(float2*)p1 = make_float2(c2, c3);
            }
        }
    }
}

// ------------------- flash attention on tensor cores -----------------------
#define ASTR 88
#define AQH  0
#define AQL  (64 * ASTR)
#define AKH  (2 * 64 * ASTR)
#define AKL  (3 * 64 * ASTR)
#define AVH  (4 * 64 * ASTR)
#define AVL  (5 * 64 * ASTR)
#define ATT_SMEM (6 * 64 * ASTR * 2)

__global__ void __launch_bounds__(128)
attn_mma_kernel(const float* __restrict__ qkv,
                __nv_bfloat16* __restrict__ oh,
                __nv_bfloat16* __restrict__ ol)
{
    extern __shared__ __align__(16) __nv_bfloat16 sm[];

    const int tid  = threadIdx.x;
    const int wid  = tid >> 5;
    const int lane = tid & 31;
    const int qt = blockIdx.x, h = blockIdx.y, w = blockIdx.z;
    const int tok0 = w * 512;
    const int q0   = qt * 64;
    const int qoff = h * DHEAD;
    const int koff = CDIM + h * DHEAD;
    const int voff = 2 * CDIM + h * DHEAD;
    const int wm   = wid * 16;

#pragma unroll
    for (int i = 0; i < 8; i++) {
        int idx = tid + i * 128;
        int r = idx >> 4, c4 = (idx & 15) << 2;
        float4 v = *(const float4*)(qkv + (size_t)(tok0 + q0 + r) * (3 * CDIM) + qoff + c4);
        v.x *= 0.125f; v.y *= 0.125f; v.z *= 0.125f; v.w *= 0.125f;
        split4(v, &sm[AQH + r * ASTR + c4], &sm[AQL + r * ASTR + c4]);
    }
    __syncthreads();

    unsigned qh[4][4], ql[4][4];
    {
        unsigned baseH = (unsigned)__cvta_generic_to_shared(&sm[AQH]);
        unsigned baseL = (unsigned)__cvta_generic_to_shared(&sm[AQL]);
        int row = wm + (lane & 15);
        int coloff = (lane >> 4) << 3;
#pragma unroll
        for (int ks = 0; ks < 4; ks++) {
            unsigned off = (unsigned)(row * ASTR + ks * 16 + coloff) * 2;
            ldsm_x4(qh[ks], baseH + off);
            ldsm_x4(ql[ks], baseL + off);
        }
    }

    float m0 = -1e30f, m1 = -1e30f, l0 = 0.f, l1 = 0.f;
    float oacc[8][4];
#pragma unroll
    for (int i = 0; i < 8; i++)
#pragma unroll
        for (int j = 0; j < 4; j++) oacc[i][j] = 0.f;

    const unsigned bKH = (unsigned)__cvta_generic_to_shared(&sm[AKH]);
    const unsigned bKL = (unsigned)__cvta_generic_to_shared(&sm[AKL]);
    const unsigned bVH = (unsigned)__cvta_generic_to_shared(&sm[AVH]);
    const unsigned bVL = (unsigned)__cvta_generic_to_shared(&sm[AVL]);

    const int k_key  = ((lane >> 4) << 3) + (lane & 7);
    const int k_kc   = ((lane >> 3) & 1) << 3;
    const int v_kr   = (((lane >> 3) & 1) << 3) + (lane & 7);
    const int v_col  = (lane >> 4) << 3;

    for (int kt = 0; kt < 8; kt++) {
        __syncthreads();
#pragma unroll
        for (int i = 0; i < 8; i++) {
            int idx = tid + i * 128;
            int r = idx >> 4, c4 = (idx & 15) << 2;
            size_t rowb = (size_t)(tok0 + kt * 64 + r) * (3 * CDIM);
            float4 vk = *(const float4*)(qkv + rowb + koff + c4);
            split4(vk, &sm[AKH + r * ASTR + c4], &sm[AKL + r * ASTR + c4]);
            float4 vv = *(const float4*)(qkv + rowb + voff + c4);
            split4(vv, &sm[AVH + r * ASTR + c4], &sm[AVL + r * ASTR + c4]);
        }
        __syncthreads();

        float s[8][4];
#pragma unroll
        for (int i = 0; i < 8; i++)
#pragma unroll
            for (int j = 0; j < 4; j++) s[i][j] = 0.f;

#pragma unroll
        for (int p = 0; p < 4; p++) {
#pragma unroll
            for (int ks = 0; ks < 4; ks++) {
                unsigned kb_h[4], kb_l[4];
                unsigned off = (unsigned)((p * 16 + k_key) * ASTR + ks * 16 + k_kc) * 2;
                ldsm_x4(kb_h, bKH + off);
                ldsm_x4(kb_l, bKL + off);
                mma16816(s[2 * p],     qh[ks], &kb_h[0]);
                mma16816(s[2 * p],     ql[ks], &kb_h[0]);
                mma16816(s[2 * p],     qh[ks], &kb_l[0]);
                mma16816(s[2 * p + 1], qh[ks], &kb_h[2]);
                mma16816(s[2 * p + 1], ql[ks], &kb_h[2]);
                mma16816(s[2 * p + 1], qh[ks], &kb_l[2]);
            }
        }

        float mx0 = -1e30f, mx1 = -1e30f;
#pragma unroll
        for (int nb = 0; nb < 8; nb++) {
            mx0 = fmaxf(mx0, fmaxf(s[nb][0], s[nb][1]));
            mx1 = fmaxf(mx1, fmaxf(s[nb][2], s[nb][3]));
        }
        mx0 = fmaxf(mx0, __shfl_xor_sync(0xffffffffu, mx0, 1));
        mx0 = fmaxf(mx0, __shfl_xor_sync(0xffffffffu, mx0, 2));
        mx1 = fmaxf(mx1, __shfl_xor_sync(0xffffffffu, mx1, 1));
        mx1 = fmaxf(mx1, __shfl_xor_sync(0xffffffffu, mx1, 2));

        float nm0 = fmaxf(m0, mx0);
        float nm1 = fmaxf(m1, mx1);
        float al0 = __expf(m0 - nm0);
        float al1 = __expf(m1 - nm1);
        m0 = nm0; m1 = nm1;

        float sum0 = 0.f, sum1 = 0.f;
#pragma unroll
        for (int nb = 0; nb < 8; nb++) {
            s[nb][0] = __expf(s[nb][0] - nm0);
            s[nb][1] = __expf(s[nb][1] - nm0);
            s[nb][2] = __expf(s[nb][2] - nm1);
            s[nb][3] = __expf(s[nb][3] - nm1);
            sum0 += s[nb][0] + s[nb][1];
            sum1 += s[nb][2] + s[nb][3];
        }
        sum0 += __shfl_xor_sync(0xffffffffu, sum0, 1);
        sum0 += __shfl_xor_sync(0xffffffffu, sum0, 2);
        sum1 += __shfl_xor_sync(0xffffffffu, sum1, 1);
        sum1 += __shfl_xor_sync(0xffffffffu, sum1, 2);
        l0 = l0 * al0 + sum0;
        l1 = l1 * al1 + sum1;

#pragma unroll
        for (int nb = 0; nb < 8; nb++) {
            oacc[nb][0] *= al0; oacc[nb][1] *= al0;
            oacc[nb][2] *= al1; oacc[nb][3] *= al1;
        }

#pragma unroll
        for (int kk = 0; kk < 4; kk++) {
            unsigned pa_h[4], pa_l[4];
            pack_hl(s[2 * kk][0],     s[2 * kk][1],     pa_h[0], pa_l[0]);
            pack_hl(s[2 * kk][2],     s[2 * kk][3],     pa_h[1], pa_l[1]);
            pack_hl(s[2 * kk + 1][0], s[2 * kk + 1][1], pa_h[2], pa_l[2]);
            pack_hl(s[2 * kk + 1][2], s[2 * kk + 1][3], pa_h[3], pa_l[3]);
#pragma unroll
            for (int p = 0; p < 4; p++) {
                unsigned vb_h[4], vb_l[4];
                unsigned off = (unsigned)((kk * 16 + v_kr) * ASTR + p * 16 + v_col) * 2;
                ldsm_x4t(vb_h, bVH + off);
                ldsm_x4t(vb_l, bVL + off);
                mma16816(oacc[2 * p],     pa_h, &vb_h[0]);
                mma16816(oacc[2 * p],     pa_l, &vb_h[0]);
                mma16816(oacc[2 * p],     pa_h, &vb_l[0]);
                mma16816(oacc[2 * p + 1], pa_h, &vb_h[2]);
                mma16816(oacc[2 * p + 1], pa_l, &vb_h[2]);
                mma16816(oacc[2 * p + 1], pa_h, &vb_l[2]);
            }
        }
    }

    float i0 = 1.0f / l0, i1 = 1.0f / l1;
    int r0  = tok0 + q0 + wm + (lane >> 2);
    int col = h * DHEAD + ((lane & 3) << 1);
#pragma unroll
    for (int nb = 0; nb < 8; nb++) {
        unsigned h0, lo0, h1, lo1;
        pack_hl(oacc[nb][0] * i0, oacc[nb][1] * i0, h0, lo0);
        pack_hl(oacc[nb][2] * i1, oacc[nb][3] * i1, h1, lo1);
        size_t p0 = (size_t)r0 * CDIM + col + nb * 8;
        size_t p1 = (size_t)(r0 + 8) * CDIM + col + nb * 8;
        *(unsigned*)(oh + p0) = h0;
        *(unsigned*)(ol + p0) = lo0;
        *(unsigned*)(oh + p1) = h1;
        *(unsigned*)(ol + p1) = lo1;
    }
}

// ----------------------------- out head ------------------------------------
__global__ void outhead_kernel(const float* __restrict__ a,
                               const float* __restrict__ w,
                               const float* __restrict__ b)
{
    __shared__ float row[CDIM];
    int n = blockIdx.x;
    for (int i = threadIdx.x; i < CDIM; i += 64)
        row[i] = a[(size_t)n * CDIM + i];
    __syncthreads();
    int oc = threadIdx.x;
    if (oc < OUTC) {
        float acc = b[oc];
#pragma unroll 8
        for (int k = 0; k < CDIM; k++)
            acc += row[k] * w[k * OUTC + oc];
        g_out[n * OUTC + oc] = acc;
    }
}

// ---------------------------- postprocess ----------------------------------
__global__ void post_kernel(const int* __restrict__ coords,
                            const float* __restrict__ perturb,
                            float* __restrict__ out)
{
    int idx = blockIdx.x * 256 + threadIdx.x;
    if (idx >= NTOK * NGAUSS) return;
    int n = idx >> 2, g = idx & 3;
    const float* r = g_out + n * OUTC;
#pragma unroll
    for (int j = 0; j < 3; j++) {
        float off = tanhf(r[g * 3 + j] + perturb[g * 3 + j]) * 4.8828125e-4f;
        float xb  = ((float)coords[n * 4 + 1 + j] + 0.5f) * 0.0625f;
        out[idx * 3 + j]          = xb + off;
        out[49152 + idx * 3 + j]  = r[12 + g * 3 + j];
        out[98304 + idx * 3 + j]  = r[24 + g * 3 + j];
    }
#pragma unroll
    for (int j = 0; j < 4; j++)
        out[147456 + idx * 4 + j] = r[36 + g * 4 + j];
    out[212992 + idx] = r[52 + g];
}

// ------------------------------- launch ------------------------------------
extern "C" void kernel_launch(void* const* d_in, const int* in_sizes, int n_in,
                              void* d_out, int out_size)
{
    const float* feats   = (const float*)d_in[0];
    const int*   coords  = (const int*)  d_in[1];
    const float* emb_x   = (const float*)d_in[2];
    const float* emb_y   = (const float*)d_in[3];
    const float* emb_z   = (const float*)d_in[4];
    const float* w_in    = (const float*)d_in[5];
    const float* b_in    = (const float*)d_in[6];
    const float* ln1_g   = (const float*)d_in[7];
    const float* ln1_b   = (const float*)d_in[8];
    const float* w_qkv   = (const float*)d_in[9];
    const float* b_qkv   = (const float*)d_in[10];
    const float* w_o     = (const float*)d_in[11];
    const float* b_o     = (const float*)d_in[12];
    const float* ln2_g   = (const float*)d_in[13];
    const float* ln2_b   = (const float*)d_in[14];
    const float* w_m1    = (const float*)d_in[15];
    const float* b_m1    = (const float*)d_in[16];
    const float* w_m2    = (const float*)d_in[17];
    const float* b_m2    = (const float*)d_in[18];
    const float* w_out   = (const float*)d_in[19];
    const float* b_out   = (const float*)d_in[20];
    const float* perturb = (const float*)d_in[21];
    float* out = (float*)d_out;

    float *ph, *pa, *pqkv;
    __nv_bfloat16 *pah, *pal, *poh, *pol, *pmh, *pml;
    __nv_bfloat16 *pwqh, *pwql, *pwoh, *pwol, *pw1h, *pw1l, *pw2h, *pw2l;
    cudaGetSymbolAddress((void**)&ph,   g_h);
    cudaGetSymbolAddress((void**)&pa,   g_a);
    cudaGetSymbolAddress((void**)&pqkv, g_qkv);
    cudaGetSymbolAddress((void**)&pah,  g_ah);
    cudaGetSymbolAddress((void**)&pal,  g_al);
    cudaGetSymbolAddress((void**)&poh,  g_oh);
    cudaGetSymbolAddress((void**)&pol,  g_ol);
    cudaGetSymbolAddress((void**)&pmh,  g_mh);
    cudaGetSymbolAddress((void**)&pml,  g_ml);
    cudaGetSymbolAddress((void**)&pwqh, g_wqkv_h);
    cudaGetSymbolAddress((void**)&pwql, g_wqkv_l);
    cudaGetSymbolAddress((void**)&pwoh, g_wo_h);
    cudaGetSymbolAddress((void**)&pwol, g_wo_l);
    cudaGetSymbolAddress((void**)&pw1h, g_wm1_h);
    cudaGetSymbolAddress((void**)&pw1l, g_wm1_l);
    cudaGetSymbolAddress((void**)&pw2h, g_wm2_h);
    cudaGetSymbolAddress((void**)&pw2l, g_wm2_l);

    cudaFuncSetAttribute(attn_mma_kernel,
                         cudaFuncAttributeMaxDynamicSharedMemorySize, ATT_SMEM);
    cudaFuncSetAttribute(gemm_v2_kernel,
                         cudaFuncAttributeMaxDynamicSharedMemorySize, GSMEM_BYTES);

    {
        int n4q = LAYERS * CDIM * 3 * CDIM / 4;
        int n4o = LAYERS * CDIM * CDIM / 4;
        int n4m = LAYERS * CDIM * MLPDIM / 4;
        wsplit_kernel<<<(n4q + 255) / 256, 256>>>(w_qkv, pwqh, pwql, n4q);
        wsplit_kernel<<<(n4o + 255) / 256, 256>>>(w_o,   pwoh, pwol, n4o);
        wsplit_kernel<<<(n4m + 255) / 256, 256>>>(w_m1,  pw1h, pw1l, n4m);
        wsplit_kernel<<<(n4m + 255) / 256, 256>>>(w_m2,  pw2h, pw2l, n4m);
    }

    embed_kernel<<<NTOK, CDIM>>>(feats, coords, emb_x, emb_y, emb_z, w_in, b_in);

    for (int l = 0; l < LAYERS; l++) {
        ln_kernel<<<NTOK, 256>>>(ph, ln1_g + l * CDIM, ln1_b + l * CDIM,
                                 nullptr, pah, pal, 1e-6f, 1);
        gemm_v2_kernel<<<dim3(3 * CDIM / BN, NTOK / BM), 256, GSMEM_BYTES>>>(
            pah, pal,
            pwqh + (size_t)l * CDIM * 3 * CDIM, pwql + (size_t)l * CDIM * 3 * CDIM,
            b_qkv + l * 3 * CDIM, pqkv, nullptr, nullptr,
            NTOK, 3 * CDIM, CDIM, 0);
        attn_mma_kernel<<<dim3(8, HEADS, 8), 128, ATT_SMEM>>>(pqkv, poh, pol);
        gemm_v2_kernel<<<dim3(CDIM / BN, NTOK / BM), 256, GSMEM_BYTES>>>(
            poh, pol,
            pwoh + (size_t)l * CDIM * CDIM, pwol + (size_t)l * CDIM * CDIM,
            b_o + l * CDIM, ph, nullptr, nullptr,
            NTOK, CDIM, CDIM, 1);
        ln_kernel<<<NTOK, 256>>>(ph, ln2_g + l * CDIM, ln2_b + l * CDIM,
                                 nullptr, pah, pal, 1e-6f, 1);
        gemm_v2_kernel<<<dim3(MLPDIM / BN, NTOK / BM), 256, GSMEM_BYTES>>>(
            pah, pal,
            pw1h + (size_t)l * CDIM * MLPDIM, pw1l + (size_t)l * CDIM * MLPDIM,
            b_m1 + l * MLPDIM, nullptr, pmh, pml,
            NTOK, MLPDIM, CDIM, 2);
        gemm_v2_kernel<<<dim3(CDIM / BN, NTOK / BM), 256, GSMEM_BYTES>>>(
            pmh, pml,
            pw2h + (size_t)l * MLPDIM * CDIM, pw2l + (size_t)l * MLPDIM * CDIM,
            b_m2 + l * CDIM, ph, nullptr, nullptr,
            NTOK, CDIM, MLPDIM, 1);
    }

    ln_kernel<<<NTOK, 256>>>(ph, nullptr, nullptr, pa, nullptr, nullptr, 1e-5f, 0);
    outhead_kernel<<<NTOK, 64>>>(pa, w_out, b_out);
    post_kernel<<<(NTOK * NGAUSS + 255) / 256, 256>>>(coords, perturb, out);
}

// round 7
// speedup vs baseline: 1.0716x; 1.0716x over previous
#include <cuda_runtime.h>
#include <cuda_bf16.h>
#include <math.h>
#include <stdint.h>

// ---------------------------------------------------------------------------
// GSDecoder round 7: round-5 architecture (pre-split bf16x3, cp.async GEMM
// BK=32) with the GEMM restructured for 2 CTAs/SM (launch_bounds(256,2),
// reduced live registers). tcgen05 removed (toolchain targets compute_100).
// ---------------------------------------------------------------------------

#define NTOK   4096
#define CDIM   512
#define HEADS  8
#define DHEAD  64
#define LAYERS 8
#define MLPDIM 2048
#define OUTC   56
#define NGAUSS 4

// ------------------------- scratch (device globals) ------------------------
__device__ float g_h   [NTOK * CDIM];
__device__ float g_a   [NTOK * CDIM];
__device__ float g_qkv [NTOK * 3 * CDIM];
__device__ float g_out [NTOK * OUTC];

__device__ __nv_bfloat16 g_ah[NTOK * CDIM],  g_al[NTOK * CDIM];
__device__ __nv_bfloat16 g_oh[NTOK * CDIM],  g_ol[NTOK * CDIM];
__device__ __nv_bfloat16 g_mh[NTOK * MLPDIM], g_ml[NTOK * MLPDIM];

__device__ __nv_bfloat16 g_wqkv_h[LAYERS * CDIM * 3 * CDIM];
__device__ __nv_bfloat16 g_wqkv_l[LAYERS * CDIM * 3 * CDIM];
__device__ __nv_bfloat16 g_wo_h  [LAYERS * CDIM * CDIM];
__device__ __nv_bfloat16 g_wo_l  [LAYERS * CDIM * CDIM];
__device__ __nv_bfloat16 g_wm1_h [LAYERS * CDIM * MLPDIM];
__device__ __nv_bfloat16 g_wm1_l [LAYERS * CDIM * MLPDIM];
__device__ __nv_bfloat16 g_wm2_h [LAYERS * MLPDIM * CDIM];
__device__ __nv_bfloat16 g_wm2_l [LAYERS * MLPDIM * CDIM];

// ------------------------------ helpers ------------------------------------
__device__ __forceinline__ float gelu_f(float x) {
    float x3 = x * x * x;
    return 0.5f * x * (1.0f + tanhf(0.7978845608028654f * (x + 0.044715f * x3)));
}

__device__ __forceinline__ void ldsm_x4(unsigned* r, unsigned addr) {
    asm volatile("ldmatrix.sync.aligned.m8n8.x4.shared.b16 {%0,%1,%2,%3}, [%4];"
                 : "=r"(r[0]), "=r"(r[1]), "=r"(r[2]), "=r"(r[3]) : "r"(addr));
}
__device__ __forceinline__ void ldsm_x4t(unsigned* r, unsigned addr) {
    asm volatile("ldmatrix.sync.aligned.m8n8.x4.trans.shared.b16 {%0,%1,%2,%3}, [%4];"
                 : "=r"(r[0]), "=r"(r[1]), "=r"(r[2]), "=r"(r[3]) : "r"(addr));
}
__device__ __forceinline__ void ldsm_x2t(unsigned* r, unsigned addr) {
    asm volatile("ldmatrix.sync.aligned.m8n8.x2.trans.shared.b16 {%0,%1}, [%2];"
                 : "=r"(r[0]), "=r"(r[1]) : "r"(addr));
}
__device__ __forceinline__ void mma16816(float* c, const unsigned* a, const unsigned* b) {
    asm volatile("mma.sync.aligned.m16n8k16.row.col.f32.bf16.bf16.f32 "
                 "{%0,%1,%2,%3}, {%4,%5,%6,%7}, {%8,%9}, {%0,%1,%2,%3};"
                 : "+f"(c[0]), "+f"(c[1]), "+f"(c[2]), "+f"(c[3])
                 : "r"(a[0]), "r"(a[1]), "r"(a[2]), "r"(a[3]),
                   "r"(b[0]), "r"(b[1]));
}
__device__ __forceinline__ void cpa16(unsigned dst, const void* src) {
    asm volatile("cp.async.cg.shared.global [%0], [%1], 16;" :: "r"(dst), "l"(src));
}
__device__ __forceinline__ void cpa_commit() { asm volatile("cp.async.commit_group;"); }
template <int NWAIT>
__device__ __forceinline__ void cpa_wait() {
    asm volatile("cp.async.wait_group %0;" :: "n"(NWAIT));
}

__device__ __forceinline__ void split4(float4 v, __nv_bfloat16* h, __nv_bfloat16* l) {
    float x0 = v.x, x1 = v.y, x2 = v.z, x3 = v.w;
    __nv_bfloat16 h0 = __float2bfloat16_rn(x0);
    __nv_bfloat16 h1 = __float2bfloat16_rn(x1);
    __nv_bfloat16 h2 = __float2bfloat16_rn(x2);
    __nv_bfloat16 h3 = __float2bfloat16_rn(x3);
    __nv_bfloat16 l0 = __float2bfloat16_rn(x0 - __bfloat162float(h0));
    __nv_bfloat16 l1 = __float2bfloat16_rn(x1 - __bfloat162float(h1));
    __nv_bfloat16 l2 = __float2bfloat16_rn(x2 - __bfloat162float(h2));
    __nv_bfloat16 l3 = __float2bfloat16_rn(x3 - __bfloat162float(h3));
    ((__nv_bfloat162*)h)[0] = __halves2bfloat162(h0, h1);
    ((__nv_bfloat162*)h)[1] = __halves2bfloat162(h2, h3);
    ((__nv_bfloat162*)l)[0] = __halves2bfloat162(l0, l1);
    ((__nv_bfloat162*)l)[1] = __halves2bfloat162(l2, l3);
}

__device__ __forceinline__ void pack_hl(float x, float y, unsigned& hi, unsigned& lo) {
    __nv_bfloat16 hx = __float2bfloat16_rn(x);
    __nv_bfloat16 hy = __float2bfloat16_rn(y);
    __nv_bfloat16 lx = __float2bfloat16_rn(x - __bfloat162float(hx));
    __nv_bfloat16 ly = __float2bfloat16_rn(y - __bfloat162float(hy));
    __nv_bfloat162 H = __halves2bfloat162(hx, hy);
    __nv_bfloat162 L = __halves2bfloat162(lx, ly);
    hi = *(unsigned*)&H;
    lo = *(unsigned*)&L;
}

// --------------------------- weight pre-split ------------------------------
__global__ void wsplit_kernel(const float* __restrict__ src,
                              __nv_bfloat16* __restrict__ h,
                              __nv_bfloat16* __restrict__ l, int n4)
{
    int i = blockIdx.x * 256 + threadIdx.x;
    if (i < n4) {
        float4 v = ((const float4*)src)[i];
        split4(v, h + (size_t)i * 4, l + (size_t)i * 4);
    }
}

// ------------------------------ embed + PE ---------------------------------
__global__ void embed_kernel(const float* __restrict__ feats,
                             const int*   __restrict__ coords,
                             const float* __restrict__ ex,
                             const float* __restrict__ ey,
                             const float* __restrict__ ez,
                             const float* __restrict__ w_in,
                             const float* __restrict__ b_in)
{
    int n = blockIdx.x;
    int c = threadIdx.x;
    const float* f = feats + (size_t)n * 8;
    float acc = b_in[c];
#pragma unroll
    for (int l = 0; l < 8; l++) acc += f[l] * w_in[l * CDIM + c];

    int cx = coords[n * 4 + 1];
    int cy = coords[n * 4 + 2];
    int cz = coords[n * 4 + 3];
    float pe;
    if (c < 170)      pe = ex[cx * 170 + c];
    else if (c < 340) pe = ey[cy * 170 + (c - 170)];
    else              pe = ez[cz * 172 + (c - 340)];
    g_h[(size_t)n * CDIM + c] = acc + pe;
}

// ------------------------------ layernorm ----------------------------------
__global__ void __launch_bounds__(256)
ln_kernel(const float* __restrict__ x,
          const float* __restrict__ g,
          const float* __restrict__ b,
          float* __restrict__ of,
          __nv_bfloat16* __restrict__ oh,
          __nv_bfloat16* __restrict__ ol,
          float eps, int has_gb)
{
    int n   = blockIdx.x;
    int tid = threadIdx.x;
    const float* xr = x + (size_t)n * CDIM;
    float v0 = xr[tid], v1 = xr[tid + 256];
    float s  = v0 + v1;
    float s2 = v0 * v0 + v1 * v1;
#pragma unroll
    for (int off = 16; off; off >>= 1) {
        s  += __shfl_xor_sync(0xffffffffu, s,  off);
        s2 += __shfl_xor_sync(0xffffffffu, s2, off);
    }
    __shared__ float sh[16];
    __shared__ float stats[2];
    int wid = tid >> 5, lane = tid & 31;
    if (lane == 0) { sh[wid] = s; sh[wid + 8] = s2; }
    __syncthreads();
    if (tid == 0) {
        float ts = 0.f, ts2 = 0.f;
#pragma unroll
        for (int i = 0; i < 8; i++) { ts += sh[i]; ts2 += sh[i + 8]; }
        float mean = ts * (1.0f / 512.0f);
        float var  = ts2 * (1.0f / 512.0f) - mean * mean;
        if (var < 0.f) var = 0.f;
        stats[0] = mean;
        stats[1] = rsqrtf(var + eps);
    }
    __syncthreads();
    float mean = stats[0], r = stats[1];
    float o0 = (v0 - mean) * r;
    float o1 = (v1 - mean) * r;
    if (has_gb) {
        o0 = o0 * g[tid]       + b[tid];
        o1 = o1 * g[tid + 256] + b[tid + 256];
    }
    size_t base = (size_t)n * CDIM;
    if (of) { of[base + tid] = o0; of[base + tid + 256] = o1; }
    if (oh) {
        __nv_bfloat16 h0 = __float2bfloat16_rn(o0);
        __nv_bfloat16 h1 = __float2bfloat16_rn(o1);
        oh[base + tid]       = h0;
        oh[base + tid + 256] = h1;
        ol[base + tid]       = __float2bfloat16_rn(o0 - __bfloat162float(h0));
        ol[base + tid + 256] = __float2bfloat16_rn(o1 - __bfloat162float(h1));
    }
}

// ----------------- pure-bf16 tensor-core GEMM (bf16x3) ---------------------
// C = epi( Ah@Bh + Al@Bh + Ah@Bl + bias )
// epi 0: store fp32 Cf; epi 1: Cf += residual; epi 2: gelu -> Ch/Cl bf16
#define BM 128
#define BN 128
#define BK2 32
#define ASTR2 40
#define BSTR2 136
#define A_PL (128 * ASTR2)
#define B_PL (32 * BSTR2)
#define STG  (2 * A_PL + 2 * B_PL)
#define GSMEM_BYTES (2 * STG * 2)

__global__ void __launch_bounds__(256, 2)
gemm_v2_kernel(const __nv_bfloat16* __restrict__ Ah, const __nv_bfloat16* __restrict__ Al,
               const __nv_bfloat16* __restrict__ Bh, const __nv_bfloat16* __restrict__ Bl,
               const float* __restrict__ bias, float* __restrict__ Cf,
               __nv_bfloat16* __restrict__ Ch, __nv_bfloat16* __restrict__ Cl,
               int M, int N, int K, int epi)
{
    extern __shared__ __align__(16) __nv_bfloat16 smem2[];

    const int tid  = threadIdx.x;
    const int wid  = tid >> 5;
    const int lane = tid & 31;
    const int n0 = blockIdx.x * BN;
    const int m0 = blockIdx.y * BM;
    const int wm = (wid >> 2) * 64;
    const int wn = (wid & 3) * 32;

    float acc[4][4][4];
#pragma unroll
    for (int i = 0; i < 4; i++)
#pragma unroll
        for (int j = 0; j < 4; j++)
#pragma unroll
            for (int k = 0; k < 4; k++) acc[i][j][k] = 0.f;

    const int a_row = tid >> 2,  a_off = (tid & 3) << 3;
    const int b_row = tid >> 3,  b_c = (tid & 7) << 4;

    auto stage = [&](int s, int k0) {
        __nv_bfloat16* base = smem2 + s * STG;
#pragma unroll
        for (int p = 0; p < 2; p++) {
            const __nv_bfloat16* src = p ? Al : Ah;
            __nv_bfloat16* d = base + p * A_PL;
            cpa16((unsigned)__cvta_generic_to_shared(d + a_row * ASTR2 + a_off),
                  src + (size_t)(m0 + a_row) * K + k0 + a_off);
            cpa16((unsigned)__cvta_generic_to_shared(d + (a_row + 64) * ASTR2 + a_off),
                  src + (size_t)(m0 + a_row + 64) * K + k0 + a_off);
        }
#pragma unroll
        for (int p = 0; p < 2; p++) {
            const __nv_bfloat16* src = p ? Bl : Bh;
            __nv_bfloat16* d = base + 2 * A_PL + p * B_PL;
            cpa16((unsigned)__cvta_generic_to_shared(d + b_row * BSTR2 + b_c),
                  src + (size_t)(k0 + b_row) * N + n0 + b_c);
            cpa16((unsigned)__cvta_generic_to_shared(d + b_row * BSTR2 + b_c + 8),
                  src + (size_t)(k0 + b_row) * N + n0 + b_c + 8);
        }
        cpa_commit();
    };

    stage(0, 0);
    const int KT = K / BK2;
    for (int kt = 0; kt < KT; kt++) {
        int buf = kt & 1;
        if (kt + 1 < KT) { stage(buf ^ 1, (kt + 1) * BK2); cpa_wait<1>(); }
        else             { cpa_wait<0>(); }
        __syncthreads();

        __nv_bfloat16* base = smem2 + buf * STG;
        unsigned aH = (unsigned)__cvta_generic_to_shared(
            base + (wm + (lane & 15)) * ASTR2 + ((lane >> 4) << 3));
        unsigned aL = aH + A_PL * 2;
        unsigned bH = (unsigned)__cvta_generic_to_shared(
            base + 2 * A_PL + (lane & 15) * BSTR2 + wn);
        unsigned bL = bH + B_PL * 2;

#pragma unroll
        for (int ks = 0; ks < 2; ks++) {
            // hold all B fragments (16 regs), stream A fragments per mb
            unsigned bh[4][2], bl4[4][2];
#pragma unroll
            for (int nb = 0; nb < 4; nb++) {
                unsigned off = (unsigned)(ks * 16 * BSTR2) * 2 + nb * 16;
                ldsm_x2t(bh[nb],  bH + off);
                ldsm_x2t(bl4[nb], bL + off);
            }
#pragma unroll
            for (int mb = 0; mb < 4; mb++) {
                unsigned ah[4], al4[4];
                unsigned off = (unsigned)(mb * 16 * ASTR2 + ks * 16) * 2;
                ldsm_x4(ah,  aH + off);
                ldsm_x4(al4, aL + off);
#pragma unroll
                for (int nb = 0; nb < 4; nb++) {
                    mma16816(acc[mb][nb], ah,  bh[nb]);
                    mma16816(acc[mb][nb], al4, bh[nb]);
                    mma16816(acc[mb][nb], ah,  bl4[nb]);
                }
            }
        }
        __syncthreads();
    }

    // ---- epilogue ----
#pragma unroll
    for (int mb = 0; mb < 4; mb++) {
        int m = m0 + wm + mb * 16 + (lane >> 2);
#pragma unroll
        for (int nb = 0; nb < 4; nb++) {
            int n = n0 + wn + nb * 8 + ((lane & 3) << 1);
            float2 bv = *(const float2*)(bias + n);
            float c0 = acc[mb][nb][0] + bv.x;
            float c1 = acc[mb][nb][1] + bv.y;
            float c2 = acc[mb][nb][2] + bv.x;
            float c3 = acc[mb][nb][3] + bv.y;
            if (epi == 2) {
                c0 = gelu_f(c0); c1 = gelu_f(c1);
                c2 = gelu_f(c2); c3 = gelu_f(c3);
                unsigned h0, l0, h1, l1;
                pack_hl(c0, c1, h0, l0);
                pack_hl(c2, c3, h1, l1);
                *(unsigned*)(Ch + (size_t)m * N + n)       = h0;
                *(unsigned*)(Cl + (size_t)m * N + n)       = l0;
                *(unsigned*)(Ch + (size_t)(m + 8) * N + n) = h1;
                *(unsigned*)(Cl + (size_t)(m + 8) * N + n) = l1;
            } else {
                float* p0 = Cf + (size_t)m * N + n;
                float* p1 = Cf + (size_t)(m + 8) * N + n;
                if (epi == 1) {
                    float2 r0 = *(float2*)p0;
                    float2 r1 = *(float2*)p1;
                    c0 += r0.x; c1 += r0.y; c2 += r1.x; c3 += r1.y;
                }
                *(float2*)p0 = make_float2(c0, c1);
                *(float2*)p1 = make_float2(c2, c3);
            }
        }
    }
}

// ------------------- flash attention on tensor cores -----------------------
#define ASTR 88
#define AQH  0
#define AQL  (64 * ASTR)
#define AKH  (2 * 64 * ASTR)
#define AKL  (3 * 64 * ASTR)
#define AVH  (4 * 64 * ASTR)
#define AVL  (5 * 64 * ASTR)
#define ATT_SMEM (6 * 64 * ASTR * 2)

__global__ void __launch_bounds__(128)
attn_mma_kernel(const float* __restrict__ qkv,
                __nv_bfloat16* __restrict__ oh,
                __nv_bfloat16* __restrict__ ol)
{
    extern __shared__ __align__(16) __nv_bfloat16 sm[];
    const int tid  = threadIdx.x;
    const int wid  = tid >> 5;
    const int lane = tid & 31;
    const int qt = blockIdx.x, h = blockIdx.y, w = blockIdx.z;
    const int tok0 = w * 512;
    const int q0   = qt * 64;
    const int qoff = h * DHEAD;
    const int koff = CDIM + h * DHEAD;
    const int voff = 2 * CDIM + h * DHEAD;
    const int wm   = wid * 16;

#pragma unroll
    for (int i = 0; i < 8; i++) {
        int idx = tid + i * 128;
        int r = idx >> 4, c4 = (idx & 15) << 2;
        float4 v = *(const float4*)(qkv + (size_t)(tok0 + q0 + r) * (3 * CDIM) + qoff + c4);
        v.x *= 0.125f; v.y *= 0.125f; v.z *= 0.125f; v.w *= 0.125f;
        split4(v, &sm[AQH + r * ASTR + c4], &sm[AQL + r * ASTR + c4]);
    }
    __syncthreads();

    unsigned qh[4][4], ql[4][4];
    {
        unsigned baseH = (unsigned)__cvta_generic_to_shared(&sm[AQH]);
        unsigned baseL = (unsigned)__cvta_generic_to_shared(&sm[AQL]);
        int row = wm + (lane & 15);
        int coloff = (lane >> 4) << 3;
#pragma unroll
        for (int ks = 0; ks < 4; ks++) {
            unsigned off = (unsigned)(row * ASTR + ks * 16 + coloff) * 2;
            ldsm_x4(qh[ks], baseH + off);
            ldsm_x4(ql[ks], baseL + off);
        }
    }

    float m0 = -1e30f, m1 = -1e30f, l0 = 0.f, l1 = 0.f;
    float oacc[8][4];
#pragma unroll
    for (int i = 0; i < 8; i++)
#pragma unroll
        for (int j = 0; j < 4; j++) oacc[i][j] = 0.f;

    const unsigned bKH = (unsigned)__cvta_generic_to_shared(&sm[AKH]);
    const unsigned bKL = (unsigned)__cvta_generic_to_shared(&sm[AKL]);
    const unsigned bVH = (unsigned)__cvta_generic_to_shared(&sm[AVH]);
    const unsigned bVL = (unsigned)__cvta_generic_to_shared(&sm[AVL]);

    const int k_key  = ((lane >> 4) << 3) + (lane & 7);
    const int k_kc   = ((lane >> 3) & 1) << 3;
    const int v_kr   = (((lane >> 3) & 1) << 3) + (lane & 7);
    const int v_col  = (lane >> 4) << 3;

    for (int kt = 0; kt < 8; kt++) {
        __syncthreads();
#pragma unroll
        for (int i = 0; i < 8; i++) {
            int idx = tid + i * 128;
            int r = idx >> 4, c4 = (idx & 15) << 2;
            size_t rowb = (size_t)(tok0 + kt * 64 + r) * (3 * CDIM);
            float4 vk = *(const float4*)(qkv + rowb + koff + c4);
            split4(vk, &sm[AKH + r * ASTR + c4], &sm[AKL + r * ASTR + c4]);
            float4 vv = *(const float4*)(qkv + rowb + voff + c4);
            split4(vv, &sm[AVH + r * ASTR + c4], &sm[AVL + r * ASTR + c4]);
        }
        __syncthreads();

        float s[8][4];
#pragma unroll
        for (int i = 0; i < 8; i++)
#pragma unroll
            for (int j = 0; j < 4; j++) s[i][j] = 0.f;

#pragma unroll
        for (int p = 0; p < 4; p++) {
#pragma unroll
            for (int ks = 0; ks < 4; ks++) {
                unsigned kb_h[4], kb_l[4];
                unsigned off = (unsigned)((p * 16 + k_key) * ASTR + ks * 16 + k_kc) * 2;
                ldsm_x4(kb_h, bKH + off);
                ldsm_x4(kb_l, bKL + off);
                mma16816(s[2 * p],     qh[ks], &kb_h[0]);
                mma16816(s[2 * p],     ql[ks], &kb_h[0]);
                mma16816(s[2 * p],     qh[ks], &kb_l[0]);
                mma16816(s[2 * p + 1], qh[ks], &kb_h[2]);
                mma16816(s[2 * p + 1], ql[ks], &kb_h[2]);
                mma16816(s[2 * p + 1], qh[ks], &kb_l[2]);
            }
        }

        float mx0 = -1e30f, mx1 = -1e30f;
#pragma unroll
        for (int nb = 0; nb < 8; nb++) {
            mx0 = fmaxf(mx0, fmaxf(s[nb][0], s[nb][1]));
            mx1 = fmaxf(mx1, fmaxf(s[nb][2], s[nb][3]));
        }
        mx0 = fmaxf(mx0, __shfl_xor_sync(0xffffffffu, mx0, 1));
        mx0 = fmaxf(mx0, __shfl_xor_sync(0xffffffffu, mx0, 2));
        mx1 = fmaxf(mx1, __shfl_xor_sync(0xffffffffu, mx1, 1));
        mx1 = fmaxf(mx1, __shfl_xor_sync(0xffffffffu, mx1, 2));

        float nm0 = fmaxf(m0, mx0);
        float nm1 = fmaxf(m1, mx1);
        float al0 = __expf(m0 - nm0);
        float al1 = __expf(m1 - nm1);
        m0 = nm0; m1 = nm1;

        float sum0 = 0.f, sum1 = 0.f;
#pragma unroll
        for (int nb = 0; nb < 8; nb++) {
            s[nb][0] = __expf(s[nb][0] - nm0);
            s[nb][1] = __expf(s[nb][1] - nm0);
            s[nb][2] = __expf(s[nb][2] - nm1);
            s[nb][3] = __expf(s[nb][3] - nm1);
            sum0 += s[nb][0] + s[nb][1];
            sum1 += s[nb][2] + s[nb][3];
        }
        sum0 += __shfl_xor_sync(0xffffffffu, sum0, 1);
        sum0 += __shfl_xor_sync(0xffffffffu, sum0, 2);
        sum1 += __shfl_xor_sync(0xffffffffu, sum1, 1);
        sum1 += __shfl_xor_sync(0xffffffffu, sum1, 2);
        l0 = l0 * al0 + sum0;
        l1 = l1 * al1 + sum1;

#pragma unroll
        for (int nb = 0; nb < 8; nb++) {
            oacc[nb][0] *= al0; oacc[nb][1] *= al0;
            oacc[nb][2] *= al1; oacc[nb][3] *= al1;
        }

#pragma unroll
        for (int kk = 0; kk < 4; kk++) {
            unsigned pa_h[4], pa_l[4];
            pack_hl(s[2 * kk][0],     s[2 * kk][1],     pa_h[0], pa_l[0]);
            pack_hl(s[2 * kk][2],     s[2 * kk][3],     pa_h[1], pa_l[1]);
            pack_hl(s[2 * kk + 1][0], s[2 * kk + 1][1], pa_h[2], pa_l[2]);
            pack_hl(s[2 * kk + 1][2], s[2 * kk + 1][3], pa_h[3], pa_l[3]);
#pragma unroll
            for (int p = 0; p < 4; p++) {
                unsigned vb_h[4], vb_l[4];
                unsigned off = (unsigned)((kk * 16 + v_kr) * ASTR + p * 16 + v_col) * 2;
                ldsm_x4t(vb_h, bVH + off);
                ldsm_x4t(vb_l, bVL + off);
                mma16816(oacc[2 * p],     pa_h, &vb_h[0]);
                mma16816(oacc[2 * p],     pa_l, &vb_h[0]);
                mma16816(oacc[2 * p],     pa_h, &vb_l[0]);
                mma16816(oacc[2 * p + 1], pa_h, &vb_h[2]);
                mma16816(oacc[2 * p + 1], pa_l, &vb_h[2]);
                mma16816(oacc[2 * p + 1], pa_h, &vb_l[2]);
            }
        }
    }

    float i0 = 1.0f / l0, i1 = 1.0f / l1;
    int r0  = tok0 + q0 + wm + (lane >> 2);
    int col = h * DHEAD + ((lane & 3) << 1);
#pragma unroll
    for (int nb = 0; nb < 8; nb++) {
        unsigned h0, lo0, h1, lo1;
        pack_hl(oacc[nb][0] * i0, oacc[nb][1] * i0, h0, lo0);
        pack_hl(oacc[nb][2] * i1, oacc[nb][3] * i1, h1, lo1);
        size_t p0 = (size_t)r0 * CDIM + col + nb * 8;
        size_t p1 = (size_t)(r0 + 8) * CDIM + col + nb * 8;
        *(unsigned*)(oh + p0) = h0;
        *(unsigned*)(ol + p0) = lo0;
        *(unsigned*)(oh + p1) = h1;
        *(unsigned*)(ol + p1) = lo1;
    }
}

// ----------------------------- out head ------------------------------------
__global__ void outhead_kernel(const float* __restrict__ a,
                               const float* __restrict__ w,
                               const float* __restrict__ b)
{
    __shared__ float row[CDIM];
    int n = blockIdx.x;
    for (int i = threadIdx.x; i < CDIM; i += 64)
        row[i] = a[(size_t)n * CDIM + i];
    __syncthreads();
    int oc = threadIdx.x;
    if (oc < OUTC) {
        float acc = b[oc];
#pragma unroll 8
        for (int k = 0; k < CDIM; k++)
            acc += row[k] * w[k * OUTC + oc];
        g_out[n * OUTC + oc] = acc;
    }
}

// ---------------------------- postprocess ----------------------------------
__global__ void post_kernel(const int* __restrict__ coords,
                            const float* __restrict__ perturb,
                            float* __restrict__ out)
{
    int idx = blockIdx.x * 256 + threadIdx.x;
    if (idx >= NTOK * NGAUSS) return;
    int n = idx >> 2, g = idx & 3;
    const float* r = g_out + n * OUTC;
#pragma unroll
    for (int j = 0; j < 3; j++) {
        float off = tanhf(r[g * 3 + j] + perturb[g * 3 + j]) * 4.8828125e-4f;
        float xb  = ((float)coords[n * 4 + 1 + j] + 0.5f) * 0.0625f;
        out[idx * 3 + j]          = xb + off;
        out[49152 + idx * 3 + j]  = r[12 + g * 3 + j];
        out[98304 + idx * 3 + j]  = r[24 + g * 3 + j];
    }
#pragma unroll
    for (int j = 0; j < 4; j++)
        out[147456 + idx * 4 + j] = r[36 + g * 4 + j];
    out[212992 + idx] = r[52 + g];
}

// ------------------------------- launch ------------------------------------
extern "C" void kernel_launch(void* const* d_in, const int* in_sizes, int n_in,
                              void* d_out, int out_size)
{
    const float* feats   = (const float*)d_in[0];
    const int*   coords  = (const int*)  d_in[1];
    const float* emb_x   = (const float*)d_in[2];
    const float* emb_y   = (const float*)d_in[3];
    const float* emb_z   = (const float*)d_in[4];
    const float* w_in    = (const float*)d_in[5];
    const float* b_in    = (const float*)d_in[6];
    const float* ln1_g   = (const float*)d_in[7];
    const float* ln1_b   = (const float*)d_in[8];
    const float* w_qkv   = (const float*)d_in[9];
    const float* b_qkv   = (const float*)d_in[10];
    const float* w_o     = (const float*)d_in[11];
    const float* b_o     = (const float*)d_in[12];
    const float* ln2_g   = (const float*)d_in[13];
    const float* ln2_b   = (const float*)d_in[14];
    const float* w_m1    = (const float*)d_in[15];
    const float* b_m1    = (const float*)d_in[16];
    const float* w_m2    = (const float*)d_in[17];
    const float* b_m2    = (const float*)d_in[18];
    const float* w_out   = (const float*)d_in[19];
    const float* b_out   = (const float*)d_in[20];
    const float* perturb = (const float*)d_in[21];
    float* out = (float*)d_out;

    float *ph, *pa, *pqkv;
    __nv_bfloat16 *pah, *pal, *poh, *pol, *pmh, *pml;
    __nv_bfloat16 *pwqh, *pwql, *pwoh, *pwol, *pw1h, *pw1l, *pw2h, *pw2l;
    cudaGetSymbolAddress((void**)&ph,   g_h);
    cudaGetSymbolAddress((void**)&pa,   g_a);
    cudaGetSymbolAddress((void**)&pqkv, g_qkv);
    cudaGetSymbolAddress((void**)&pah,  g_ah);
    cudaGetSymbolAddress((void**)&pal,  g_al);
    cudaGetSymbolAddress((void**)&poh,  g_oh);
    cudaGetSymbolAddress((void**)&pol,  g_ol);
    cudaGetSymbolAddress((void**)&pmh,  g_mh);
    cudaGetSymbolAddress((void**)&pml,  g_ml);
    cudaGetSymbolAddress((void**)&pwqh, g_wqkv_h);
    cudaGetSymbolAddress((void**)&pwql, g_wqkv_l);
    cudaGetSymbolAddress((void**)&pwoh, g_wo_h);
    cudaGetSymbolAddress((void**)&pwol, g_wo_l);
    cudaGetSymbolAddress((void**)&pw1h, g_wm1_h);
    cudaGetSymbolAddress((void**)&pw1l, g_wm1_l);
    cudaGetSymbolAddress((void**)&pw2h, g_wm2_h);
    cudaGetSymbolAddress((void**)&pw2l, g_wm2_l);

    cudaFuncSetAttribute(attn_mma_kernel,
                         cudaFuncAttributeMaxDynamicSharedMemorySize, ATT_SMEM);
    cudaFuncSetAttribute(gemm_v2_kernel,
                         cudaFuncAttributeMaxDynamicSharedMemorySize, GSMEM_BYTES);

    {
        int n4q = LAYERS * CDIM * 3 * CDIM / 4;
        int n4o = LAYERS * CDIM * CDIM / 4;
        int n4m = LAYERS * CDIM * MLPDIM / 4;
        wsplit_kernel<<<(n4q + 255) / 256, 256>>>(w_qkv, pwqh, pwql, n4q);
        wsplit_kernel<<<(n4o + 255) / 256, 256>>>(w_o,   pwoh, pwol, n4o);
        wsplit_kernel<<<(n4m + 255) / 256, 256>>>(w_m1,  pw1h, pw1l, n4m);
        wsplit_kernel<<<(n4m + 255) / 256, 256>>>(w_m2,  pw2h, pw2l, n4m);
    }

    embed_kernel<<<NTOK, CDIM>>>(feats, coords, emb_x, emb_y, emb_z, w_in, b_in);

    for (int l = 0; l < LAYERS; l++) {
        ln_kernel<<<NTOK, 256>>>(ph, ln1_g + l * CDIM, ln1_b + l * CDIM,
                                 nullptr, pah, pal, 1e-6f, 1);
        gemm_v2_kernel<<<dim3(3 * CDIM / BN, NTOK / BM), 256, GSMEM_BYTES>>>(
            pah, pal,
            pwqh + (size_t)l * CDIM * 3 * CDIM, pwql + (size_t)l * CDIM * 3 * CDIM,
            b_qkv + l * 3 * CDIM, pqkv, nullptr, nullptr,
            NTOK, 3 * CDIM, CDIM, 0);
        attn_mma_kernel<<<dim3(8, HEADS, 8), 128, ATT_SMEM>>>(pqkv, poh, pol);
        gemm_v2_kernel<<<dim3(CDIM / BN, NTOK / BM), 256, GSMEM_BYTES>>>(
            poh, pol,
            pwoh + (size_t)l * CDIM * CDIM, pwol + (size_t)l * CDIM * CDIM,
            b_o + l * CDIM, ph, nullptr, nullptr,
            NTOK, CDIM, CDIM, 1);
        ln_kernel<<<NTOK, 256>>>(ph, ln2_g + l * CDIM, ln2_b + l * CDIM,
                                 nullptr, pah, pal, 1e-6f, 1);
        gemm_v2_kernel<<<dim3(MLPDIM / BN, NTOK / BM), 256, GSMEM_BYTES>>>(
            pah, pal,
            pw1h + (size_t)l * CDIM * MLPDIM, pw1l + (size_t)l * CDIM * MLPDIM,
            b_m1 + l * MLPDIM, nullptr, pmh, pml,
            NTOK, MLPDIM, CDIM, 2);
        gemm_v2_kernel<<<dim3(CDIM / BN, NTOK / BM), 256, GSMEM_BYTES>>>(
            pmh, pml,
            pw2h + (size_t)l * MLPDIM * CDIM, pw2l + (size_t)l * MLPDIM * CDIM,
            b_m2 + l * CDIM, ph, nullptr, nullptr,
            NTOK, CDIM, MLPDIM, 1);
    }

    ln_kernel<<<NTOK, 256>>>(ph, nullptr, nullptr, pa, nullptr, nullptr, 1e-5f, 0);
    outhead_kernel<<<NTOK, 64>>>(pa, w_out, b_out);
    post_kernel<<<(NTOK * NGAUSS + 255) / 256, 256>>>(coords, perturb, out);
}

// round 8
// speedup vs baseline: 1.3453x; 1.2554x over previous
#include <cuda_runtime.h>
#include <cuda_bf16.h>
#include <cuda_fp16.h>
#include <math.h>
#include <stdint.h>

// ---------------------------------------------------------------------------
// GSDecoder round 8: GEMMs switch bf16x3 (3 passes) -> fp16x2 (2 passes).
// Activations split as fp16 hi/lo of 256*x (scale avoids denormal lo);
// weights single fp16. Attention stays bf16x3 internally. HMMA pipe was
// measured at ceiling (~290 TF/s), so pass-count is the only lever.
// ---------------------------------------------------------------------------

#define NTOK   4096
#define CDIM   512
#define HEADS  8
#define DHEAD  64
#define LAYERS 8
#define MLPDIM 2048
#define OUTC   56
#define NGAUSS 4

#define ASCALE     256.0f
#define INV_ASCALE 0.00390625f

// ------------------------- scratch (device globals) ------------------------
__device__ float g_h   [NTOK * CDIM];
__device__ float g_a   [NTOK * CDIM];
__device__ float g_qkv [NTOK * 3 * CDIM];
__device__ float g_out [NTOK * OUTC];

__device__ __half g_ah[NTOK * CDIM],  g_al[NTOK * CDIM];     // LN out (x256)
__device__ __half g_oh[NTOK * CDIM],  g_ol[NTOK * CDIM];     // attn out (x256)
__device__ __half g_mh[NTOK * MLPDIM], g_ml[NTOK * MLPDIM];  // gelu out (x256)

__device__ __half g_wqkv_h[LAYERS * CDIM * 3 * CDIM];
__device__ __half g_wo_h  [LAYERS * CDIM * CDIM];
__device__ __half g_wm1_h [LAYERS * CDIM * MLPDIM];
__device__ __half g_wm2_h [LAYERS * MLPDIM * CDIM];

// ------------------------------ helpers ------------------------------------
__device__ __forceinline__ float gelu_f(float x) {
    float x3 = x * x * x;
    return 0.5f * x * (1.0f + tanhf(0.7978845608028654f * (x + 0.044715f * x3)));
}

__device__ __forceinline__ void ldsm_x4(unsigned* r, unsigned addr) {
    asm volatile("ldmatrix.sync.aligned.m8n8.x4.shared.b16 {%0,%1,%2,%3}, [%4];"
                 : "=r"(r[0]), "=r"(r[1]), "=r"(r[2]), "=r"(r[3]) : "r"(addr));
}
__device__ __forceinline__ void ldsm_x4t(unsigned* r, unsigned addr) {
    asm volatile("ldmatrix.sync.aligned.m8n8.x4.trans.shared.b16 {%0,%1,%2,%3}, [%4];"
                 : "=r"(r[0]), "=r"(r[1]), "=r"(r[2]), "=r"(r[3]) : "r"(addr));
}
__device__ __forceinline__ void ldsm_x2t(unsigned* r, unsigned addr) {
    asm volatile("ldmatrix.sync.aligned.m8n8.x2.trans.shared.b16 {%0,%1}, [%2];"
                 : "=r"(r[0]), "=r"(r[1]) : "r"(addr));
}
// bf16 mma (attention)
__device__ __forceinline__ void mma16816(float* c, const unsigned* a, const unsigned* b) {
    asm volatile("mma.sync.aligned.m16n8k16.row.col.f32.bf16.bf16.f32 "
                 "{%0,%1,%2,%3}, {%4,%5,%6,%7}, {%8,%9}, {%0,%1,%2,%3};"
                 : "+f"(c[0]), "+f"(c[1]), "+f"(c[2]), "+f"(c[3])
                 : "r"(a[0]), "r"(a[1]), "r"(a[2]), "r"(a[3]),
                   "r"(b[0]), "r"(b[1]));
}
// fp16 mma (GEMMs)
__device__ __forceinline__ void mma16816h(float* c, const unsigned* a, const unsigned* b) {
    asm volatile("mma.sync.aligned.m16n8k16.row.col.f32.f16.f16.f32 "
                 "{%0,%1,%2,%3}, {%4,%5,%6,%7}, {%8,%9}, {%0,%1,%2,%3};"
                 : "+f"(c[0]), "+f"(c[1]), "+f"(c[2]), "+f"(c[3])
                 : "r"(a[0]), "r"(a[1]), "r"(a[2]), "r"(a[3]),
                   "r"(b[0]), "r"(b[1]));
}
__device__ __forceinline__ void cpa16(unsigned dst, const void* src) {
    asm volatile("cp.async.cg.shared.global [%0], [%1], 16;" :: "r"(dst), "l"(src));
}
__device__ __forceinline__ void cpa_commit() { asm volatile("cp.async.commit_group;"); }
template <int NWAIT>
__device__ __forceinline__ void cpa_wait() {
    asm volatile("cp.async.wait_group %0;" :: "n"(NWAIT));
}

// bf16 split (attention internals)
__device__ __forceinline__ void split4(float4 v, __nv_bfloat16* h, __nv_bfloat16* l) {
    float x0 = v.x, x1 = v.y, x2 = v.z, x3 = v.w;
    __nv_bfloat16 h0 = __float2bfloat16_rn(x0);
    __nv_bfloat16 h1 = __float2bfloat16_rn(x1);
    __nv_bfloat16 h2 = __float2bfloat16_rn(x2);
    __nv_bfloat16 h3 = __float2bfloat16_rn(x3);
    __nv_bfloat16 l0 = __float2bfloat16_rn(x0 - __bfloat162float(h0));
    __nv_bfloat16 l1 = __float2bfloat16_rn(x1 - __bfloat162float(h1));
    __nv_bfloat16 l2 = __float2bfloat16_rn(x2 - __bfloat162float(h2));
    __nv_bfloat16 l3 = __float2bfloat16_rn(x3 - __bfloat162float(h3));
    ((__nv_bfloat162*)h)[0] = __halves2bfloat162(h0, h1);
    ((__nv_bfloat162*)h)[1] = __halves2bfloat162(h2, h3);
    ((__nv_bfloat162*)l)[0] = __halves2bfloat162(l0, l1);
    ((__nv_bfloat162*)l)[1] = __halves2bfloat162(l2, l3);
}
__device__ __forceinline__ void pack_hl(float x, float y, unsigned& hi, unsigned& lo) {
    __nv_bfloat16 hx = __float2bfloat16_rn(x);
    __nv_bfloat16 hy = __float2bfloat16_rn(y);
    __nv_bfloat16 lx = __float2bfloat16_rn(x - __bfloat162float(hx));
    __nv_bfloat16 ly = __float2bfloat16_rn(y - __bfloat162float(hy));
    __nv_bfloat162 H = __halves2bfloat162(hx, hy);
    __nv_bfloat162 L = __halves2bfloat162(lx, ly);
    hi = *(unsigned*)&H;
    lo = *(unsigned*)&L;
}
// fp16 scaled split: writes hi/lo of (ASCALE*x, ASCALE*y)
__device__ __forceinline__ void pack_h2s(float x, float y, unsigned& hi, unsigned& lo) {
    float xs = x * ASCALE, ys = y * ASCALE;
    __half hx = __float2half_rn(xs);
    __half hy = __float2half_rn(ys);
    __half lx = __float2half_rn(xs - __half2float(hx));
    __half ly = __float2half_rn(ys - __half2float(hy));
    __half2 H = __halves2half2(hx, hy);
    __half2 L = __halves2half2(lx, ly);
    hi = *(unsigned*)&H;
    lo = *(unsigned*)&L;
}

// --------------------------- weight fp16 cast ------------------------------
__global__ void wcast_kernel(const float* __restrict__ src,
                             __half* __restrict__ h, int n4)
{
    int i = blockIdx.x * 256 + threadIdx.x;
    if (i < n4) {
        float4 v = ((const float4*)src)[i];
        __half2 a = __halves2half2(__float2half_rn(v.x), __float2half_rn(v.y));
        __half2 b = __halves2half2(__float2half_rn(v.z), __float2half_rn(v.w));
        ((__half2*)h)[i * 2]     = a;
        ((__half2*)h)[i * 2 + 1] = b;
    }
}

// ------------------------------ embed + PE ---------------------------------
__global__ void embed_kernel(const float* __restrict__ feats,
                             const int*   __restrict__ coords,
                             const float* __restrict__ ex,
                             const float* __restrict__ ey,
                             const float* __restrict__ ez,
                             const float* __restrict__ w_in,
                             const float* __restrict__ b_in)
{
    int n = blockIdx.x;
    int c = threadIdx.x;
    const float* f = feats + (size_t)n * 8;
    float acc = b_in[c];
#pragma unroll
    for (int l = 0; l < 8; l++) acc += f[l] * w_in[l * CDIM + c];

    int cx = coords[n * 4 + 1];
    int cy = coords[n * 4 + 2];
    int cz = coords[n * 4 + 3];
    float pe;
    if (c < 170)      pe = ex[cx * 170 + c];
    else if (c < 340) pe = ey[cy * 170 + (c - 170)];
    else              pe = ez[cz * 172 + (c - 340)];
    g_h[(size_t)n * CDIM + c] = acc + pe;
}

// ------------------------------ layernorm ----------------------------------
// writes fp32 (if of) and/or scaled fp16 hi/lo (if oh)
__global__ void __launch_bounds__(256)
ln_kernel(const float* __restrict__ x,
          const float* __restrict__ g,
          const float* __restrict__ b,
          float* __restrict__ of,
          __half* __restrict__ oh,
          __half* __restrict__ ol,
          float eps, int has_gb)
{
    int n   = blockIdx.x;
    int tid = threadIdx.x;
    const float* xr = x + (size_t)n * CDIM;
    float v0 = xr[tid], v1 = xr[tid + 256];
    float s  = v0 + v1;
    float s2 = v0 * v0 + v1 * v1;
#pragma unroll
    for (int off = 16; off; off >>= 1) {
        s  += __shfl_xor_sync(0xffffffffu, s,  off);
        s2 += __shfl_xor_sync(0xffffffffu, s2, off);
    }
    __shared__ float sh[16];
    __shared__ float stats[2];
    int wid = tid >> 5, lane = tid & 31;
    if (lane == 0) { sh[wid] = s; sh[wid + 8] = s2; }
    __syncthreads();
    if (tid == 0) {
        float ts = 0.f, ts2 = 0.f;
#pragma unroll
        for (int i = 0; i < 8; i++) { ts += sh[i]; ts2 += sh[i + 8]; }
        float mean = ts * (1.0f / 512.0f);
        float var  = ts2 * (1.0f / 512.0f) - mean * mean;
        if (var < 0.f) var = 0.f;
        stats[0] = mean;
        stats[1] = rsqrtf(var + eps);
    }
    __syncthreads();
    float mean = stats[0], r = stats[1];
    float o0 = (v0 - mean) * r;
    float o1 = (v1 - mean) * r;
    if (has_gb) {
        o0 = o0 * g[tid]       + b[tid];
        o1 = o1 * g[tid + 256] + b[tid + 256];
    }
    size_t base = (size_t)n * CDIM;
    if (of) { of[base + tid] = o0; of[base + tid + 256] = o1; }
    if (oh) {
        float s0 = o0 * ASCALE, s1 = o1 * ASCALE;
        __half h0 = __float2half_rn(s0);
        __half h1 = __float2half_rn(s1);
        oh[base + tid]       = h0;
        oh[base + tid + 256] = h1;
        ol[base + tid]       = __float2half_rn(s0 - __half2float(h0));
        ol[base + tid + 256] = __float2half_rn(s1 - __half2float(h1));
    }
}

// ----------------- fp16x2 tensor-core GEMM ---------------------------------
// D = A256h@Bh + A256l@Bh ;  C = epi( D/256 + bias )
// epi 0: fp32 Cf; epi 1: Cf += residual; epi 2: gelu -> scaled fp16 Ch/Cl
#define BM 128
#define BN 128
#define BK2 32
#define ASTR2 40
#define BSTR2 136
#define A_PL (128 * ASTR2)            // 5120 halves per polarity
#define B_PL (32 * BSTR2)             // 4352 halves
#define STG  (2 * A_PL + B_PL)        // 14592 halves per stage
#define GSMEM_BYTES (2 * STG * 2)     // 58368 bytes

__global__ void __launch_bounds__(256, 2)
gemm_f16_kernel(const __half* __restrict__ Ah, const __half* __restrict__ Al,
                const __half* __restrict__ Bh,
                const float* __restrict__ bias, float* __restrict__ Cf,
                __half* __restrict__ Ch, __half* __restrict__ Cl,
                int M, int N, int K, int epi)
{
    extern __shared__ __align__(16) __half smemh[];

    const int tid  = threadIdx.x;
    const int wid  = tid >> 5;
    const int lane = tid & 31;
    const int n0 = blockIdx.x * BN;
    const int m0 = blockIdx.y * BM;
    const int wm = (wid >> 2) * 64;
    const int wn = (wid & 3) * 32;

    float acc[4][4][4];
#pragma unroll
    for (int i = 0; i < 4; i++)
#pragma unroll
        for (int j = 0; j < 4; j++)
#pragma unroll
            for (int k = 0; k < 4; k++) acc[i][j][k] = 0.f;

    const int a_row = tid >> 2,  a_off = (tid & 3) << 3;
    const int b_row = tid >> 3,  b_c = (tid & 7) << 4;

    auto stage = [&](int s, int k0) {
        __half* base = smemh + s * STG;
#pragma unroll
        for (int p = 0; p < 2; p++) {
            const __half* src = p ? Al : Ah;
            __half* d = base + p * A_PL;
            cpa16((unsigned)__cvta_generic_to_shared(d + a_row * ASTR2 + a_off),
                  src + (size_t)(m0 + a_row) * K + k0 + a_off);
            cpa16((unsigned)__cvta_generic_to_shared(d + (a_row + 64) * ASTR2 + a_off),
                  src + (size_t)(m0 + a_row + 64) * K + k0 + a_off);
        }
        {
            __half* d = base + 2 * A_PL;
            cpa16((unsigned)__cvta_generic_to_shared(d + b_row * BSTR2 + b_c),
                  Bh + (size_t)(k0 + b_row) * N + n0 + b_c);
            cpa16((unsigned)__cvta_generic_to_shared(d + b_row * BSTR2 + b_c + 8),
                  Bh + (size_t)(k0 + b_row) * N + n0 + b_c + 8);
        }
        cpa_commit();
    };

    stage(0, 0);
    const int KT = K / BK2;
    for (int kt = 0; kt < KT; kt++) {
        int buf = kt & 1;
        if (kt + 1 < KT) { stage(buf ^ 1, (kt + 1) * BK2); cpa_wait<1>(); }
        else             { cpa_wait<0>(); }
        __syncthreads();

        __half* base = smemh + buf * STG;
        unsigned aH = (unsigned)__cvta_generic_to_shared(
            base + (wm + (lane & 15)) * ASTR2 + ((lane >> 4) << 3));
        unsigned aL = aH + A_PL * 2;
        unsigned bH = (unsigned)__cvta_generic_to_shared(
            base + 2 * A_PL + (lane & 15) * BSTR2 + wn);

#pragma unroll
        for (int ks = 0; ks < 2; ks++) {
            unsigned bh[4][2];
#pragma unroll
            for (int nb = 0; nb < 4; nb++) {
                unsigned off = (unsigned)(ks * 16 * BSTR2) * 2 + nb * 16;
                ldsm_x2t(bh[nb], bH + off);
            }
#pragma unroll
            for (int mb = 0; mb < 4; mb++) {
                unsigned ah[4], al4[4];
                unsigned off = (unsigned)(mb * 16 * ASTR2 + ks * 16) * 2;
                ldsm_x4(ah,  aH + off);
                ldsm_x4(al4, aL + off);
#pragma unroll
                for (int nb = 0; nb < 4; nb++) {
                    mma16816h(acc[mb][nb], ah,  bh[nb]);
                    mma16816h(acc[mb][nb], al4, bh[nb]);
                }
            }
        }
        __syncthreads();
    }

    // ---- epilogue ----
#pragma unroll
    for (int mb = 0; mb < 4; mb++) {
        int m = m0 + wm + mb * 16 + (lane >> 2);
#pragma unroll
        for (int nb = 0; nb < 4; nb++) {
            int n = n0 + wn + nb * 8 + ((lane & 3) << 1);
            float2 bv = *(const float2*)(bias + n);
            float c0 = acc[mb][nb][0] * INV_ASCALE + bv.x;
            float c1 = acc[mb][nb][1] * INV_ASCALE + bv.y;
            float c2 = acc[mb][nb][2] * INV_ASCALE + bv.x;
            float c3 = acc[mb][nb][3] * INV_ASCALE + bv.y;
            if (epi == 2) {
                c0 = gelu_f(c0); c1 = gelu_f(c1);
                c2 = gelu_f(c2); c3 = gelu_f(c3);
                unsigned h0, l0, h1, l1;
                pack_h2s(c0, c1, h0, l0);
                pack_h2s(c2, c3, h1, l1);
                *(unsigned*)(Ch + (size_t)m * N + n)       = h0;
                *(unsigned*)(Cl + (size_t)m * N + n)       = l0;
                *(unsigned*)(Ch + (size_t)(m + 8) * N + n) = h1;
                *(unsigned*)(Cl + (size_t)(m + 8) * N + n) = l1;
            } else {
                float* p0 = Cf + (size_t)m * N + n;
                float* p1 = Cf + (size_t)(m + 8) * N + n;
                if (epi == 1) {
                    float2 r0 = *(float2*)p0;
                    float2 r1 = *(float2*)p1;
                    c0 += r0.x; c1 += r0.y; c2 += r1.x; c3 += r1.y;
                }
                *(float2*)p0 = make_float2(c0, c1);
                *(float2*)p1 = make_float2(c2, c3);
            }
        }
    }
}

// ------------------- flash attention on tensor cores -----------------------
#define ASTR 88
#define AQH  0
#define AQL  (64 * ASTR)
#define AKH  (2 * 64 * ASTR)
#define AKL  (3 * 64 * ASTR)
#define AVH  (4 * 64 * ASTR)
#define AVL  (5 * 64 * ASTR)
#define ATT_SMEM (6 * 64 * ASTR * 2)

__global__ void __launch_bounds__(128)
attn_mma_kernel(const float* __restrict__ qkv,
                __half* __restrict__ oh,
                __half* __restrict__ ol)
{
    extern __shared__ __align__(16) __nv_bfloat16 sm[];
    const int tid  = threadIdx.x;
    const int wid  = tid >> 5;
    const int lane = tid & 31;
    const int qt = blockIdx.x, h = blockIdx.y, w = blockIdx.z;
    const int tok0 = w * 512;
    const int q0   = qt * 64;
    const int qoff = h * DHEAD;
    const int koff = CDIM + h * DHEAD;
    const int voff = 2 * CDIM + h * DHEAD;
    const int wm   = wid * 16;

#pragma unroll
    for (int i = 0; i < 8; i++) {
        int idx = tid + i * 128;
        int r = idx >> 4, c4 = (idx & 15) << 2;
        float4 v = *(const float4*)(qkv + (size_t)(tok0 + q0 + r) * (3 * CDIM) + qoff + c4);
        v.x *= 0.125f; v.y *= 0.125f; v.z *= 0.125f; v.w *= 0.125f;
        split4(v, &sm[AQH + r * ASTR + c4], &sm[AQL + r * ASTR + c4]);
    }
    __syncthreads();

    unsigned qh[4][4], ql[4][4];
    {
        unsigned baseH = (unsigned)__cvta_generic_to_shared(&sm[AQH]);
        unsigned baseL = (unsigned)__cvta_generic_to_shared(&sm[AQL]);
        int row = wm + (lane & 15);
        int coloff = (lane >> 4) << 3;
#pragma unroll
        for (int ks = 0; ks < 4; ks++) {
            unsigned off = (unsigned)(row * ASTR + ks * 16 + coloff) * 2;
            ldsm_x4(qh[ks], baseH + off);
            ldsm_x4(ql[ks], baseL + off);
        }
    }

    float m0 = -1e30f, m1 = -1e30f, l0 = 0.f, l1 = 0.f;
    float oacc[8][4];
#pragma unroll
    for (int i = 0; i < 8; i++)
#pragma unroll
        for (int j = 0; j < 4; j++) oacc[i][j] = 0.f;

    const unsigned bKH = (unsigned)__cvta_generic_to_shared(&sm[AKH]);
    const unsigned bKL = (unsigned)__cvta_generic_to_shared(&sm[AKL]);
    const unsigned bVH = (unsigned)__cvta_generic_to_shared(&sm[AVH]);
    const unsigned bVL = (unsigned)__cvta_generic_to_shared(&sm[AVL]);

    const int k_key  = ((lane >> 4) << 3) + (lane & 7);
    const int k_kc   = ((lane >> 3) & 1) << 3;
    const int v_kr   = (((lane >> 3) & 1) << 3) + (lane & 7);
    const int v_col  = (lane >> 4) << 3;

    for (int kt = 0; kt < 8; kt++) {
        __syncthreads();
#pragma unroll
        for (int i = 0; i < 8; i++) {
            int idx = tid + i * 128;
            int r = idx >> 4, c4 = (idx & 15) << 2;
            size_t rowb = (size_t)(tok0 + kt * 64 + r) * (3 * CDIM);
            float4 vk = *(const float4*)(qkv + rowb + koff + c4);
            split4(vk, &sm[AKH + r * ASTR + c4], &sm[AKL + r * ASTR + c4]);
            float4 vv = *(const float4*)(qkv + rowb + voff + c4);
            split4(vv, &sm[AVH + r * ASTR + c4], &sm[AVL + r * ASTR + c4]);
        }
        __syncthreads();

        float s[8][4];
#pragma unroll
        for (int i = 0; i < 8; i++)
#pragma unroll
            for (int j = 0; j < 4; j++) s[i][j] = 0.f;

#pragma unroll
        for (int p = 0; p < 4; p++) {
#pragma unroll
            for (int ks = 0; ks < 4; ks++) {
                unsigned kb_h[4], kb_l[4];
                unsigned off = (unsigned)((p * 16 + k_key) * ASTR + ks * 16 + k_kc) * 2;
                ldsm_x4(kb_h, bKH + off);
                ldsm_x4(kb_l, bKL + off);
                mma16816(s[2 * p],     qh[ks], &kb_h[0]);
                mma16816(s[2 * p],     ql[ks], &kb_h[0]);
                mma16816(s[2 * p],     qh[ks], &kb_l[0]);
                mma16816(s[2 * p + 1], qh[ks], &kb_h[2]);
                mma16816(s[2 * p + 1], ql[ks], &kb_h[2]);
                mma16816(s[2 * p + 1], qh[ks], &kb_l[2]);
            }
        }

        float mx0 = -1e30f, mx1 = -1e30f;
#pragma unroll
        for (int nb = 0; nb < 8; nb++) {
            mx0 = fmaxf(mx0, fmaxf(s[nb][0], s[nb][1]));
            mx1 = fmaxf(mx1, fmaxf(s[nb][2], s[nb][3]));
        }
        mx0 = fmaxf(mx0, __shfl_xor_sync(0xffffffffu, mx0, 1));
        mx0 = fmaxf(mx0, __shfl_xor_sync(0xffffffffu, mx0, 2));
        mx1 = fmaxf(mx1, __shfl_xor_sync(0xffffffffu, mx1, 1));
        mx1 = fmaxf(mx1, __shfl_xor_sync(0xffffffffu, mx1, 2));

        float nm0 = fmaxf(m0, mx0);
        float nm1 = fmaxf(m1, mx1);
        float al0 = __expf(m0 - nm0);
        float al1 = __expf(m1 - nm1);
        m0 = nm0; m1 = nm1;

        float sum0 = 0.f, sum1 = 0.f;
#pragma unroll
        for (int nb = 0; nb < 8; nb++) {
            s[nb][0] = __expf(s[nb][0] - nm0);
            s[nb][1] = __expf(s[nb][1] - nm0);
            s[nb][2] = __expf(s[nb][2] - nm1);
            s[nb][3] = __expf(s[nb][3] - nm1);
            sum0 += s[nb][0] + s[nb][1];
            sum1 += s[nb][2] + s[nb][3];
        }
        sum0 += __shfl_xor_sync(0xffffffffu, sum0, 1);
        sum0 += __shfl_xor_sync(0xffffffffu, sum0, 2);
        sum1 += __shfl_xor_sync(0xffffffffu, sum1, 1);
        sum1 += __shfl_xor_sync(0xffffffffu, sum1, 2);
        l0 = l0 * al0 + sum0;
        l1 = l1 * al1 + sum1;

#pragma unroll
        for (int nb = 0; nb < 8; nb++) {
            oacc[nb][0] *= al0; oacc[nb][1] *= al0;
            oacc[nb][2] *= al1; oacc[nb][3] *= al1;
        }

#pragma unroll
        for (int kk = 0; kk < 4; kk++) {
            unsigned pa_h[4], pa_l[4];
            pack_hl(s[2 * kk][0],     s[2 * kk][1],     pa_h[0], pa_l[0]);
            pack_hl(s[2 * kk][2],     s[2 * kk][3],     pa_h[1], pa_l[1]);
            pack_hl(s[2 * kk + 1][0], s[2 * kk + 1][1], pa_h[2], pa_l[2]);
            pack_hl(s[2 * kk + 1][2], s[2 * kk + 1][3], pa_h[3], pa_l[3]);
#pragma unroll
            for (int p = 0; p < 4; p++) {
                unsigned vb_h[4], vb_l[4];
                unsigned off = (unsigned)((kk * 16 + v_kr) * ASTR + p * 16 + v_col) * 2;
                ldsm_x4t(vb_h, bVH + off);
                ldsm_x4t(vb_l, bVL + off);
                mma16816(oacc[2 * p],     pa_h, &vb_h[0]);
                mma16816(oacc[2 * p],     pa_l, &vb_h[0]);
                mma16816(oacc[2 * p],     pa_h, &vb_l[0]);
                mma16816(oacc[2 * p + 1], pa_h, &vb_h[2]);
                mma16816(oacc[2 * p + 1], pa_l, &vb_h[2]);
                mma16816(oacc[2 * p + 1], pa_h, &vb_l[2]);
            }
        }
    }

    // ---- epilogue: scaled fp16 hi/lo for the wo GEMM ----
    float i0 = 1.0f / l0, i1 = 1.0f / l1;
    int r0  = tok0 + q0 + wm + (lane >> 2);
    int col = h * DHEAD + ((lane & 3) << 1);
#pragma unroll
    for (int nb = 0; nb < 8; nb++) {
        unsigned h0, lo0, h1, lo1;
        pack_h2s(oacc[nb][0] * i0, oacc[nb][1] * i0, h0, lo0);
        pack_h2s(oacc[nb][2] * i1, oacc[nb][3] * i1, h1, lo1);
        size_t p0 = (size_t)r0 * CDIM + col + nb * 8;
        size_t p1 = (size_t)(r0 + 8) * CDIM + col + nb * 8;
        *(unsigned*)(oh + p0) = h0;
        *(unsigned*)(ol + p0) = lo0;
        *(unsigned*)(oh + p1) = h1;
        *(unsigned*)(ol + p1) = lo1;
    }
}

// ----------------------------- out head ------------------------------------
__global__ void outhead_kernel(const float* __restrict__ a,
                               const float* __restrict__ w,
                               const float* __restrict__ b)
{
    __shared__ float row[CDIM];
    int n = blockIdx.x;
    for (int i = threadIdx.x; i < CDIM; i += 64)
        row[i] = a[(size_t)n * CDIM + i];
    __syncthreads();
    int oc = threadIdx.x;
    if (oc < OUTC) {
        float acc = b[oc];
#pragma unroll 8
        for (int k = 0; k < CDIM; k++)
            acc += row[k] * w[k * OUTC + oc];
        g_out[n * OUTC + oc] = acc;
    }
}

// ---------------------------- postprocess ----------------------------------
__global__ void post_kernel(const int* __restrict__ coords,
                            const float* __restrict__ perturb,
                            float* __restrict__ out)
{
    int idx = blockIdx.x * 256 + threadIdx.x;
    if (idx >= NTOK * NGAUSS) return;
    int n = idx >> 2, g = idx & 3;
    const float* r = g_out + n * OUTC;
#pragma unroll
    for (int j = 0; j < 3; j++) {
        float off = tanhf(r[g * 3 + j] + perturb[g * 3 + j]) * 4.8828125e-4f;
        float xb  = ((float)coords[n * 4 + 1 + j] + 0.5f) * 0.0625f;
        out[idx * 3 + j]          = xb + off;
        out[49152 + idx * 3 + j]  = r[12 + g * 3 + j];
        out[98304 + idx * 3 + j]  = r[24 + g * 3 + j];
    }
#pragma unroll
    for (int j = 0; j < 4; j++)
        out[147456 + idx * 4 + j] = r[36 + g * 4 + j];
    out[212992 + idx] = r[52 + g];
}

// ------------------------------- launch ------------------------------------
extern "C" void kernel_launch(void* const* d_in, const int* in_sizes, int n_in,
                              void* d_out, int out_size)
{
    const float* feats   = (const float*)d_in[0];
    const int*   coords  = (const int*)  d_in[1];
    const float* emb_x   = (const float*)d_in[2];
    const float* emb_y   = (const float*)d_in[3];
    const float* emb_z   = (const float*)d_in[4];
    const float* w_in    = (const float*)d_in[5];
    const float* b_in    = (const float*)d_in[6];
    const float* ln1_g   = (const float*)d_in[7];
    const float* ln1_b   = (const float*)d_in[8];
    const float* w_qkv   = (const float*)d_in[9];
    const float* b_qkv   = (const float*)d_in[10];
    const float* w_o     = (const float*)d_in[11];
    const float* b_o     = (const float*)d_in[12];
    const float* ln2_g   = (const float*)d_in[13];
    const float* ln2_b   = (const float*)d_in[14];
    const float* w_m1    = (const float*)d_in[15];
    const float* b_m1    = (const float*)d_in[16];
    const float* w_m2    = (const float*)d_in[17];
    const float* b_m2    = (const float*)d_in[18];
    const float* w_out   = (const float*)d_in[19];
    const float* b_out   = (const float*)d_in[20];
    const float* perturb = (const float*)d_in[21];
    float* out = (float*)d_out;

    float *ph, *pa, *pqkv;
    __half *pah, *pal, *poh, *pol, *pmh, *pml;
    __half *pwqh, *pwoh, *pw1h, *pw2h;
    cudaGetSymbolAddress((void**)&ph,   g_h);
    cudaGetSymbolAddress((void**)&pa,   g_a);
    cudaGetSymbolAddress((void**)&pqkv, g_qkv);
    cudaGetSymbolAddress((void**)&pah,  g_ah);
    cudaGetSymbolAddress((void**)&pal,  g_al);
    cudaGetSymbolAddress((void**)&poh,  g_oh);
    cudaGetSymbolAddress((void**)&pol,  g_ol);
    cudaGetSymbolAddress((void**)&pmh,  g_mh);
    cudaGetSymbolAddress((void**)&pml,  g_ml);
    cudaGetSymbolAddress((void**)&pwqh, g_wqkv_h);
    cudaGetSymbolAddress((void**)&pwoh, g_wo_h);
    cudaGetSymbolAddress((void**)&pw1h, g_wm1_h);
    cudaGetSymbolAddress((void**)&pw2h, g_wm2_h);

    cudaFuncSetAttribute(attn_mma_kernel,
                         cudaFuncAttributeMaxDynamicSharedMemorySize, ATT_SMEM);
    cudaFuncSetAttribute(gemm_f16_kernel,
                         cudaFuncAttributeMaxDynamicSharedMemorySize, GSMEM_BYTES);

    {
        int n4q = LAYERS * CDIM * 3 * CDIM / 4;
        int n4o = LAYERS * CDIM * CDIM / 4;
        int n4m = LAYERS * CDIM * MLPDIM / 4;
        wcast_kernel<<<(n4q + 255) / 256, 256>>>(w_qkv, pwqh, n4q);
        wcast_kernel<<<(n4o + 255) / 256, 256>>>(w_o,   pwoh, n4o);
        wcast_kernel<<<(n4m + 255) / 256, 256>>>(w_m1,  pw1h, n4m);
        wcast_kernel<<<(n4m + 255) / 256, 256>>>(w_m2,  pw2h, n4m);
    }

    embed_kernel<<<NTOK, CDIM>>>(feats, coords, emb_x, emb_y, emb_z, w_in, b_in);

    for (int l = 0; l < LAYERS; l++) {
        ln_kernel<<<NTOK, 256>>>(ph, ln1_g + l * CDIM, ln1_b + l * CDIM,
                                 nullptr, pah, pal, 1e-6f, 1);
        gemm_f16_kernel<<<dim3(3 * CDIM / BN, NTOK / BM), 256, GSMEM_BYTES>>>(
            pah, pal, pwqh + (size_t)l * CDIM * 3 * CDIM,
            b_qkv + l * 3 * CDIM, pqkv, nullptr, nullptr,
            NTOK, 3 * CDIM, CDIM, 0);
        attn_mma_kernel<<<dim3(8, HEADS, 8), 128, ATT_SMEM>>>(pqkv, poh, pol);
        gemm_f16_kernel<<<dim3(CDIM / BN, NTOK / BM), 256, GSMEM_BYTES>>>(
            poh, pol, pwoh + (size_t)l * CDIM * CDIM,
            b_o + l * CDIM, ph, nullptr, nullptr,
            NTOK, CDIM, CDIM, 1);
        ln_kernel<<<NTOK, 256>>>(ph, ln2_g + l * CDIM, ln2_b + l * CDIM,
                                 nullptr, pah, pal, 1e-6f, 1);
        gemm_f16_kernel<<<dim3(MLPDIM / BN, NTOK / BM), 256, GSMEM_BYTES>>>(
            pah, pal, pw1h + (size_t)l * CDIM * MLPDIM,
            b_m1 + l * MLPDIM, nullptr, pmh, pml,
            NTOK, MLPDIM, CDIM, 2);
        gemm_f16_kernel<<<dim3(CDIM / BN, NTOK / BM), 256, GSMEM_BYTES>>>(
            pmh, pml, pw2h + (size_t)l * MLPDIM * CDIM,
            b_m2 + l * CDIM, ph, nullptr, nullptr,
            NTOK, CDIM, MLPDIM, 1);
    }

    ln_kernel<<<NTOK, 256>>>(ph, nullptr, nullptr, pa, nullptr, nullptr, 1e-5f, 0);
    outhead_kernel<<<NTOK, 64>>>(pa, w_out, b_out);
    post_kernel<<<(NTOK * NGAUSS + 255) / 256, 256>>>(coords, perturb, out);
}

// round 9
// speedup vs baseline: 1.3962x; 1.0379x over previous
#include <cuda_runtime.h>
#include <cuda_fp16.h>
#include <math.h>
#include <stdint.h>

// ---------------------------------------------------------------------------
// GSDecoder round 9: fp16x2 everywhere. qkv GEMM emits scaled fp16 hi/lo;
// attention stages via cp.async (no conversion), QK/PV 2 passes each.
// ---------------------------------------------------------------------------

#define NTOK   4096
#define CDIM   512
#define HEADS  8
#define DHEAD  64
#define LAYERS 8
#define MLPDIM 2048
#define OUTC   56
#define NGAUSS 4

#define ASCALE     256.0f
#define INV_ASCALE 0.00390625f
// softmax scale: (1/65536 from 256*256) * (1/8 from 1/sqrt(64))
#define QK_SCALE   1.9073486328125e-6f

// ------------------------- scratch (device globals) ------------------------
__device__ float g_h  [NTOK * CDIM];
__device__ float g_a  [NTOK * CDIM];
__device__ float g_out[NTOK * OUTC];

__device__ __half g_ah[NTOK * CDIM],  g_al[NTOK * CDIM];       // LN out (x256)
__device__ __half g_qh[NTOK * 3 * CDIM], g_ql[NTOK * 3 * CDIM]; // qkv (x256)
__device__ __half g_oh[NTOK * CDIM],  g_ol[NTOK * CDIM];       // attn out (x256)
__device__ __half g_mh[NTOK * MLPDIM], g_ml[NTOK * MLPDIM];    // gelu out (x256)

__device__ __half g_wqkv_h[LAYERS * CDIM * 3 * CDIM];
__device__ __half g_wo_h  [LAYERS * CDIM * CDIM];
__device__ __half g_wm1_h [LAYERS * CDIM * MLPDIM];
__device__ __half g_wm2_h [LAYERS * MLPDIM * CDIM];

// ------------------------------ helpers ------------------------------------
__device__ __forceinline__ float gelu_f(float x) {
    float x3 = x * x * x;
    return 0.5f * x * (1.0f + tanhf(0.7978845608028654f * (x + 0.044715f * x3)));
}

__device__ __forceinline__ void ldsm_x4(unsigned* r, unsigned addr) {
    asm volatile("ldmatrix.sync.aligned.m8n8.x4.shared.b16 {%0,%1,%2,%3}, [%4];"
                 : "=r"(r[0]), "=r"(r[1]), "=r"(r[2]), "=r"(r[3]) : "r"(addr));
}
__device__ __forceinline__ void ldsm_x4t(unsigned* r, unsigned addr) {
    asm volatile("ldmatrix.sync.aligned.m8n8.x4.trans.shared.b16 {%0,%1,%2,%3}, [%4];"
                 : "=r"(r[0]), "=r"(r[1]), "=r"(r[2]), "=r"(r[3]) : "r"(addr));
}
__device__ __forceinline__ void ldsm_x2t(unsigned* r, unsigned addr) {
    asm volatile("ldmatrix.sync.aligned.m8n8.x2.trans.shared.b16 {%0,%1}, [%2];"
                 : "=r"(r[0]), "=r"(r[1]) : "r"(addr));
}
__device__ __forceinline__ void mma16816h(float* c, const unsigned* a, const unsigned* b) {
    asm volatile("mma.sync.aligned.m16n8k16.row.col.f32.f16.f16.f32 "
                 "{%0,%1,%2,%3}, {%4,%5,%6,%7}, {%8,%9}, {%0,%1,%2,%3};"
                 : "+f"(c[0]), "+f"(c[1]), "+f"(c[2]), "+f"(c[3])
                 : "r"(a[0]), "r"(a[1]), "r"(a[2]), "r"(a[3]),
                   "r"(b[0]), "r"(b[1]));
}
__device__ __forceinline__ void cpa16(unsigned dst, const void* src) {
    asm volatile("cp.async.cg.shared.global [%0], [%1], 16;" :: "r"(dst), "l"(src));
}
__device__ __forceinline__ void cpa_commit() { asm volatile("cp.async.commit_group;"); }
template <int NWAIT>
__device__ __forceinline__ void cpa_wait() {
    asm volatile("cp.async.wait_group %0;" :: "n"(NWAIT));
}

// fp16 scaled split: hi/lo of (ASCALE*x, ASCALE*y)
__device__ __forceinline__ void pack_h2s(float x, float y, unsigned& hi, unsigned& lo) {
    float xs = x * ASCALE, ys = y * ASCALE;
    __half hx = __float2half_rn(xs);
    __half hy = __float2half_rn(ys);
    __half lx = __float2half_rn(xs - __half2float(hx));
    __half ly = __float2half_rn(ys - __half2float(hy));
    __half2 H = __halves2half2(hx, hy);
    __half2 L = __halves2half2(lx, ly);
    hi = *(unsigned*)&H;
    lo = *(unsigned*)&L;
}

// --------------------------- weight fp16 cast ------------------------------
__global__ void wcast_kernel(const float* __restrict__ src,
                             __half* __restrict__ h, int n4)
{
    int i = blockIdx.x * 256 + threadIdx.x;
    if (i < n4) {
        float4 v = ((const float4*)src)[i];
        __half2 a = __halves2half2(__float2half_rn(v.x), __float2half_rn(v.y));
        __half2 b = __halves2half2(__float2half_rn(v.z), __float2half_rn(v.w));
        ((__half2*)h)[i * 2]     = a;
        ((__half2*)h)[i * 2 + 1] = b;
    }
}

// ------------------------------ embed + PE ---------------------------------
__global__ void embed_kernel(const float* __restrict__ feats,
                             const int*   __restrict__ coords,
                             const float* __restrict__ ex,
                             const float* __restrict__ ey,
                             const float* __restrict__ ez,
                             const float* __restrict__ w_in,
                             const float* __restrict__ b_in)
{
    int n = blockIdx.x;
    int c = threadIdx.x;
    const float* f = feats + (size_t)n * 8;
    float acc = b_in[c];
#pragma unroll
    for (int l = 0; l < 8; l++) acc += f[l] * w_in[l * CDIM + c];

    int cx = coords[n * 4 + 1];
    int cy = coords[n * 4 + 2];
    int cz = coords[n * 4 + 3];
    float pe;
    if (c < 170)      pe = ex[cx * 170 + c];
    else if (c < 340) pe = ey[cy * 170 + (c - 170)];
    else              pe = ez[cz * 172 + (c - 340)];
    g_h[(size_t)n * CDIM + c] = acc + pe;
}

// ------------------------------ layernorm ----------------------------------
__global__ void __launch_bounds__(256)
ln_kernel(const float* __restrict__ x,
          const float* __restrict__ g,
          const float* __restrict__ b,
          float* __restrict__ of,
          __half* __restrict__ oh,
          __half* __restrict__ ol,
          float eps, int has_gb)
{
    int n   = blockIdx.x;
    int tid = threadIdx.x;
    const float* xr = x + (size_t)n * CDIM;
    float v0 = xr[tid], v1 = xr[tid + 256];
    float s  = v0 + v1;
    float s2 = v0 * v0 + v1 * v1;
#pragma unroll
    for (int off = 16; off; off >>= 1) {
        s  += __shfl_xor_sync(0xffffffffu, s,  off);
        s2 += __shfl_xor_sync(0xffffffffu, s2, off);
    }
    __shared__ float sh[16];
    __shared__ float stats[2];
    int wid = tid >> 5, lane = tid & 31;
    if (lane == 0) { sh[wid] = s; sh[wid + 8] = s2; }
    __syncthreads();
    if (tid == 0) {
        float ts = 0.f, ts2 = 0.f;
#pragma unroll
        for (int i = 0; i < 8; i++) { ts += sh[i]; ts2 += sh[i + 8]; }
        float mean = ts * (1.0f / 512.0f);
        float var  = ts2 * (1.0f / 512.0f) - mean * mean;
        if (var < 0.f) var = 0.f;
        stats[0] = mean;
        stats[1] = rsqrtf(var + eps);
    }
    __syncthreads();
    float mean = stats[0], r = stats[1];
    float o0 = (v0 - mean) * r;
    float o1 = (v1 - mean) * r;
    if (has_gb) {
        o0 = o0 * g[tid]       + b[tid];
        o1 = o1 * g[tid + 256] + b[tid + 256];
    }
    size_t base = (size_t)n * CDIM;
    if (of) { of[base + tid] = o0; of[base + tid + 256] = o1; }
    if (oh) {
        float s0 = o0 * ASCALE, s1 = o1 * ASCALE;
        __half h0 = __float2half_rn(s0);
        __half h1 = __float2half_rn(s1);
        oh[base + tid]       = h0;
        oh[base + tid + 256] = h1;
        ol[base + tid]       = __float2half_rn(s0 - __half2float(h0));
        ol[base + tid + 256] = __float2half_rn(s1 - __half2float(h1));
    }
}

// ----------------- fp16x2 tensor-core GEMM ---------------------------------
// D = A256h@Bh + A256l@Bh ;  C = epi( D/256 + bias )
// epi 0: fp32 Cf; 1: Cf += residual; 2: gelu -> fp16 Ch/Cl; 3: fp16 Ch/Cl
#define BM 128
#define BN 128
#define BK2 32
#define ASTR2 40
#define BSTR2 136
#define A_PL (128 * ASTR2)
#define B_PL (32 * BSTR2)
#define STG  (2 * A_PL + B_PL)
#define GSMEM_BYTES (2 * STG * 2)

__global__ void __launch_bounds__(256, 2)
gemm_f16_kernel(const __half* __restrict__ Ah, const __half* __restrict__ Al,
                const __half* __restrict__ Bh,
                const float* __restrict__ bias, float* __restrict__ Cf,
                __half* __restrict__ Ch, __half* __restrict__ Cl,
                int M, int N, int K, int epi)
{
    extern __shared__ __align__(16) __half smemh[];

    const int tid  = threadIdx.x;
    const int wid  = tid >> 5;
    const int lane = tid & 31;
    const int n0 = blockIdx.x * BN;
    const int m0 = blockIdx.y * BM;
    const int wm = (wid >> 2) * 64;
    const int wn = (wid & 3) * 32;

    float acc[4][4][4];
#pragma unroll
    for (int i = 0; i < 4; i++)
#pragma unroll
        for (int j = 0; j < 4; j++)
#pragma unroll
            for (int k = 0; k < 4; k++) acc[i][j][k] = 0.f;

    const int a_row = tid >> 2,  a_off = (tid & 3) << 3;
    const int b_row = tid >> 3,  b_c = (tid & 7) << 4;

    auto stage = [&](int s, int k0) {
        __half* base = smemh + s * STG;
#pragma unroll
        for (int p = 0; p < 2; p++) {
            const __half* src = p ? Al : Ah;
            __half* d = base + p * A_PL;
            cpa16((unsigned)__cvta_generic_to_shared(d + a_row * ASTR2 + a_off),
                  src + (size_t)(m0 + a_row) * K + k0 + a_off);
            cpa16((unsigned)__cvta_generic_to_shared(d + (a_row + 64) * ASTR2 + a_off),
                  src + (size_t)(m0 + a_row + 64) * K + k0 + a_off);
        }
        {
            __half* d = base + 2 * A_PL;
            cpa16((unsigned)__cvta_generic_to_shared(d + b_row * BSTR2 + b_c),
                  Bh + (size_t)(k0 + b_row) * N + n0 + b_c);
            cpa16((unsigned)__cvta_generic_to_shared(d + b_row * BSTR2 + b_c + 8),
                  Bh + (size_t)(k0 + b_row) * N + n0 + b_c + 8);
        }
        cpa_commit();
    };

    stage(0, 0);
    const int KT = K / BK2;
    for (int kt = 0; kt < KT; kt++) {
        int buf = kt & 1;
        if (kt + 1 < KT) { stage(buf ^ 1, (kt + 1) * BK2); cpa_wait<1>(); }
        else             { cpa_wait<0>(); }
        __syncthreads();

        __half* base = smemh + buf * STG;
        unsigned aH = (unsigned)__cvta_generic_to_shared(
            base + (wm + (lane & 15)) * ASTR2 + ((lane >> 4) << 3));
        unsigned aL = aH + A_PL * 2;
        unsigned bH = (unsigned)__cvta_generic_to_shared(
            base + 2 * A_PL + (lane & 15) * BSTR2 + wn);

#pragma unroll
        for (int ks = 0; ks < 2; ks++) {
            unsigned bh[4][2];
#pragma unroll
            for (int nb = 0; nb < 4; nb++) {
                unsigned off = (unsigned)(ks * 16 * BSTR2) * 2 + nb * 16;
                ldsm_x2t(bh[nb], bH + off);
            }
#pragma unroll
            for (int mb = 0; mb < 4; mb++) {
                unsigned ah[4], al4[4];
                unsigned off = (unsigned)(mb * 16 * ASTR2 + ks * 16) * 2;
                ldsm_x4(ah,  aH + off);
                ldsm_x4(al4, aL + off);
#pragma unroll
                for (int nb = 0; nb < 4; nb++) {
                    mma16816h(acc[mb][nb], ah,  bh[nb]);
                    mma16816h(acc[mb][nb], al4, bh[nb]);
                }
            }
        }
        __syncthreads();
    }

    // ---- epilogue ----
#pragma unroll
    for (int mb = 0; mb < 4; mb++) {
        int m = m0 + wm + mb * 16 + (lane >> 2);
#pragma unroll
        for (int nb = 0; nb < 4; nb++) {
            int n = n0 + wn + nb * 8 + ((lane & 3) << 1);
            float2 bv = *(const float2*)(bias + n);
            float c0 = acc[mb][nb][0] * INV_ASCALE + bv.x;
            float c1 = acc[mb][nb][1] * INV_ASCALE + bv.y;
            float c2 = acc[mb][nb][2] * INV_ASCALE + bv.x;
            float c3 = acc[mb][nb][3] * INV_ASCALE + bv.y;
            if (epi >= 2) {
                if (epi == 2) {
                    c0 = gelu_f(c0); c1 = gelu_f(c1);
                    c2 = gelu_f(c2); c3 = gelu_f(c3);
                }
                unsigned h0, l0, h1, l1;
                pack_h2s(c0, c1, h0, l0);
                pack_h2s(c2, c3, h1, l1);
                *(unsigned*)(Ch + (size_t)m * N + n)       = h0;
                *(unsigned*)(Cl + (size_t)m * N + n)       = l0;
                *(unsigned*)(Ch + (size_t)(m + 8) * N + n) = h1;
                *(unsigned*)(Cl + (size_t)(m + 8) * N + n) = l1;
            } else {
                float* p0 = Cf + (size_t)m * N + n;
                float* p1 = Cf + (size_t)(m + 8) * N + n;
                if (epi == 1) {
                    float2 r0 = *(float2*)p0;
                    float2 r1 = *(float2*)p1;
                    c0 += r0.x; c1 += r0.y; c2 += r1.x; c3 += r1.y;
                }
                *(float2*)p0 = make_float2(c0, c1);
                *(float2*)p1 = make_float2(c2, c3);
            }
        }
    }
}

// ------------------- flash attention (fp16x2, cp.async staged) -------------
// qkv stored as scaled fp16 hi/lo. smem: Qh, Ql, Kh, Vh (4 tiles, 44KB).
#define ASTR 88
#define AQH  0
#define AQL  (64 * ASTR)
#define AKH  (2 * 64 * ASTR)
#define AVH  (3 * 64 * ASTR)
#define ATT_SMEM (4 * 64 * ASTR * 2)

__global__ void __launch_bounds__(128)
attn_mma_kernel(const __half* __restrict__ qkvh,
                const __half* __restrict__ qkvl,
                __half* __restrict__ oh,
                __half* __restrict__ ol)
{
    extern __shared__ __align__(16) __half sm[];
    const int tid  = threadIdx.x;
    const int wid  = tid >> 5;
    const int lane = tid & 31;
    const int qt = blockIdx.x, h = blockIdx.y, w = blockIdx.z;
    const int tok0 = w * 512;
    const int q0   = qt * 64;
    const int qoff = h * DHEAD;
    const int koff = CDIM + h * DHEAD;
    const int voff = 2 * CDIM + h * DHEAD;
    const int wm   = wid * 16;

    const unsigned sQH = (unsigned)__cvta_generic_to_shared(&sm[AQH]);
    const unsigned sQL = (unsigned)__cvta_generic_to_shared(&sm[AQL]);
    const unsigned sKH = (unsigned)__cvta_generic_to_shared(&sm[AKH]);
    const unsigned sVH = (unsigned)__cvta_generic_to_shared(&sm[AVH]);

    // ---- stage Q hi/lo via cp.async (64 rows x 8 chunks each) ----
#pragma unroll
    for (int i = 0; i < 4; i++) {
        int id = tid + i * 128;
        int r = id >> 3, c = (id & 7) << 3;
        size_t src = (size_t)(tok0 + q0 + r) * (3 * CDIM) + qoff + c;
        unsigned doff = (unsigned)(r * ASTR + c) * 2;
        cpa16(sQH + doff, qkvh + src);
        cpa16(sQL + doff, qkvl + src);
    }
    cpa_commit();
    cpa_wait<0>();
    __syncthreads();

    // ---- Q fragments in registers ----
    unsigned qh[4][4], ql[4][4];
    {
        int row = wm + (lane & 15);
        int coloff = (lane >> 4) << 3;
#pragma unroll
        for (int ks = 0; ks < 4; ks++) {
            unsigned off = (unsigned)(row * ASTR + ks * 16 + coloff) * 2;
            ldsm_x4(qh[ks], sQH + off);
            ldsm_x4(ql[ks], sQL + off);
        }
    }

    float m0 = -1e30f, m1 = -1e30f, l0 = 0.f, l1 = 0.f;
    float oacc[8][4];
#pragma unroll
    for (int i = 0; i < 8; i++)
#pragma unroll
        for (int j = 0; j < 4; j++) oacc[i][j] = 0.f;

    const int k_key  = ((lane >> 4) << 3) + (lane & 7);
    const int k_kc   = ((lane >> 3) & 1) << 3;
    const int v_kr   = (((lane >> 3) & 1) << 3) + (lane & 7);
    const int v_col  = (lane >> 4) << 3;

    for (int kt = 0; kt < 8; kt++) {
        __syncthreads();
        // stage K hi + V hi (64 rows x 8 chunks each)
#pragma unroll
        for (int i = 0; i < 4; i++) {
            int id = tid + i * 128;
            int r = id >> 3, c = (id & 7) << 3;
            size_t rowb = (size_t)(tok0 + kt * 64 + r) * (3 * CDIM);
            unsigned doff = (unsigned)(r * ASTR + c) * 2;
            cpa16(sKH + doff, qkvh + rowb + koff + c);
            cpa16(sVH + doff, qkvh + rowb + voff + c);
        }
        cpa_commit();
        cpa_wait<0>();
        __syncthreads();

        // ---- S = Q K^T (2 passes) ----
        float s[8][4];
#pragma unroll
        for (int i = 0; i < 8; i++)
#pragma unroll
            for (int j = 0; j < 4; j++) s[i][j] = 0.f;

#pragma unroll
        for (int p = 0; p < 4; p++) {
#pragma unroll
            for (int ks = 0; ks < 4; ks++) {
                unsigned kb[4];
                unsigned off = (unsigned)((p * 16 + k_key) * ASTR + ks * 16 + k_kc) * 2;
                ldsm_x4(kb, sKH + off);
                mma16816h(s[2 * p],     qh[ks], &kb[0]);
                mma16816h(s[2 * p],     ql[ks], &kb[0]);
                mma16816h(s[2 * p + 1], qh[ks], &kb[2]);
                mma16816h(s[2 * p + 1], ql[ks], &kb[2]);
            }
        }

        // ---- online softmax (scaled) ----
        float mx0 = -1e30f, mx1 = -1e30f;
#pragma unroll
        for (int nb = 0; nb < 8; nb++) {
            s[nb][0] *= QK_SCALE; s[nb][1] *= QK_SCALE;
            s[nb][2] *= QK_SCALE; s[nb][3] *= QK_SCALE;
            mx0 = fmaxf(mx0, fmaxf(s[nb][0], s[nb][1]));
            mx1 = fmaxf(mx1, fmaxf(s[nb][2], s[nb][3]));
        }
        mx0 = fmaxf(mx0, __shfl_xor_sync(0xffffffffu, mx0, 1));
        mx0 = fmaxf(mx0, __shfl_xor_sync(0xffffffffu, mx0, 2));
        mx1 = fmaxf(mx1, __shfl_xor_sync(0xffffffffu, mx1, 1));
        mx1 = fmaxf(mx1, __shfl_xor_sync(0xffffffffu, mx1, 2));

        float nm0 = fmaxf(m0, mx0);
        float nm1 = fmaxf(m1, mx1);
        float al0 = __expf(m0 - nm0);
        float al1 = __expf(m1 - nm1);
        m0 = nm0; m1 = nm1;

        float sum0 = 0.f, sum1 = 0.f;
#pragma unroll
        for (int nb = 0; nb < 8; nb++) {
            s[nb][0] = __expf(s[nb][0] - nm0);
            s[nb][1] = __expf(s[nb][1] - nm0);
            s[nb][2] = __expf(s[nb][2] - nm1);
            s[nb][3] = __expf(s[nb][3] - nm1);
            sum0 += s[nb][0] + s[nb][1];
            sum1 += s[nb][2] + s[nb][3];
        }
        sum0 += __shfl_xor_sync(0xffffffffu, sum0, 1);
        sum0 += __shfl_xor_sync(0xffffffffu, sum0, 2);
        sum1 += __shfl_xor_sync(0xffffffffu, sum1, 1);
        sum1 += __shfl_xor_sync(0xffffffffu, sum1, 2);
        l0 = l0 * al0 + sum0;
        l1 = l1 * al1 + sum1;

#pragma unroll
        for (int nb = 0; nb < 8; nb++) {
            oacc[nb][0] *= al0; oacc[nb][1] *= al0;
            oacc[nb][2] *= al1; oacc[nb][3] *= al1;
        }

        // ---- O += P V (2 passes) ----
#pragma unroll
        for (int kk = 0; kk < 4; kk++) {
            unsigned pa_h[4], pa_l[4];
            pack_h2s(s[2 * kk][0],     s[2 * kk][1],     pa_h[0], pa_l[0]);
            pack_h2s(s[2 * kk][2],     s[2 * kk][3],     pa_h[1], pa_l[1]);
            pack_h2s(s[2 * kk + 1][0], s[2 * kk + 1][1], pa_h[2], pa_l[2]);
            pack_h2s(s[2 * kk + 1][2], s[2 * kk + 1][3], pa_h[3], pa_l[3]);
#pragma unroll
            for (int p = 0; p < 4; p++) {
                unsigned vb[4];
                unsigned off = (unsigned)((kk * 16 + v_kr) * ASTR + p * 16 + v_col) * 2;
                ldsm_x4t(vb, sVH + off);
                mma16816h(oacc[2 * p],     pa_h, &vb[0]);
                mma16816h(oacc[2 * p],     pa_l, &vb[0]);
                mma16816h(oacc[2 * p + 1], pa_h, &vb[2]);
                mma16816h(oacc[2 * p + 1], pa_l, &vb[2]);
            }
        }
    }

    // ---- epilogue: o = oacc/(65536*l); store scaled fp16 hi/lo ----
    float i0 = 1.0f / (65536.0f * l0);
    float i1 = 1.0f / (65536.0f * l1);
    int r0  = tok0 + q0 + wm + (lane >> 2);
    int col = h * DHEAD + ((lane & 3) << 1);
#pragma unroll
    for (int nb = 0; nb < 8; nb++) {
        unsigned h0, lo0, h1, lo1;
        pack_h2s(oacc[nb][0] * i0, oacc[nb][1] * i0, h0, lo0);
        pack_h2s(oacc[nb][2] * i1, oacc[nb][3] * i1, h1, lo1);
        size_t p0 = (size_t)r0 * CDIM + col + nb * 8;
        size_t p1 = (size_t)(r0 + 8) * CDIM + col + nb * 8;
        *(unsigned*)(oh + p0) = h0;
        *(unsigned*)(ol + p0) = lo0;
        *(unsigned*)(oh + p1) = h1;
        *(unsigned*)(ol + p1) = lo1;
    }
}

// ----------------------------- out head ------------------------------------
__global__ void outhead_kernel(const float* __restrict__ a,
                               const float* __restrict__ w,
                               const float* __restrict__ b)
{
    __shared__ float row[CDIM];
    int n = blockIdx.x;
    for (int i = threadIdx.x; i < CDIM; i += 64)
        row[i] = a[(size_t)n * CDIM + i];
    __syncthreads();
    int oc = threadIdx.x;
    if (oc < OUTC) {
        float acc = b[oc];
#pragma unroll 8
        for (int k = 0; k < CDIM; k++)
            acc += row[k] * w[k * OUTC + oc];
        g_out[n * OUTC + oc] = acc;
    }
}

// ---------------------------- postprocess ----------------------------------
__global__ void post_kernel(const int* __restrict__ coords,
                            const float* __restrict__ perturb,
                            float* __restrict__ out)
{
    int idx = blockIdx.x * 256 + threadIdx.x;
    if (idx >= NTOK * NGAUSS) return;
    int n = idx >> 2, g = idx & 3;
    const float* r = g_out + n * OUTC;
#pragma unroll
    for (int j = 0; j < 3; j++) {
        float off = tanhf(r[g * 3 + j] + perturb[g * 3 + j]) * 4.8828125e-4f;
        float xb  = ((float)coords[n * 4 + 1 + j] + 0.5f) * 0.0625f;
        out[idx * 3 + j]          = xb + off;
        out[49152 + idx * 3 + j]  = r[12 + g * 3 + j];
        out[98304 + idx * 3 + j]  = r[24 + g * 3 + j];
    }
#pragma unroll
    for (int j = 0; j < 4; j++)
        out[147456 + idx * 4 + j] = r[36 + g * 4 + j];
    out[212992 + idx] = r[52 + g];
}

// ------------------------------- launch ------------------------------------
extern "C" void kernel_launch(void* const* d_in, const int* in_sizes, int n_in,
                              void* d_out, int out_size)
{
    const float* feats   = (const float*)d_in[0];
    const int*   coords  = (const int*)  d_in[1];
    const float* emb_x   = (const float*)d_in[2];
    const float* emb_y   = (const float*)d_in[3];
    const float* emb_z   = (const float*)d_in[4];
    const float* w_in    = (const float*)d_in[5];
    const float* b_in    = (const float*)d_in[6];
    const float* ln1_g   = (const float*)d_in[7];
    const float* ln1_b   = (const float*)d_in[8];
    const float* w_qkv   = (const float*)d_in[9];
    const float* b_qkv   = (const float*)d_in[10];
    const float* w_o     = (const float*)d_in[11];
    const float* b_o     = (const float*)d_in[12];
    const float* ln2_g   = (const float*)d_in[13];
    const float* ln2_b   = (const float*)d_in[14];
    const float* w_m1    = (const float*)d_in[15];
    const float* b_m1    = (const float*)d_in[16];
    const float* w_m2    = (const float*)d_in[17];
    const float* b_m2    = (const float*)d_in[18];
    const float* w_out   = (const float*)d_in[19];
    const float* b_out   = (const float*)d_in[20];
    const float* perturb = (const float*)d_in[21];
    float* out = (float*)d_out;

    float *ph, *pa;
    __half *pah, *pal, *pqh, *pql, *poh, *pol, *pmh, *pml;
    __half *pwqh, *pwoh, *pw1h, *pw2h;
    cudaGetSymbolAddress((void**)&ph,   g_h);
    cudaGetSymbolAddress((void**)&pa,   g_a);
    cudaGetSymbolAddress((void**)&pah,  g_ah);
    cudaGetSymbolAddress((void**)&pal,  g_al);
    cudaGetSymbolAddress((void**)&pqh,  g_qh);
    cudaGetSymbolAddress((void**)&pql,  g_ql);
    cudaGetSymbolAddress((void**)&poh,  g_oh);
    cudaGetSymbolAddress((void**)&pol,  g_ol);
    cudaGetSymbolAddress((void**)&pmh,  g_mh);
    cudaGetSymbolAddress((void**)&pml,  g_ml);
    cudaGetSymbolAddress((void**)&pwqh, g_wqkv_h);
    cudaGetSymbolAddress((void**)&pwoh, g_wo_h);
    cudaGetSymbolAddress((void**)&pw1h, g_wm1_h);
    cudaGetSymbolAddress((void**)&pw2h, g_wm2_h);

    cudaFuncSetAttribute(attn_mma_kernel,
                         cudaFuncAttributeMaxDynamicSharedMemorySize, ATT_SMEM);
    cudaFuncSetAttribute(gemm_f16_kernel,
                         cudaFuncAttributeMaxDynamicSharedMemorySize, GSMEM_BYTES);

    {
        int n4q = LAYERS * CDIM * 3 * CDIM / 4;
        int n4o = LAYERS * CDIM * CDIM / 4;
        int n4m = LAYERS * CDIM * MLPDIM / 4;
        wcast_kernel<<<(n4q + 255) / 256, 256>>>(w_qkv, pwqh, n4q);
        wcast_kernel<<<(n4o + 255) / 256, 256>>>(w_o,   pwoh, n4o);
        wcast_kernel<<<(n4m + 255) / 256, 256>>>(w_m1,  pw1h, n4m);
        wcast_kernel<<<(n4m + 255) / 256, 256>>>(w_m2,  pw2h, n4m);
    }

    embed_kernel<<<NTOK, CDIM>>>(feats, coords, emb_x, emb_y, emb_z, w_in, b_in);

    for (int l = 0; l < LAYERS; l++) {
        ln_kernel<<<NTOK, 256>>>(ph, ln1_g + l * CDIM, ln1_b + l * CDIM,
                                 nullptr, pah, pal, 1e-6f, 1);
        gemm_f16_kernel<<<dim3(3 * CDIM / BN, NTOK / BM), 256, GSMEM_BYTES>>>(
            pah, pal, pwqh + (size_t)l * CDIM * 3 * CDIM,
            b_qkv + l * 3 * CDIM, nullptr, pqh, pql,
            NTOK, 3 * CDIM, CDIM, 3);
        attn_mma_kernel<<<dim3(8, HEADS, 8), 128, ATT_SMEM>>>(pqh, pql, poh, pol);
        gemm_f16_kernel<<<dim3(CDIM / BN, NTOK / BM), 256, GSMEM_BYTES>>>(
            poh, pol, pwoh + (size_t)l * CDIM * CDIM,
            b_o + l * CDIM, ph, nullptr, nullptr,
            NTOK, CDIM, CDIM, 1);
        ln_kernel<<<NTOK, 256>>>(ph, ln2_g + l * CDIM, ln2_b + l * CDIM,
                                 nullptr, pah, pal, 1e-6f, 1);
        gemm_f16_kernel<<<dim3(MLPDIM / BN, NTOK / BM), 256, GSMEM_BYTES>>>(
            pah, pal, pw1h + (size_t)l * CDIM * MLPDIM,
            b_m1 + l * MLPDIM, nullptr, pmh, pml,
            NTOK, MLPDIM, CDIM, 2);
        gemm_f16_kernel<<<dim3(CDIM / BN, NTOK / BM), 256, GSMEM_BYTES>>>(
            pmh, pml, pw2h + (size_t)l * MLPDIM * CDIM,
            b_m2 + l * CDIM, ph, nullptr, nullptr,
            NTOK, CDIM, MLPDIM, 1);
    }

    ln_kernel<<<NTOK, 256>>>(ph, nullptr, nullptr, pa, nullptr, nullptr, 1e-5f, 0);
    outhead_kernel<<<NTOK, 64>>>(pa, w_out, b_out);
    post_kernel<<<(NTOK * NGAUSS + 255) / 256, 256>>>(coords, perturb, out);
}

// round 10
// speedup vs baseline: 1.8953x; 1.3575x over previous
#include <cuda_runtime.h>
#include <cuda_fp16.h>
#include <math.h>
#include <stdint.h>

// ---------------------------------------------------------------------------
// GSDecoder round 10: single-pass fp16 GEMMs (A-lo dropped; error budget
// ~8e-4 < 1e-3 per the calibrated model). Attention unchanged from round 9
// (Q hi/lo 2-pass, K/V hi). qkv GEMM still emits hi/lo for attention Q.
// ---------------------------------------------------------------------------

#define NTOK   4096
#define CDIM   512
#define HEADS  8
#define DHEAD  64
#define LAYERS 8
#define MLPDIM 2048
#define OUTC   56
#define NGAUSS 4

#define ASCALE     256.0f
#define INV_ASCALE 0.00390625f
#define QK_SCALE   1.9073486328125e-6f   // 1/(256*256) * 1/8

// ------------------------- scratch (device globals) ------------------------
__device__ float g_h  [NTOK * CDIM];
__device__ float g_a  [NTOK * CDIM];
__device__ float g_out[NTOK * OUTC];

__device__ __half g_ah[NTOK * CDIM];                            // LN out (x256)
__device__ __half g_qh[NTOK * 3 * CDIM], g_ql[NTOK * 3 * CDIM]; // qkv (x256, hi/lo)
__device__ __half g_oh[NTOK * CDIM];                            // attn out (x256)
__device__ __half g_mh[NTOK * MLPDIM];                          // gelu out (x256)

__device__ __half g_wqkv_h[LAYERS * CDIM * 3 * CDIM];
__device__ __half g_wo_h  [LAYERS * CDIM * CDIM];
__device__ __half g_wm1_h [LAYERS * CDIM * MLPDIM];
__device__ __half g_wm2_h [LAYERS * MLPDIM * CDIM];

// ------------------------------ helpers ------------------------------------
__device__ __forceinline__ float gelu_f(float x) {
    float x3 = x * x * x;
    return 0.5f * x * (1.0f + tanhf(0.7978845608028654f * (x + 0.044715f * x3)));
}

__device__ __forceinline__ void ldsm_x4(unsigned* r, unsigned addr) {
    asm volatile("ldmatrix.sync.aligned.m8n8.x4.shared.b16 {%0,%1,%2,%3}, [%4];"
                 : "=r"(r[0]), "=r"(r[1]), "=r"(r[2]), "=r"(r[3]) : "r"(addr));
}
__device__ __forceinline__ void ldsm_x4t(unsigned* r, unsigned addr) {
    asm volatile("ldmatrix.sync.aligned.m8n8.x4.trans.shared.b16 {%0,%1,%2,%3}, [%4];"
                 : "=r"(r[0]), "=r"(r[1]), "=r"(r[2]), "=r"(r[3]) : "r"(addr));
}
__device__ __forceinline__ void ldsm_x2t(unsigned* r, unsigned addr) {
    asm volatile("ldmatrix.sync.aligned.m8n8.x2.trans.shared.b16 {%0,%1}, [%2];"
                 : "=r"(r[0]), "=r"(r[1]) : "r"(addr));
}
__device__ __forceinline__ void mma16816h(float* c, const unsigned* a, const unsigned* b) {
    asm volatile("mma.sync.aligned.m16n8k16.row.col.f32.f16.f16.f32 "
                 "{%0,%1,%2,%3}, {%4,%5,%6,%7}, {%8,%9}, {%0,%1,%2,%3};"
                 : "+f"(c[0]), "+f"(c[1]), "+f"(c[2]), "+f"(c[3])
                 : "r"(a[0]), "r"(a[1]), "r"(a[2]), "r"(a[3]),
                   "r"(b[0]), "r"(b[1]));
}
__device__ __forceinline__ void cpa16(unsigned dst, const void* src) {
    asm volatile("cp.async.cg.shared.global [%0], [%1], 16;" :: "r"(dst), "l"(src));
}
__device__ __forceinline__ void cpa_commit() { asm volatile("cp.async.commit_group;"); }
template <int NWAIT>
__device__ __forceinline__ void cpa_wait() {
    asm volatile("cp.async.wait_group %0;" :: "n"(NWAIT));
}

// scaled fp16 hi/lo of (256x, 256y)
__device__ __forceinline__ void pack_h2s(float x, float y, unsigned& hi, unsigned& lo) {
    float xs = x * ASCALE, ys = y * ASCALE;
    __half hx = __float2half_rn(xs);
    __half hy = __float2half_rn(ys);
    __half lx = __float2half_rn(xs - __half2float(hx));
    __half ly = __float2half_rn(ys - __half2float(hy));
    __half2 H = __halves2half2(hx, hy);
    __half2 L = __halves2half2(lx, ly);
    hi = *(unsigned*)&H;
    lo = *(unsigned*)&L;
}
// scaled fp16 hi only
__device__ __forceinline__ unsigned pack_h2(float x, float y) {
    __half2 H = __halves2half2(__float2half_rn(x * ASCALE), __float2half_rn(y * ASCALE));
    return *(unsigned*)&H;
}

// --------------------------- weight fp16 cast ------------------------------
__global__ void wcast_kernel(const float* __restrict__ src,
                             __half* __restrict__ h, int n4)
{
    int i = blockIdx.x * 256 + threadIdx.x;
    if (i < n4) {
        float4 v = ((const float4*)src)[i];
        __half2 a = __halves2half2(__float2half_rn(v.x), __float2half_rn(v.y));
        __half2 b = __halves2half2(__float2half_rn(v.z), __float2half_rn(v.w));
        ((__half2*)h)[i * 2]     = a;
        ((__half2*)h)[i * 2 + 1] = b;
    }
}

// ------------------------------ embed + PE ---------------------------------
__global__ void embed_kernel(const float* __restrict__ feats,
                             const int*   __restrict__ coords,
                             const float* __restrict__ ex,
                             const float* __restrict__ ey,
                             const float* __restrict__ ez,
                             const float* __restrict__ w_in,
                             const float* __restrict__ b_in)
{
    int n = blockIdx.x;
    int c = threadIdx.x;
    const float* f = feats + (size_t)n * 8;
    float acc = b_in[c];
#pragma unroll
    for (int l = 0; l < 8; l++) acc += f[l] * w_in[l * CDIM + c];

    int cx = coords[n * 4 + 1];
    int cy = coords[n * 4 + 2];
    int cz = coords[n * 4 + 3];
    float pe;
    if (c < 170)      pe = ex[cx * 170 + c];
    else if (c < 340) pe = ey[cy * 170 + (c - 170)];
    else              pe = ez[cz * 172 + (c - 340)];
    g_h[(size_t)n * CDIM + c] = acc + pe;
}

// ------------------------------ layernorm ----------------------------------
__global__ void __launch_bounds__(256)
ln_kernel(const float* __restrict__ x,
          const float* __restrict__ g,
          const float* __restrict__ b,
          float* __restrict__ of,
          __half* __restrict__ oh,
          float eps, int has_gb)
{
    int n   = blockIdx.x;
    int tid = threadIdx.x;
    const float* xr = x + (size_t)n * CDIM;
    float v0 = xr[tid], v1 = xr[tid + 256];
    float s  = v0 + v1;
    float s2 = v0 * v0 + v1 * v1;
#pragma unroll
    for (int off = 16; off; off >>= 1) {
        s  += __shfl_xor_sync(0xffffffffu, s,  off);
        s2 += __shfl_xor_sync(0xffffffffu, s2, off);
    }
    __shared__ float sh[16];
    __shared__ float stats[2];
    int wid = tid >> 5, lane = tid & 31;
    if (lane == 0) { sh[wid] = s; sh[wid + 8] = s2; }
    __syncthreads();
    if (tid == 0) {
        float ts = 0.f, ts2 = 0.f;
#pragma unroll
        for (int i = 0; i < 8; i++) { ts += sh[i]; ts2 += sh[i + 8]; }
        float mean = ts * (1.0f / 512.0f);
        float var  = ts2 * (1.0f / 512.0f) - mean * mean;
        if (var < 0.f) var = 0.f;
        stats[0] = mean;
        stats[1] = rsqrtf(var + eps);
    }
    __syncthreads();
    float mean = stats[0], r = stats[1];
    float o0 = (v0 - mean) * r;
    float o1 = (v1 - mean) * r;
    if (has_gb) {
        o0 = o0 * g[tid]       + b[tid];
        o1 = o1 * g[tid + 256] + b[tid + 256];
    }
    size_t base = (size_t)n * CDIM;
    if (of) { of[base + tid] = o0; of[base + tid + 256] = o1; }
    if (oh) {
        oh[base + tid]       = __float2half_rn(o0 * ASCALE);
        oh[base + tid + 256] = __float2half_rn(o1 * ASCALE);
    }
}

// ----------------- single-pass fp16 tensor-core GEMM -----------------------
// D = A256h@Bh ;  C = epi( D/256 + bias )
// epi 0: fp32 Cf; 1: Cf += residual; 2: gelu -> fp16 Ch; 3: fp16 Ch+Cl (hi/lo)
#define BM 128
#define BN 128
#define BK2 32
#define ASTR2 40
#define BSTR2 136
#define A_PL (128 * ASTR2)            // 5120 halves
#define B_PL (32 * BSTR2)             // 4352 halves
#define STG  (A_PL + B_PL)            // 9472 halves per stage
#define GSMEM_BYTES (2 * STG * 2)     // 37888 bytes

__global__ void __launch_bounds__(256, 2)
gemm_f16_kernel(const __half* __restrict__ Ah,
                const __half* __restrict__ Bh,
                const float* __restrict__ bias, float* __restrict__ Cf,
                __half* __restrict__ Ch, __half* __restrict__ Cl,
                int M, int N, int K, int epi)
{
    extern __shared__ __align__(16) __half smemh[];

    const int tid  = threadIdx.x;
    const int wid  = tid >> 5;
    const int lane = tid & 31;
    const int n0 = blockIdx.x * BN;
    const int m0 = blockIdx.y * BM;
    const int wm = (wid >> 2) * 64;
    const int wn = (wid & 3) * 32;

    float acc[4][4][4];
#pragma unroll
    for (int i = 0; i < 4; i++)
#pragma unroll
        for (int j = 0; j < 4; j++)
#pragma unroll
            for (int k = 0; k < 4; k++) acc[i][j][k] = 0.f;

    const int a_row = tid >> 2,  a_off = (tid & 3) << 3;
    const int b_row = tid >> 3,  b_c = (tid & 7) << 4;

    auto stage = [&](int s, int k0) {
        __half* base = smemh + s * STG;
        cpa16((unsigned)__cvta_generic_to_shared(base + a_row * ASTR2 + a_off),
              Ah + (size_t)(m0 + a_row) * K + k0 + a_off);
        cpa16((unsigned)__cvta_generic_to_shared(base + (a_row + 64) * ASTR2 + a_off),
              Ah + (size_t)(m0 + a_row + 64) * K + k0 + a_off);
        __half* d = base + A_PL;
        cpa16((unsigned)__cvta_generic_to_shared(d + b_row * BSTR2 + b_c),
              Bh + (size_t)(k0 + b_row) * N + n0 + b_c);
        cpa16((unsigned)__cvta_generic_to_shared(d + b_row * BSTR2 + b_c + 8),
              Bh + (size_t)(k0 + b_row) * N + n0 + b_c + 8);
        cpa_commit();
    };

    stage(0, 0);
    const int KT = K / BK2;
    for (int kt = 0; kt < KT; kt++) {
        int buf = kt & 1;
        if (kt + 1 < KT) { stage(buf ^ 1, (kt + 1) * BK2); cpa_wait<1>(); }
        else             { cpa_wait<0>(); }
        __syncthreads();

        __half* base = smemh + buf * STG;
        unsigned aH = (unsigned)__cvta_generic_to_shared(
            base + (wm + (lane & 15)) * ASTR2 + ((lane >> 4) << 3));
        unsigned bH = (unsigned)__cvta_generic_to_shared(
            base + A_PL + (lane & 15) * BSTR2 + wn);

#pragma unroll
        for (int ks = 0; ks < 2; ks++) {
            unsigned bh[4][2];
#pragma unroll
            for (int nb = 0; nb < 4; nb++) {
                unsigned off = (unsigned)(ks * 16 * BSTR2) * 2 + nb * 16;
                ldsm_x2t(bh[nb], bH + off);
            }
#pragma unroll
            for (int mb = 0; mb < 4; mb++) {
                unsigned ah[4];
                unsigned off = (unsigned)(mb * 16 * ASTR2 + ks * 16) * 2;
                ldsm_x4(ah, aH + off);
#pragma unroll
                for (int nb = 0; nb < 4; nb++)
                    mma16816h(acc[mb][nb], ah, bh[nb]);
            }
        }
        __syncthreads();
    }

    // ---- epilogue ----
#pragma unroll
    for (int mb = 0; mb < 4; mb++) {
        int m = m0 + wm + mb * 16 + (lane >> 2);
#pragma unroll
        for (int nb = 0; nb < 4; nb++) {
            int n = n0 + wn + nb * 8 + ((lane & 3) << 1);
            float2 bv = *(const float2*)(bias + n);
            float c0 = acc[mb][nb][0] * INV_ASCALE + bv.x;
            float c1 = acc[mb][nb][1] * INV_ASCALE + bv.y;
            float c2 = acc[mb][nb][2] * INV_ASCALE + bv.x;
            float c3 = acc[mb][nb][3] * INV_ASCALE + bv.y;
            if (epi == 2) {
                c0 = gelu_f(c0); c1 = gelu_f(c1);
                c2 = gelu_f(c2); c3 = gelu_f(c3);
                *(unsigned*)(Ch + (size_t)m * N + n)       = pack_h2(c0, c1);
                *(unsigned*)(Ch + (size_t)(m + 8) * N + n) = pack_h2(c2, c3);
            } else if (epi == 3) {
                unsigned h0, l0, h1, l1;
                pack_h2s(c0, c1, h0, l0);
                pack_h2s(c2, c3, h1, l1);
                *(unsigned*)(Ch + (size_t)m * N + n)       = h0;
                *(unsigned*)(Cl + (size_t)m * N + n)       = l0;
                *(unsigned*)(Ch + (size_t)(m + 8) * N + n) = h1;
                *(unsigned*)(Cl + (size_t)(m + 8) * N + n) = l1;
            } else {
                float* p0 = Cf + (size_t)m * N + n;
                float* p1 = Cf + (size_t)(m + 8) * N + n;
                if (epi == 1) {
                    float2 r0 = *(float2*)p0;
                    float2 r1 = *(float2*)p1;
                    c0 += r0.x; c1 += r0.y; c2 += r1.x; c3 += r1.y;
                }
                *(float2*)p0 = make_float2(c0, c1);
                *(float2*)p1 = make_float2(c2, c3);
            }
        }
    }
}

// ------------------- flash attention (fp16x2, cp.async staged) -------------
#define ASTR 88
#define AQH  0
#define AQL  (64 * ASTR)
#define AKH  (2 * 64 * ASTR)
#define AVH  (3 * 64 * ASTR)
#define ATT_SMEM (4 * 64 * ASTR * 2)

__global__ void __launch_bounds__(128)
attn_mma_kernel(const __half* __restrict__ qkvh,
                const __half* __restrict__ qkvl,
                __half* __restrict__ oh)
{
    extern __shared__ __align__(16) __half sm[];
    const int tid  = threadIdx.x;
    const int wid  = tid >> 5;
    const int lane = tid & 31;
    const int qt = blockIdx.x, h = blockIdx.y, w = blockIdx.z;
    const int tok0 = w * 512;
    const int q0   = qt * 64;
    const int qoff = h * DHEAD;
    const int koff = CDIM + h * DHEAD;
    const int voff = 2 * CDIM + h * DHEAD;
    const int wm   = wid * 16;

    const unsigned sQH = (unsigned)__cvta_generic_to_shared(&sm[AQH]);
    const unsigned sQL = (unsigned)__cvta_generic_to_shared(&sm[AQL]);
    const unsigned sKH = (unsigned)__cvta_generic_to_shared(&sm[AKH]);
    const unsigned sVH = (unsigned)__cvta_generic_to_shared(&sm[AVH]);

#pragma unroll
    for (int i = 0; i < 4; i++) {
        int id = tid + i * 128;
        int r = id >> 3, c = (id & 7) << 3;
        size_t src = (size_t)(tok0 + q0 + r) * (3 * CDIM) + qoff + c;
        unsigned doff = (unsigned)(r * ASTR + c) * 2;
        cpa16(sQH + doff, qkvh + src);
        cpa16(sQL + doff, qkvl + src);
    }
    cpa_commit();
    cpa_wait<0>();
    __syncthreads();

    unsigned qh[4][4], ql[4][4];
    {
        int row = wm + (lane & 15);
        int coloff = (lane >> 4) << 3;
#pragma unroll
        for (int ks = 0; ks < 4; ks++) {
            unsigned off = (unsigned)(row * ASTR + ks * 16 + coloff) * 2;
            ldsm_x4(qh[ks], sQH + off);
            ldsm_x4(ql[ks], sQL + off);
        }
    }

    float m0 = -1e30f, m1 = -1e30f, l0 = 0.f, l1 = 0.f;
    float oacc[8][4];
#pragma unroll
    for (int i = 0; i < 8; i++)
#pragma unroll
        for (int j = 0; j < 4; j++) oacc[i][j] = 0.f;

    const int k_key  = ((lane >> 4) << 3) + (lane & 7);
    const int k_kc   = ((lane >> 3) & 1) << 3;
    const int v_kr   = (((lane >> 3) & 1) << 3) + (lane & 7);
    const int v_col  = (lane >> 4) << 3;

    for (int kt = 0; kt < 8; kt++) {
        __syncthreads();
#pragma unroll
        for (int i = 0; i < 4; i++) {
            int id = tid + i * 128;
            int r = id >> 3, c = (id & 7) << 3;
            size_t rowb = (size_t)(tok0 + kt * 64 + r) * (3 * CDIM);
            unsigned doff = (unsigned)(r * ASTR + c) * 2;
            cpa16(sKH + doff, qkvh + rowb + koff + c);
            cpa16(sVH + doff, qkvh + rowb + voff + c);
        }
        cpa_commit();
        cpa_wait<0>();
        __syncthreads();

        float s[8][4];
#pragma unroll
        for (int i = 0; i < 8; i++)
#pragma unroll
            for (int j = 0; j < 4; j++) s[i][j] = 0.f;

#pragma unroll
        for (int p = 0; p < 4; p++) {
#pragma unroll
            for (int ks = 0; ks < 4; ks++) {
                unsigned kb[4];
                unsigned off = (unsigned)((p * 16 + k_key) * ASTR + ks * 16 + k_kc) * 2;
                ldsm_x4(kb, sKH + off);
                mma16816h(s[2 * p],     qh[ks], &kb[0]);
                mma16816h(s[2 * p],     ql[ks], &kb[0]);
                mma16816h(s[2 * p + 1], qh[ks], &kb[2]);
                mma16816h(s[2 * p + 1], ql[ks], &kb[2]);
            }
        }

        float mx0 = -1e30f, mx1 = -1e30f;
#pragma unroll
        for (int nb = 0; nb < 8; nb++) {
            s[nb][0] *= QK_SCALE; s[nb][1] *= QK_SCALE;
            s[nb][2] *= QK_SCALE; s[nb][3] *= QK_SCALE;
            mx0 = fmaxf(mx0, fmaxf(s[nb][0], s[nb][1]));
            mx1 = fmaxf(mx1, fmaxf(s[nb][2], s[nb][3]));
        }
        mx0 = fmaxf(mx0, __shfl_xor_sync(0xffffffffu, mx0, 1));
        mx0 = fmaxf(mx0, __shfl_xor_sync(0xffffffffu, mx0, 2));
        mx1 = fmaxf(mx1, __shfl_xor_sync(0xffffffffu, mx1, 1));
        mx1 = fmaxf(mx1, __shfl_xor_sync(0xffffffffu, mx1, 2));

        float nm0 = fmaxf(m0, mx0);
        float nm1 = fmaxf(m1, mx1);
        float al0 = __expf(m0 - nm0);
        float al1 = __expf(m1 - nm1);
        m0 = nm0; m1 = nm1;

        float sum0 = 0.f, sum1 = 0.f;
#pragma unroll
        for (int nb = 0; nb < 8; nb++) {
            s[nb][0] = __expf(s[nb][0] - nm0);
            s[nb][1] = __expf(s[nb][1] - nm0);
            s[nb][2] = __expf(s[nb][2] - nm1);
            s[nb][3] = __expf(s[nb][3] - nm1);
            sum0 += s[nb][0] + s[nb][1];
            sum1 += s[nb][2] + s[nb][3];
        }
        sum0 += __shfl_xor_sync(0xffffffffu, sum0, 1);
        sum0 += __shfl_xor_sync(0xffffffffu, sum0, 2);
        sum1 += __shfl_xor_sync(0xffffffffu, sum1, 1);
        sum1 += __shfl_xor_sync(0xffffffffu, sum1, 2);
        l0 = l0 * al0 + sum0;
        l1 = l1 * al1 + sum1;

#pragma unroll
        for (int nb = 0; nb < 8; nb++) {
            oacc[nb][0] *= al0; oacc[nb][1] *= al0;
            oacc[nb][2] *= al1; oacc[nb][3] *= al1;
        }

#pragma unroll
        for (int kk = 0; kk < 4; kk++) {
            unsigned pa_h[4], pa_l[4];
            pack_h2s(s[2 * kk][0],     s[2 * kk][1],     pa_h[0], pa_l[0]);
            pack_h2s(s[2 * kk][2],     s[2 * kk][3],     pa_h[1], pa_l[1]);
            pack_h2s(s[2 * kk + 1][0], s[2 * kk + 1][1], pa_h[2], pa_l[2]);
            pack_h2s(s[2 * kk + 1][2], s[2 * kk + 1][3], pa_h[3], pa_l[3]);
#pragma unroll
            for (int p = 0; p < 4; p++) {
                unsigned vb[4];
                unsigned off = (unsigned)((kk * 16 + v_kr) * ASTR + p * 16 + v_col) * 2;
                ldsm_x4t(vb, sVH + off);
                mma16816h(oacc[2 * p],     pa_h, &vb[0]);
                mma16816h(oacc[2 * p],     pa_l, &vb[0]);
                mma16816h(oacc[2 * p + 1], pa_h, &vb[2]);
                mma16816h(oacc[2 * p + 1], pa_l, &vb[2]);
            }
        }
    }

    // ---- epilogue: o = oacc/(65536*l); store scaled fp16 hi ----
    float i0 = 1.0f / (65536.0f * l0);
    float i1 = 1.0f / (65536.0f * l1);
    int r0  = tok0 + q0 + wm + (lane >> 2);
    int col = h * DHEAD + ((lane & 3) << 1);
#pragma unroll
    for (int nb = 0; nb < 8; nb++) {
        size_t p0 = (size_t)r0 * CDIM + col + nb * 8;
        size_t p1 = (size_t)(r0 + 8) * CDIM + col + nb * 8;
        *(unsigned*)(oh + p0) = pack_h2(oacc[nb][0] * i0, oacc[nb][1] * i0);
        *(unsigned*)(oh + p1) = pack_h2(oacc[nb][2] * i1, oacc[nb][3] * i1);
    }
}

// ----------------------------- out head ------------------------------------
__global__ void outhead_kernel(const float* __restrict__ a,
                               const float* __restrict__ w,
                               const float* __restrict__ b)
{
    __shared__ float row[CDIM];
    int n = blockIdx.x;
    for (int i = threadIdx.x; i < CDIM; i += 64)
        row[i] = a[(size_t)n * CDIM + i];
    __syncthreads();
    int oc = threadIdx.x;
    if (oc < OUTC) {
        float acc = b[oc];
#pragma unroll 8
        for (int k = 0; k < CDIM; k++)
            acc += row[k] * w[k * OUTC + oc];
        g_out[n * OUTC + oc] = acc;
    }
}

// ---------------------------- postprocess ----------------------------------
__global__ void post_kernel(const int* __restrict__ coords,
                            const float* __restrict__ perturb,
                            float* __restrict__ out)
{
    int idx = blockIdx.x * 256 + threadIdx.x;
    if (idx >= NTOK * NGAUSS) return;
    int n = idx >> 2, g = idx & 3;
    const float* r = g_out + n * OUTC;
#pragma unroll
    for (int j = 0; j < 3; j++) {
        float off = tanhf(r[g * 3 + j] + perturb[g * 3 + j]) * 4.8828125e-4f;
        float xb  = ((float)coords[n * 4 + 1 + j] + 0.5f) * 0.0625f;
        out[idx * 3 + j]          = xb + off;
        out[49152 + idx * 3 + j]  = r[12 + g * 3 + j];
        out[98304 + idx * 3 + j]  = r[24 + g * 3 + j];
    }
#pragma unroll
    for (int j = 0; j < 4; j++)
        out[147456 + idx * 4 + j] = r[36 + g * 4 + j];
    out[212992 + idx] = r[52 + g];
}

// ------------------------------- launch ------------------------------------
extern "C" void kernel_launch(void* const* d_in, const int* in_sizes, int n_in,
                              void* d_out, int out_size)
{
    const float* feats   = (const float*)d_in[0];
    const int*   coords  = (const int*)  d_in[1];
    const float* emb_x   = (const float*)d_in[2];
    const float* emb_y   = (const float*)d_in[3];
    const float* emb_z   = (const float*)d_in[4];
    const float* w_in    = (const float*)d_in[5];
    const float* b_in    = (const float*)d_in[6];
    const float* ln1_g   = (const float*)d_in[7];
    const float* ln1_b   = (const float*)d_in[8];
    const float* w_qkv   = (const float*)d_in[9];
    const float* b_qkv   = (const float*)d_in[10];
    const float* w_o     = (const float*)d_in[11];
    const float* b_o     = (const float*)d_in[12];
    const float* ln2_g   = (const float*)d_in[13];
    const float* ln2_b   = (const float*)d_in[14];
    const float* w_m1    = (const float*)d_in[15];
    const float* b_m1    = (const float*)d_in[16];
    const float* w_m2    = (const float*)d_in[17];
    const float* b_m2    = (const float*)d_in[18];
    const float* w_out   = (const float*)d_in[19];
    const float* b_out   = (const float*)d_in[20];
    const float* perturb = (const float*)d_in[21];
    float* out = (float*)d_out;

    float *ph, *pa;
    __half *pah, *pqh, *pql, *poh, *pmh;
    __half *pwqh, *pwoh, *pw1h, *pw2h;
    cudaGetSymbolAddress((void**)&ph,   g_h);
    cudaGetSymbolAddress((void**)&pa,   g_a);
    cudaGetSymbolAddress((void**)&pah,  g_ah);
    cudaGetSymbolAddress((void**)&pqh,  g_qh);
    cudaGetSymbolAddress((void**)&pql,  g_ql);
    cudaGetSymbolAddress((void**)&poh,  g_oh);
    cudaGetSymbolAddress((void**)&pmh,  g_mh);
    cudaGetSymbolAddress((void**)&pwqh, g_wqkv_h);
    cudaGetSymbolAddress((void**)&pwoh, g_wo_h);
    cudaGetSymbolAddress((void**)&pw1h, g_wm1_h);
    cudaGetSymbolAddress((void**)&pw2h, g_wm2_h);

    cudaFuncSetAttribute(attn_mma_kernel,
                         cudaFuncAttributeMaxDynamicSharedMemorySize, ATT_SMEM);
    cudaFuncSetAttribute(gemm_f16_kernel,
                         cudaFuncAttributeMaxDynamicSharedMemorySize, GSMEM_BYTES);

    {
        int n4q = LAYERS * CDIM * 3 * CDIM / 4;
        int n4o = LAYERS * CDIM * CDIM / 4;
        int n4m = LAYERS * CDIM * MLPDIM / 4;
        wcast_kernel<<<(n4q + 255) / 256, 256>>>(w_qkv, pwqh, n4q);
        wcast_kernel<<<(n4o + 255) / 256, 256>>>(w_o,   pwoh, n4o);
        wcast_kernel<<<(n4m + 255) / 256, 256>>>(w_m1,  pw1h, n4m);
        wcast_kernel<<<(n4m + 255) / 256, 256>>>(w_m2,  pw2h, n4m);
    }

    embed_kernel<<<NTOK, CDIM>>>(feats, coords, emb_x, emb_y, emb_z, w_in, b_in);

    for (int l = 0; l < LAYERS; l++) {
        ln_kernel<<<NTOK, 256>>>(ph, ln1_g + l * CDIM, ln1_b + l * CDIM,
                                 nullptr, pah, 1e-6f, 1);
        gemm_f16_kernel<<<dim3(3 * CDIM / BN, NTOK / BM), 256, GSMEM_BYTES>>>(
            pah, pwqh + (size_t)l * CDIM * 3 * CDIM,
            b_qkv + l * 3 * CDIM, nullptr, pqh, pql,
            NTOK, 3 * CDIM, CDIM, 3);
        attn_mma_kernel<<<dim3(8, HEADS, 8), 128, ATT_SMEM>>>(pqh, pql, poh);
        gemm_f16_kernel<<<dim3(CDIM / BN, NTOK / BM), 256, GSMEM_BYTES>>>(
            poh, pwoh + (size_t)l * CDIM * CDIM,
            b_o + l * CDIM, ph, nullptr, nullptr,
            NTOK, CDIM, CDIM, 1);
        ln_kernel<<<NTOK, 256>>>(ph, ln2_g + l * CDIM, ln2_b + l * CDIM,
                                 nullptr, pah, 1e-6f, 1);
        gemm_f16_kernel<<<dim3(MLPDIM / BN, NTOK / BM), 256, GSMEM_BYTES>>>(
            pah, pw1h + (size_t)l * CDIM * MLPDIM,
            b_m1 + l * MLPDIM, nullptr, pmh, nullptr,
            NTOK, MLPDIM, CDIM, 2);
        gemm_f16_kernel<<<dim3(CDIM / BN, NTOK / BM), 256, GSMEM_BYTES>>>(
            pmh, pw2h + (size_t)l * MLPDIM * CDIM,
            b_m2 + l * CDIM, ph, nullptr, nullptr,
            NTOK, CDIM, MLPDIM, 1);
    }

    ln_kernel<<<NTOK, 256>>>(ph, nullptr, nullptr, pa, nullptr, 1e-5f, 0);
    outhead_kernel<<<NTOK, 64>>>(pa, w_out, b_out);
    post_kernel<<<(NTOK * NGAUSS + 255) / 256, 256>>>(coords, perturb, out);
}

// round 11
// speedup vs baseline: 2.1597x; 1.1395x over previous
#include <cuda_runtime.h>
#include <cuda_fp16.h>
#include <math.h>
#include <stdint.h>

// ---------------------------------------------------------------------------
// GSDecoder round 11: single-pass fp16 everywhere (GEMMs and attention both
// 1 MMA pass; P/Q lo-corrections dropped per measured ~1e-6 sensitivity).
// Warp-per-row LN (no barriers). HMMA pipe is the ceiling.
// ---------------------------------------------------------------------------

#define NTOK   4096
#define CDIM   512
#define HEADS  8
#define DHEAD  64
#define LAYERS 8
#define MLPDIM 2048
#define OUTC   56
#define NGAUSS 4

#define ASCALE     256.0f
#define INV_ASCALE 0.00390625f
#define QK_SCALE   1.9073486328125e-6f   // 1/(256*256) / 8

// ------------------------- scratch (device globals) ------------------------
__device__ float g_h  [NTOK * CDIM];
__device__ float g_a  [NTOK * CDIM];
__device__ float g_out[NTOK * OUTC];

__device__ __half g_ah[NTOK * CDIM];          // LN out (x256)
__device__ __half g_qh[NTOK * 3 * CDIM];      // qkv (x256)
__device__ __half g_oh[NTOK * CDIM];          // attn out (x256)
__device__ __half g_mh[NTOK * MLPDIM];        // gelu out (x256)

__device__ __half g_wqkv_h[LAYERS * CDIM * 3 * CDIM];
__device__ __half g_wo_h  [LAYERS * CDIM * CDIM];
__device__ __half g_wm1_h [LAYERS * CDIM * MLPDIM];
__device__ __half g_wm2_h [LAYERS * MLPDIM * CDIM];

// ------------------------------ helpers ------------------------------------
__device__ __forceinline__ float gelu_f(float x) {
    float x3 = x * x * x;
    return 0.5f * x * (1.0f + tanhf(0.7978845608028654f * (x + 0.044715f * x3)));
}

__device__ __forceinline__ void ldsm_x4(unsigned* r, unsigned addr) {
    asm volatile("ldmatrix.sync.aligned.m8n8.x4.shared.b16 {%0,%1,%2,%3}, [%4];"
                 : "=r"(r[0]), "=r"(r[1]), "=r"(r[2]), "=r"(r[3]) : "r"(addr));
}
__device__ __forceinline__ void ldsm_x4t(unsigned* r, unsigned addr) {
    asm volatile("ldmatrix.sync.aligned.m8n8.x4.trans.shared.b16 {%0,%1,%2,%3}, [%4];"
                 : "=r"(r[0]), "=r"(r[1]), "=r"(r[2]), "=r"(r[3]) : "r"(addr));
}
__device__ __forceinline__ void ldsm_x2t(unsigned* r, unsigned addr) {
    asm volatile("ldmatrix.sync.aligned.m8n8.x2.trans.shared.b16 {%0,%1}, [%2];"
                 : "=r"(r[0]), "=r"(r[1]) : "r"(addr));
}
__device__ __forceinline__ void mma16816h(float* c, const unsigned* a, const unsigned* b) {
    asm volatile("mma.sync.aligned.m16n8k16.row.col.f32.f16.f16.f32 "
                 "{%0,%1,%2,%3}, {%4,%5,%6,%7}, {%8,%9}, {%0,%1,%2,%3};"
                 : "+f"(c[0]), "+f"(c[1]), "+f"(c[2]), "+f"(c[3])
                 : "r"(a[0]), "r"(a[1]), "r"(a[2]), "r"(a[3]),
                   "r"(b[0]), "r"(b[1]));
}
__device__ __forceinline__ void cpa16(unsigned dst, const void* src) {
    asm volatile("cp.async.cg.shared.global [%0], [%1], 16;" :: "r"(dst), "l"(src));
}
__device__ __forceinline__ void cpa_commit() { asm volatile("cp.async.commit_group;"); }
template <int NWAIT>
__device__ __forceinline__ void cpa_wait() {
    asm volatile("cp.async.wait_group %0;" :: "n"(NWAIT));
}

// scaled fp16 of (256x, 256y)
__device__ __forceinline__ unsigned pack_h2(float x, float y) {
    __half2 H = __halves2half2(__float2half_rn(x * ASCALE), __float2half_rn(y * ASCALE));
    return *(unsigned*)&H;
}

// --------------------------- weight fp16 cast ------------------------------
__global__ void wcast_kernel(const float* __restrict__ src,
                             __half* __restrict__ h, int n4)
{
    int i = blockIdx.x * 256 + threadIdx.x;
    if (i < n4) {
        float4 v = ((const float4*)src)[i];
        __half2 a = __halves2half2(__float2half_rn(v.x), __float2half_rn(v.y));
        __half2 b = __halves2half2(__float2half_rn(v.z), __float2half_rn(v.w));
        ((__half2*)h)[i * 2]     = a;
        ((__half2*)h)[i * 2 + 1] = b;
    }
}

// ------------------------------ embed + PE ---------------------------------
__global__ void embed_kernel(const float* __restrict__ feats,
                             const int*   __restrict__ coords,
                             const float* __restrict__ ex,
                             const float* __restrict__ ey,
                             const float* __restrict__ ez,
                             const float* __restrict__ w_in,
                             const float* __restrict__ b_in)
{
    int n = blockIdx.x;
    int c = threadIdx.x;
    const float* f = feats + (size_t)n * 8;
    float acc = b_in[c];
#pragma unroll
    for (int l = 0; l < 8; l++) acc += f[l] * w_in[l * CDIM + c];

    int cx = coords[n * 4 + 1];
    int cy = coords[n * 4 + 2];
    int cz = coords[n * 4 + 3];
    float pe;
    if (c < 170)      pe = ex[cx * 170 + c];
    else if (c < 340) pe = ey[cy * 170 + (c - 170)];
    else              pe = ez[cz * 172 + (c - 340)];
    g_h[(size_t)n * CDIM + c] = acc + pe;
}

// ----------------------- warp-per-row layernorm ----------------------------
// 256 threads = 8 warps = 8 rows per block; pure shfl reduction.
__global__ void __launch_bounds__(256)
ln_kernel(const float* __restrict__ x,
          const float* __restrict__ g,
          const float* __restrict__ b,
          float* __restrict__ of,
          __half* __restrict__ oh,
          float eps, int has_gb)
{
    int warp = threadIdx.x >> 5;
    int lane = threadIdx.x & 31;
    int n = blockIdx.x * 8 + warp;
    const float4* xr = (const float4*)(x + (size_t)n * CDIM);

    float4 v[4];
    float s = 0.f, s2 = 0.f;
#pragma unroll
    for (int k = 0; k < 4; k++) {
        v[k] = xr[lane + k * 32];
        s  += v[k].x + v[k].y + v[k].z + v[k].w;
        s2 += v[k].x * v[k].x + v[k].y * v[k].y
            + v[k].z * v[k].z + v[k].w * v[k].w;
    }
#pragma unroll
    for (int off = 16; off; off >>= 1) {
        s  += __shfl_xor_sync(0xffffffffu, s,  off);
        s2 += __shfl_xor_sync(0xffffffffu, s2, off);
    }
    float mean = s * (1.0f / 512.0f);
    float var  = s2 * (1.0f / 512.0f) - mean * mean;
    if (var < 0.f) var = 0.f;
    float r = rsqrtf(var + eps);

#pragma unroll
    for (int k = 0; k < 4; k++) {
        int c = (lane + k * 32) * 4;
        float o0 = (v[k].x - mean) * r;
        float o1 = (v[k].y - mean) * r;
        float o2 = (v[k].z - mean) * r;
        float o3 = (v[k].w - mean) * r;
        if (has_gb) {
            float4 gv = *(const float4*)(g + c);
            float4 bv = *(const float4*)(b + c);
            o0 = o0 * gv.x + bv.x; o1 = o1 * gv.y + bv.y;
            o2 = o2 * gv.z + bv.z; o3 = o3 * gv.w + bv.w;
        }
        if (of)
            *(float4*)(of + (size_t)n * CDIM + c) = make_float4(o0, o1, o2, o3);
        if (oh) {
            uint2 pk;
            pk.x = pack_h2(o0, o1);
            pk.y = pack_h2(o2, o3);
            *(uint2*)(oh + (size_t)n * CDIM + c) = pk;
        }
    }
}

// ----------------- single-pass fp16 tensor-core GEMM -----------------------
// D = A256h@Bh ;  C = epi( D/256 + bias )
// epi 0: fp32 Cf; 1: Cf += residual; 2: gelu -> fp16 Ch; 3: fp16 Ch
#define BM 128
#define BN 128
#define BK2 32
#define ASTR2 40
#define BSTR2 136
#define A_PL (128 * ASTR2)
#define B_PL (32 * BSTR2)
#define STG  (A_PL + B_PL)
#define GSMEM_BYTES (2 * STG * 2)

__global__ void __launch_bounds__(256, 2)
gemm_f16_kernel(const __half* __restrict__ Ah,
                const __half* __restrict__ Bh,
                const float* __restrict__ bias, float* __restrict__ Cf,
                __half* __restrict__ Ch,
                int M, int N, int K, int epi)
{
    extern __shared__ __align__(16) __half smemh[];

    const int tid  = threadIdx.x;
    const int wid  = tid >> 5;
    const int lane = tid & 31;
    const int n0 = blockIdx.x * BN;
    const int m0 = blockIdx.y * BM;
    const int wm = (wid >> 2) * 64;
    const int wn = (wid & 3) * 32;

    float acc[4][4][4];
#pragma unroll
    for (int i = 0; i < 4; i++)
#pragma unroll
        for (int j = 0; j < 4; j++)
#pragma unroll
            for (int k = 0; k < 4; k++) acc[i][j][k] = 0.f;

    const int a_row = tid >> 2,  a_off = (tid & 3) << 3;
    const int b_row = tid >> 3,  b_c = (tid & 7) << 4;

    auto stage = [&](int s, int k0) {
        __half* base = smemh + s * STG;
        cpa16((unsigned)__cvta_generic_to_shared(base + a_row * ASTR2 + a_off),
              Ah + (size_t)(m0 + a_row) * K + k0 + a_off);
        cpa16((unsigned)__cvta_generic_to_shared(base + (a_row + 64) * ASTR2 + a_off),
              Ah + (size_t)(m0 + a_row + 64) * K + k0 + a_off);
        __half* d = base + A_PL;
        cpa16((unsigned)__cvta_generic_to_shared(d + b_row * BSTR2 + b_c),
              Bh + (size_t)(k0 + b_row) * N + n0 + b_c);
        cpa16((unsigned)__cvta_generic_to_shared(d + b_row * BSTR2 + b_c + 8),
              Bh + (size_t)(k0 + b_row) * N + n0 + b_c + 8);
        cpa_commit();
    };

    stage(0, 0);
    const int KT = K / BK2;
    for (int kt = 0; kt < KT; kt++) {
        int buf = kt & 1;
        if (kt + 1 < KT) { stage(buf ^ 1, (kt + 1) * BK2); cpa_wait<1>(); }
        else             { cpa_wait<0>(); }
        __syncthreads();

        __half* base = smemh + buf * STG;
        unsigned aH = (unsigned)__cvta_generic_to_shared(
            base + (wm + (lane & 15)) * ASTR2 + ((lane >> 4) << 3));
        unsigned bH = (unsigned)__cvta_generic_to_shared(
            base + A_PL + (lane & 15) * BSTR2 + wn);

#pragma unroll
        for (int ks = 0; ks < 2; ks++) {
            unsigned bh[4][2];
#pragma unroll
            for (int nb = 0; nb < 4; nb++) {
                unsigned off = (unsigned)(ks * 16 * BSTR2) * 2 + nb * 16;
                ldsm_x2t(bh[nb], bH + off);
            }
#pragma unroll
            for (int mb = 0; mb < 4; mb++) {
                unsigned ah[4];
                unsigned off = (unsigned)(mb * 16 * ASTR2 + ks * 16) * 2;
                ldsm_x4(ah, aH + off);
#pragma unroll
                for (int nb = 0; nb < 4; nb++)
                    mma16816h(acc[mb][nb], ah, bh[nb]);
            }
        }
        __syncthreads();
    }

    // ---- epilogue ----
#pragma unroll
    for (int mb = 0; mb < 4; mb++) {
        int m = m0 + wm + mb * 16 + (lane >> 2);
#pragma unroll
        for (int nb = 0; nb < 4; nb++) {
            int n = n0 + wn + nb * 8 + ((lane & 3) << 1);
            float2 bv = *(const float2*)(bias + n);
            float c0 = acc[mb][nb][0] * INV_ASCALE + bv.x;
            float c1 = acc[mb][nb][1] * INV_ASCALE + bv.y;
            float c2 = acc[mb][nb][2] * INV_ASCALE + bv.x;
            float c3 = acc[mb][nb][3] * INV_ASCALE + bv.y;
            if (epi >= 2) {
                if (epi == 2) {
                    c0 = gelu_f(c0); c1 = gelu_f(c1);
                    c2 = gelu_f(c2); c3 = gelu_f(c3);
                }
                *(unsigned*)(Ch + (size_t)m * N + n)       = pack_h2(c0, c1);
                *(unsigned*)(Ch + (size_t)(m + 8) * N + n) = pack_h2(c2, c3);
            } else {
                float* p0 = Cf + (size_t)m * N + n;
                float* p1 = Cf + (size_t)(m + 8) * N + n;
                if (epi == 1) {
                    float2 r0 = *(float2*)p0;
                    float2 r1 = *(float2*)p1;
                    c0 += r0.x; c1 += r0.y; c2 += r1.x; c3 += r1.y;
                }
                *(float2*)p0 = make_float2(c0, c1);
                *(float2*)p1 = make_float2(c2, c3);
            }
        }
    }
}

// --------------- flash attention (single-pass fp16, cp.async) --------------
// smem: Qh, Kh, Vh (3 tiles, 33KB)
#define ASTR 88
#define AQH  0
#define AKH  (64 * ASTR)
#define AVH  (2 * 64 * ASTR)
#define ATT_SMEM (3 * 64 * ASTR * 2)

__global__ void __launch_bounds__(128)
attn_mma_kernel(const __half* __restrict__ qkvh,
                __half* __restrict__ oh)
{
    extern __shared__ __align__(16) __half sm[];
    const int tid  = threadIdx.x;
    const int wid  = tid >> 5;
    const int lane = tid & 31;
    const int qt = blockIdx.x, h = blockIdx.y, w = blockIdx.z;
    const int tok0 = w * 512;
    const int q0   = qt * 64;
    const int qoff = h * DHEAD;
    const int koff = CDIM + h * DHEAD;
    const int voff = 2 * CDIM + h * DHEAD;
    const int wm   = wid * 16;

    const unsigned sQH = (unsigned)__cvta_generic_to_shared(&sm[AQH]);
    const unsigned sKH = (unsigned)__cvta_generic_to_shared(&sm[AKH]);
    const unsigned sVH = (unsigned)__cvta_generic_to_shared(&sm[AVH]);

#pragma unroll
    for (int i = 0; i < 4; i++) {
        int id = tid + i * 128;
        int r = id >> 3, c = (id & 7) << 3;
        cpa16(sQH + (unsigned)(r * ASTR + c) * 2,
              qkvh + (size_t)(tok0 + q0 + r) * (3 * CDIM) + qoff + c);
    }
    cpa_commit();
    cpa_wait<0>();
    __syncthreads();

    unsigned qh[4][4];
    {
        int row = wm + (lane & 15);
        int coloff = (lane >> 4) << 3;
#pragma unroll
        for (int ks = 0; ks < 4; ks++)
            ldsm_x4(qh[ks], sQH + (unsigned)(row * ASTR + ks * 16 + coloff) * 2);
    }

    float m0 = -1e30f, m1 = -1e30f, l0 = 0.f, l1 = 0.f;
    float oacc[8][4];
#pragma unroll
    for (int i = 0; i < 8; i++)
#pragma unroll
        for (int j = 0; j < 4; j++) oacc[i][j] = 0.f;

    const int k_key  = ((lane >> 4) << 3) + (lane & 7);
    const int k_kc   = ((lane >> 3) & 1) << 3;
    const int v_kr   = (((lane >> 3) & 1) << 3) + (lane & 7);
    const int v_col  = (lane >> 4) << 3;

    for (int kt = 0; kt < 8; kt++) {
        __syncthreads();
#pragma unroll
        for (int i = 0; i < 4; i++) {
            int id = tid + i * 128;
            int r = id >> 3, c = (id & 7) << 3;
            size_t rowb = (size_t)(tok0 + kt * 64 + r) * (3 * CDIM);
            unsigned doff = (unsigned)(r * ASTR + c) * 2;
            cpa16(sKH + doff, qkvh + rowb + koff + c);
            cpa16(sVH + doff, qkvh + rowb + voff + c);
        }
        cpa_commit();
        cpa_wait<0>();
        __syncthreads();

        // ---- S = Q K^T (1 pass) ----
        float s[8][4];
#pragma unroll
        for (int i = 0; i < 8; i++)
#pragma unroll
            for (int j = 0; j < 4; j++) s[i][j] = 0.f;

#pragma unroll
        for (int p = 0; p < 4; p++) {
#pragma unroll
            for (int ks = 0; ks < 4; ks++) {
                unsigned kb[4];
                unsigned off = (unsigned)((p * 16 + k_key) * ASTR + ks * 16 + k_kc) * 2;
                ldsm_x4(kb, sKH + off);
                mma16816h(s[2 * p],     qh[ks], &kb[0]);
                mma16816h(s[2 * p + 1], qh[ks], &kb[2]);
            }
        }

        // ---- online softmax ----
        float mx0 = -1e30f, mx1 = -1e30f;
#pragma unroll
        for (int nb = 0; nb < 8; nb++) {
            s[nb][0] *= QK_SCALE; s[nb][1] *= QK_SCALE;
            s[nb][2] *= QK_SCALE; s[nb][3] *= QK_SCALE;
            mx0 = fmaxf(mx0, fmaxf(s[nb][0], s[nb][1]));
            mx1 = fmaxf(mx1, fmaxf(s[nb][2], s[nb][3]));
        }
        mx0 = fmaxf(mx0, __shfl_xor_sync(0xffffffffu, mx0, 1));
        mx0 = fmaxf(mx0, __shfl_xor_sync(0xffffffffu, mx0, 2));
        mx1 = fmaxf(mx1, __shfl_xor_sync(0xffffffffu, mx1, 1));
        mx1 = fmaxf(mx1, __shfl_xor_sync(0xffffffffu, mx1, 2));

        float nm0 = fmaxf(m0, mx0);
        float nm1 = fmaxf(m1, mx1);
        float al0 = __expf(m0 - nm0);
        float al1 = __expf(m1 - nm1);
        m0 = nm0; m1 = nm1;

        float sum0 = 0.f, sum1 = 0.f;
#pragma unroll
        for (int nb = 0; nb < 8; nb++) {
            s[nb][0] = __expf(s[nb][0] - nm0);
            s[nb][1] = __expf(s[nb][1] - nm0);
            s[nb][2] = __expf(s[nb][2] - nm1);
            s[nb][3] = __expf(s[nb][3] - nm1);
            sum0 += s[nb][0] + s[nb][1];
            sum1 += s[nb][2] + s[nb][3];
        }
        sum0 += __shfl_xor_sync(0xffffffffu, sum0, 1);
        sum0 += __shfl_xor_sync(0xffffffffu, sum0, 2);
        sum1 += __shfl_xor_sync(0xffffffffu, sum1, 1);
        sum1 += __shfl_xor_sync(0xffffffffu, sum1, 2);
        l0 = l0 * al0 + sum0;
        l1 = l1 * al1 + sum1;

#pragma unroll
        for (int nb = 0; nb < 8; nb++) {
            oacc[nb][0] *= al0; oacc[nb][1] *= al0;
            oacc[nb][2] *= al1; oacc[nb][3] *= al1;
        }

        // ---- O += P V (1 pass; P as 256p fp16) ----
#pragma unroll
        for (int kk = 0; kk < 4; kk++) {
            unsigned pa[4];
            pa[0] = pack_h2(s[2 * kk][0],     s[2 * kk][1]);
            pa[1] = pack_h2(s[2 * kk][2],     s[2 * kk][3]);
            pa[2] = pack_h2(s[2 * kk + 1][0], s[2 * kk + 1][1]);
            pa[3] = pack_h2(s[2 * kk + 1][2], s[2 * kk + 1][3]);
#pragma unroll
            for (int p = 0; p < 4; p++) {
                unsigned vb[4];
                unsigned off = (unsigned)((kk * 16 + v_kr) * ASTR + p * 16 + v_col) * 2;
                ldsm_x4t(vb, sVH + off);
                mma16816h(oacc[2 * p],     pa, &vb[0]);
                mma16816h(oacc[2 * p + 1], pa, &vb[2]);
            }
        }
    }

    // ---- epilogue: o = oacc/(65536*l) ; store 256*o fp16 ----
    float i0 = 1.0f / (65536.0f * l0);
    float i1 = 1.0f / (65536.0f * l1);
    int r0  = tok0 + q0 + wm + (lane >> 2);
    int col = h * DHEAD + ((lane & 3) << 1);
#pragma unroll
    for (int nb = 0; nb < 8; nb++) {
        size_t p0 = (size_t)r0 * CDIM + col + nb * 8;
        size_t p1 = (size_t)(r0 + 8) * CDIM + col + nb * 8;
        *(unsigned*)(oh + p0) = pack_h2(oacc[nb][0] * i0, oacc[nb][1] * i0);
        *(unsigned*)(oh + p1) = pack_h2(oacc[nb][2] * i1, oacc[nb][3] * i1);
    }
}

// ----------------------------- out head ------------------------------------
__global__ void outhead_kernel(const float* __restrict__ a,
                               const float* __restrict__ w,
                               const float* __restrict__ b)
{
    __shared__ float row[CDIM];
    int n = blockIdx.x;
    for (int i = threadIdx.x; i < CDIM; i += 64)
        row[i] = a[(size_t)n * CDIM + i];
    __syncthreads();
    int oc = threadIdx.x;
    if (oc < OUTC) {
        float acc = b[oc];
#pragma unroll 8
        for (int k = 0; k < CDIM; k++)
            acc += row[k] * w[k * OUTC + oc];
        g_out[n * OUTC + oc] = acc;
    }
}

// ---------------------------- postprocess ----------------------------------
__global__ void post_kernel(const int* __restrict__ coords,
                            const float* __restrict__ perturb,
                            float* __restrict__ out)
{
    int idx = blockIdx.x * 256 + threadIdx.x;
    if (idx >= NTOK * NGAUSS) return;
    int n = idx >> 2, g = idx & 3;
    const float* r = g_out + n * OUTC;
#pragma unroll
    for (int j = 0; j < 3; j++) {
        float off = tanhf(r[g * 3 + j] + perturb[g * 3 + j]) * 4.8828125e-4f;
        float xb  = ((float)coords[n * 4 + 1 + j] + 0.5f) * 0.0625f;
        out[idx * 3 + j]          = xb + off;
        out[49152 + idx * 3 + j]  = r[12 + g * 3 + j];
        out[98304 + idx * 3 + j]  = r[24 + g * 3 + j];
    }
#pragma unroll
    for (int j = 0; j < 4; j++)
        out[147456 + idx * 4 + j] = r[36 + g * 4 + j];
    out[212992 + idx] = r[52 + g];
}

// ------------------------------- launch ------------------------------------
extern "C" void kernel_launch(void* const* d_in, const int* in_sizes, int n_in,
                              void* d_out, int out_size)
{
    const float* feats   = (const float*)d_in[0];
    const int*   coords  = (const int*)  d_in[1];
    const float* emb_x   = (const float*)d_in[2];
    const float* emb_y   = (const float*)d_in[3];
    const float* emb_z   = (const float*)d_in[4];
    const float* w_in    = (const float*)d_in[5];
    const float* b_in    = (const float*)d_in[6];
    const float* ln1_g   = (const float*)d_in[7];
    const float* ln1_b   = (const float*)d_in[8];
    const float* w_qkv   = (const float*)d_in[9];
    const float* b_qkv   = (const float*)d_in[10];
    const float* w_o     = (const float*)d_in[11];
    const float* b_o     = (const float*)d_in[12];
    const float* ln2_g   = (const float*)d_in[13];
    const float* ln2_b   = (const float*)d_in[14];
    const float* w_m1    = (const float*)d_in[15];
    const float* b_m1    = (const float*)d_in[16];
    const float* w_m2    = (const float*)d_in[17];
    const float* b_m2    = (const float*)d_in[18];
    const float* w_out   = (const float*)d_in[19];
    const float* b_out   = (const float*)d_in[20];
    const float* perturb = (const float*)d_in[21];
    float* out = (float*)d_out;

    float *ph, *pa;
    __half *pah, *pqh, *poh, *pmh;
    __half *pwqh, *pwoh, *pw1h, *pw2h;
    cudaGetSymbolAddress((void**)&ph,   g_h);
    cudaGetSymbolAddress((void**)&pa,   g_a);
    cudaGetSymbolAddress((void**)&pah,  g_ah);
    cudaGetSymbolAddress((void**)&pqh,  g_qh);
    cudaGetSymbolAddress((void**)&poh,  g_oh);
    cudaGetSymbolAddress((void**)&pmh,  g_mh);
    cudaGetSymbolAddress((void**)&pwqh, g_wqkv_h);
    cudaGetSymbolAddress((void**)&pwoh, g_wo_h);
    cudaGetSymbolAddress((void**)&pw1h, g_wm1_h);
    cudaGetSymbolAddress((void**)&pw2h, g_wm2_h);

    cudaFuncSetAttribute(attn_mma_kernel,
                         cudaFuncAttributeMaxDynamicSharedMemorySize, ATT_SMEM);
    cudaFuncSetAttribute(gemm_f16_kernel,
                         cudaFuncAttributeMaxDynamicSharedMemorySize, GSMEM_BYTES);

    {
        int n4q = LAYERS * CDIM * 3 * CDIM / 4;
        int n4o = LAYERS * CDIM * CDIM / 4;
        int n4m = LAYERS * CDIM * MLPDIM / 4;
        wcast_kernel<<<(n4q + 255) / 256, 256>>>(w_qkv, pwqh, n4q);
        wcast_kernel<<<(n4o + 255) / 256, 256>>>(w_o,   pwoh, n4o);
        wcast_kernel<<<(n4m + 255) / 256, 256>>>(w_m1,  pw1h, n4m);
        wcast_kernel<<<(n4m + 255) / 256, 256>>>(w_m2,  pw2h, n4m);
    }

    embed_kernel<<<NTOK, CDIM>>>(feats, coords, emb_x, emb_y, emb_z, w_in, b_in);

    for (int l = 0; l < LAYERS; l++) {
        ln_kernel<<<NTOK / 8, 256>>>(ph, ln1_g + l * CDIM, ln1_b + l * CDIM,
                                     nullptr, pah, 1e-6f, 1);
        gemm_f16_kernel<<<dim3(3 * CDIM / BN, NTOK / BM), 256, GSMEM_BYTES>>>(
            pah, pwqh + (size_t)l * CDIM * 3 * CDIM,
            b_qkv + l * 3 * CDIM, nullptr, pqh,
            NTOK, 3 * CDIM, CDIM, 3);
        attn_mma_kernel<<<dim3(8, HEADS, 8), 128, ATT_SMEM>>>(pqh, poh);
        gemm_f16_kernel<<<dim3(CDIM / BN, NTOK / BM), 256, GSMEM_BYTES>>>(
            poh, pwoh + (size_t)l * CDIM * CDIM,
            b_o + l * CDIM, ph, nullptr,
            NTOK, CDIM, CDIM, 1);
        ln_kernel<<<NTOK / 8, 256>>>(ph, ln2_g + l * CDIM, ln2_b + l * CDIM,
                                     nullptr, pah, 1e-6f, 1);
        gemm_f16_kernel<<<dim3(MLPDIM / BN, NTOK / BM), 256, GSMEM_BYTES>>>(
            pah, pw1h + (size_t)l * CDIM * MLPDIM,
            b_m1 + l * MLPDIM, nullptr, pmh,
            NTOK, MLPDIM, CDIM, 2);
        gemm_f16_kernel<<<dim3(CDIM / BN, NTOK / BM), 256, GSMEM_BYTES>>>(
            pmh, pw2h + (size_t)l * MLPDIM * CDIM,
            b_m2 + l * CDIM, ph, nullptr,
            NTOK, CDIM, MLPDIM, 1);
    }

    ln_kernel<<<NTOK / 8, 256>>>(ph, nullptr, nullptr, pa, nullptr, 1e-5f, 0);
    outhead_kernel<<<NTOK, 64>>>(pa, w_out, b_out);
    post_kernel<<<(NTOK * NGAUSS + 255) / 256, 256>>>(coords, perturb, out);
}

// round 12
// speedup vs baseline: 2.1863x; 1.0123x over previous
#include <cuda_runtime.h>
#include <cuda_fp16.h>
#include <math.h>
#include <stdint.h>

// ---------------------------------------------------------------------------
// GSDecoder round 12: round-11 numerics (single-pass fp16) +
//  - double-buffered K/V staging in attention (load/MMA overlap)
//  - fused final LN + out-head + postprocess (one kernel, no g_a/g_out)
//  - single merged weight-cast kernel
// ---------------------------------------------------------------------------

#define NTOK   4096
#define CDIM   512
#define HEADS  8
#define DHEAD  64
#define LAYERS 8
#define MLPDIM 2048
#define OUTC   56
#define NGAUSS 4

#define ASCALE     256.0f
#define INV_ASCALE 0.00390625f
#define QK_SCALE   1.9073486328125e-6f   // 1/(256*256) / 8

// ------------------------- scratch (device globals) ------------------------
__device__ float g_h  [NTOK * CDIM];

__device__ __half g_ah[NTOK * CDIM];          // LN out (x256)
__device__ __half g_qh[NTOK * 3 * CDIM];      // qkv (x256)
__device__ __half g_oh[NTOK * CDIM];          // attn out (x256)
__device__ __half g_mh[NTOK * MLPDIM];        // gelu out (x256)

__device__ __half g_wqkv_h[LAYERS * CDIM * 3 * CDIM];
__device__ __half g_wo_h  [LAYERS * CDIM * CDIM];
__device__ __half g_wm1_h [LAYERS * CDIM * MLPDIM];
__device__ __half g_wm2_h [LAYERS * MLPDIM * CDIM];

// ------------------------------ helpers ------------------------------------
__device__ __forceinline__ float gelu_f(float x) {
    float x3 = x * x * x;
    return 0.5f * x * (1.0f + tanhf(0.7978845608028654f * (x + 0.044715f * x3)));
}

__device__ __forceinline__ void ldsm_x4(unsigned* r, unsigned addr) {
    asm volatile("ldmatrix.sync.aligned.m8n8.x4.shared.b16 {%0,%1,%2,%3}, [%4];"
                 : "=r"(r[0]), "=r"(r[1]), "=r"(r[2]), "=r"(r[3]) : "r"(addr));
}
__device__ __forceinline__ void ldsm_x4t(unsigned* r, unsigned addr) {
    asm volatile("ldmatrix.sync.aligned.m8n8.x4.trans.shared.b16 {%0,%1,%2,%3}, [%4];"
                 : "=r"(r[0]), "=r"(r[1]), "=r"(r[2]), "=r"(r[3]) : "r"(addr));
}
__device__ __forceinline__ void ldsm_x2t(unsigned* r, unsigned addr) {
    asm volatile("ldmatrix.sync.aligned.m8n8.x2.trans.shared.b16 {%0,%1}, [%2];"
                 : "=r"(r[0]), "=r"(r[1]) : "r"(addr));
}
__device__ __forceinline__ void mma16816h(float* c, const unsigned* a, const unsigned* b) {
    asm volatile("mma.sync.aligned.m16n8k16.row.col.f32.f16.f16.f32 "
                 "{%0,%1,%2,%3}, {%4,%5,%6,%7}, {%8,%9}, {%0,%1,%2,%3};"
                 : "+f"(c[0]), "+f"(c[1]), "+f"(c[2]), "+f"(c[3])
                 : "r"(a[0]), "r"(a[1]), "r"(a[2]), "r"(a[3]),
                   "r"(b[0]), "r"(b[1]));
}
__device__ __forceinline__ void cpa16(unsigned dst, const void* src) {
    asm volatile("cp.async.cg.shared.global [%0], [%1], 16;" :: "r"(dst), "l"(src));
}
__device__ __forceinline__ void cpa_commit() { asm volatile("cp.async.commit_group;"); }
template <int NWAIT>
__device__ __forceinline__ void cpa_wait() {
    asm volatile("cp.async.wait_group %0;" :: "n"(NWAIT));
}

__device__ __forceinline__ unsigned pack_h2(float x, float y) {
    __half2 H = __halves2half2(__float2half_rn(x * ASCALE), __float2half_rn(y * ASCALE));
    return *(unsigned*)&H;
}

// ----------------------- merged weight fp16 cast ---------------------------
__global__ void wcast_all_kernel(const float* __restrict__ s0, __half* __restrict__ d0, int n0,
                                 const float* __restrict__ s1, __half* __restrict__ d1, int n1,
                                 const float* __restrict__ s2, __half* __restrict__ d2, int n2,
                                 const float* __restrict__ s3, __half* __restrict__ d3, int n3)
{
    int i = blockIdx.x * 256 + threadIdx.x;
    const float* src; __half* dst;
    if (i < n0)                 { src = s0; dst = d0; }
    else if ((i -= n0) < n1)    { src = s1; dst = d1; }
    else if ((i -= n1) < n2)    { src = s2; dst = d2; }
    else if ((i -= n2) < n3)    { src = s3; dst = d3; }
    else return;
    float4 v = ((const float4*)src)[i];
    __half2 a = __halves2half2(__float2half_rn(v.x), __float2half_rn(v.y));
    __half2 b = __halves2half2(__float2half_rn(v.z), __float2half_rn(v.w));
    ((__half2*)dst)[i * 2]     = a;
    ((__half2*)dst)[i * 2 + 1] = b;
}

// ------------------------------ embed + PE ---------------------------------
__global__ void embed_kernel(const float* __restrict__ feats,
                             const int*   __restrict__ coords,
                             const float* __restrict__ ex,
                             const float* __restrict__ ey,
                             const float* __restrict__ ez,
                             const float* __restrict__ w_in,
                             const float* __restrict__ b_in)
{
    int n = blockIdx.x;
    int c = threadIdx.x;
    const float* f = feats + (size_t)n * 8;
    float acc = b_in[c];
#pragma unroll
    for (int l = 0; l < 8; l++) acc += f[l] * w_in[l * CDIM + c];

    int cx = coords[n * 4 + 1];
    int cy = coords[n * 4 + 2];
    int cz = coords[n * 4 + 3];
    float pe;
    if (c < 170)      pe = ex[cx * 170 + c];
    else if (c < 340) pe = ey[cy * 170 + (c - 170)];
    else              pe = ez[cz * 172 + (c - 340)];
    g_h[(size_t)n * CDIM + c] = acc + pe;
}

// ----------------------- warp-per-row layernorm ----------------------------
__global__ void __launch_bounds__(256)
ln_kernel(const float* __restrict__ x,
          const float* __restrict__ g,
          const float* __restrict__ b,
          __half* __restrict__ oh,
          float eps)
{
    int warp = threadIdx.x >> 5;
    int lane = threadIdx.x & 31;
    int n = blockIdx.x * 8 + warp;
    const float4* xr = (const float4*)(x + (size_t)n * CDIM);

    float4 v[4];
    float s = 0.f, s2 = 0.f;
#pragma unroll
    for (int k = 0; k < 4; k++) {
        v[k] = xr[lane + k * 32];
        s  += v[k].x + v[k].y + v[k].z + v[k].w;
        s2 += v[k].x * v[k].x + v[k].y * v[k].y
            + v[k].z * v[k].z + v[k].w * v[k].w;
    }
#pragma unroll
    for (int off = 16; off; off >>= 1) {
        s  += __shfl_xor_sync(0xffffffffu, s,  off);
        s2 += __shfl_xor_sync(0xffffffffu, s2, off);
    }
    float mean = s * (1.0f / 512.0f);
    float var  = s2 * (1.0f / 512.0f) - mean * mean;
    if (var < 0.f) var = 0.f;
    float r = rsqrtf(var + eps);

#pragma unroll
    for (int k = 0; k < 4; k++) {
        int c = (lane + k * 32) * 4;
        float4 gv = *(const float4*)(g + c);
        float4 bv = *(const float4*)(b + c);
        float o0 = (v[k].x - mean) * r * gv.x + bv.x;
        float o1 = (v[k].y - mean) * r * gv.y + bv.y;
        float o2 = (v[k].z - mean) * r * gv.z + bv.z;
        float o3 = (v[k].w - mean) * r * gv.w + bv.w;
        uint2 pk;
        pk.x = pack_h2(o0, o1);
        pk.y = pack_h2(o2, o3);
        *(uint2*)(oh + (size_t)n * CDIM + c) = pk;
    }
}

// ----------------- single-pass fp16 tensor-core GEMM -----------------------
#define BM 128
#define BN 128
#define BK2 32
#define ASTR2 40
#define BSTR2 136
#define A_PL (128 * ASTR2)
#define B_PL (32 * BSTR2)
#define STG  (A_PL + B_PL)
#define GSMEM_BYTES (2 * STG * 2)

__global__ void __launch_bounds__(256, 2)
gemm_f16_kernel(const __half* __restrict__ Ah,
                const __half* __restrict__ Bh,
                const float* __restrict__ bias, float* __restrict__ Cf,
                __half* __restrict__ Ch,
                int M, int N, int K, int epi)
{
    extern __shared__ __align__(16) __half smemh[];

    const int tid  = threadIdx.x;
    const int wid  = tid >> 5;
    const int lane = tid & 31;
    const int n0 = blockIdx.x * BN;
    const int m0 = blockIdx.y * BM;
    const int wm = (wid >> 2) * 64;
    const int wn = (wid & 3) * 32;

    float acc[4][4][4];
#pragma unroll
    for (int i = 0; i < 4; i++)
#pragma unroll
        for (int j = 0; j < 4; j++)
#pragma unroll
            for (int k = 0; k < 4; k++) acc[i][j][k] = 0.f;

    const int a_row = tid >> 2,  a_off = (tid & 3) << 3;
    const int b_row = tid >> 3,  b_c = (tid & 7) << 4;

    auto stage = [&](int s, int k0) {
        __half* base = smemh + s * STG;
        cpa16((unsigned)__cvta_generic_to_shared(base + a_row * ASTR2 + a_off),
              Ah + (size_t)(m0 + a_row) * K + k0 + a_off);
        cpa16((unsigned)__cvta_generic_to_shared(base + (a_row + 64) * ASTR2 + a_off),
              Ah + (size_t)(m0 + a_row + 64) * K + k0 + a_off);
        __half* d = base + A_PL;
        cpa16((unsigned)__cvta_generic_to_shared(d + b_row * BSTR2 + b_c),
              Bh + (size_t)(k0 + b_row) * N + n0 + b_c);
        cpa16((unsigned)__cvta_generic_to_shared(d + b_row * BSTR2 + b_c + 8),
              Bh + (size_t)(k0 + b_row) * N + n0 + b_c + 8);
        cpa_commit();
    };

    stage(0, 0);
    const int KT = K / BK2;
    for (int kt = 0; kt < KT; kt++) {
        int buf = kt & 1;
        if (kt + 1 < KT) { stage(buf ^ 1, (kt + 1) * BK2); cpa_wait<1>(); }
        else             { cpa_wait<0>(); }
        __syncthreads();

        __half* base = smemh + buf * STG;
        unsigned aH = (unsigned)__cvta_generic_to_shared(
            base + (wm + (lane & 15)) * ASTR2 + ((lane >> 4) << 3));
        unsigned bH = (unsigned)__cvta_generic_to_shared(
            base + A_PL + (lane & 15) * BSTR2 + wn);

#pragma unroll
        for (int ks = 0; ks < 2; ks++) {
            unsigned bh[4][2];
#pragma unroll
            for (int nb = 0; nb < 4; nb++) {
                unsigned off = (unsigned)(ks * 16 * BSTR2) * 2 + nb * 16;
                ldsm_x2t(bh[nb], bH + off);
            }
#pragma unroll
            for (int mb = 0; mb < 4; mb++) {
                unsigned ah[4];
                unsigned off = (unsigned)(mb * 16 * ASTR2 + ks * 16) * 2;
                ldsm_x4(ah, aH + off);
#pragma unroll
                for (int nb = 0; nb < 4; nb++)
                    mma16816h(acc[mb][nb], ah, bh[nb]);
            }
        }
        __syncthreads();
    }

#pragma unroll
    for (int mb = 0; mb < 4; mb++) {
        int m = m0 + wm + mb * 16 + (lane >> 2);
#pragma unroll
        for (int nb = 0; nb < 4; nb++) {
            int n = n0 + wn + nb * 8 + ((lane & 3) << 1);
            float2 bv = *(const float2*)(bias + n);
            float c0 = acc[mb][nb][0] * INV_ASCALE + bv.x;
            float c1 = acc[mb][nb][1] * INV_ASCALE + bv.y;
            float c2 = acc[mb][nb][2] * INV_ASCALE + bv.x;
            float c3 = acc[mb][nb][3] * INV_ASCALE + bv.y;
            if (epi >= 2) {
                if (epi == 2) {
                    c0 = gelu_f(c0); c1 = gelu_f(c1);
                    c2 = gelu_f(c2); c3 = gelu_f(c3);
                }
                *(unsigned*)(Ch + (size_t)m * N + n)       = pack_h2(c0, c1);
                *(unsigned*)(Ch + (size_t)(m + 8) * N + n) = pack_h2(c2, c3);
            } else {
                float* p0 = Cf + (size_t)m * N + n;
                float* p1 = Cf + (size_t)(m + 8) * N + n;
                if (epi == 1) {
                    float2 r0 = *(float2*)p0;
                    float2 r1 = *(float2*)p1;
                    c0 += r0.x; c1 += r0.y; c2 += r1.x; c3 += r1.y;
                }
                *(float2*)p0 = make_float2(c0, c1);
                *(float2*)p1 = make_float2(c2, c3);
            }
        }
    }
}

// ---- flash attention: single-pass fp16, double-buffered K/V staging -------
// smem: Qh + 2x(Kh,Vh) = 5 tiles of 64*ASTR halves (55KB)
#define ASTR 88
#define TILE_H (64 * ASTR)
#define AQH  0
#define AKV0 TILE_H
#define ATT_SMEM (5 * TILE_H * 2)

__global__ void __launch_bounds__(128)
attn_mma_kernel(const __half* __restrict__ qkvh,
                __half* __restrict__ oh)
{
    extern __shared__ __align__(16) __half sm[];
    const int tid  = threadIdx.x;
    const int wid  = tid >> 5;
    const int lane = tid & 31;
    const int qt = blockIdx.x, h = blockIdx.y, w = blockIdx.z;
    const int tok0 = w * 512;
    const int q0   = qt * 64;
    const int qoff = h * DHEAD;
    const int koff = CDIM + h * DHEAD;
    const int voff = 2 * CDIM + h * DHEAD;
    const int wm   = wid * 16;

    const unsigned sQH = (unsigned)__cvta_generic_to_shared(&sm[AQH]);
    const unsigned sKV = (unsigned)__cvta_generic_to_shared(&sm[AKV0]);

    // Q stage
#pragma unroll
    for (int i = 0; i < 4; i++) {
        int id = tid + i * 128;
        int r = id >> 3, c = (id & 7) << 3;
        cpa16(sQH + (unsigned)(r * ASTR + c) * 2,
              qkvh + (size_t)(tok0 + q0 + r) * (3 * CDIM) + qoff + c);
    }
    cpa_commit();

    const int st_r = tid >> 3, st_c = (tid & 7) << 3;
    auto stageKV = [&](int buf, int kt) {
        unsigned base = sKV + (unsigned)(buf * 2 * TILE_H) * 2;
#pragma unroll
        for (int i = 0; i < 4; i++) {
            int r = st_r + i * 16;
            size_t rowb = (size_t)(tok0 + kt * 64 + r) * (3 * CDIM);
            unsigned doff = (unsigned)(r * ASTR + st_c) * 2;
            cpa16(base + doff, qkvh + rowb + koff + st_c);
            cpa16(base + (unsigned)TILE_H * 2 + doff, qkvh + rowb + voff + st_c);
        }
        cpa_commit();
    };

    stageKV(0, 0);                 // group: Q, then KV0
    cpa_wait<1>();                 // Q ready
    __syncthreads();

    unsigned qh[4][4];
    {
        int row = wm + (lane & 15);
        int coloff = (lane >> 4) << 3;
#pragma unroll
        for (int ks = 0; ks < 4; ks++)
            ldsm_x4(qh[ks], sQH + (unsigned)(row * ASTR + ks * 16 + coloff) * 2);
    }

    float m0 = -1e30f, m1 = -1e30f, l0 = 0.f, l1 = 0.f;
    float oacc[8][4];
#pragma unroll
    for (int i = 0; i < 8; i++)
#pragma unroll
        for (int j = 0; j < 4; j++) oacc[i][j] = 0.f;

    const int k_key  = ((lane >> 4) << 3) + (lane & 7);
    const int k_kc   = ((lane >> 3) & 1) << 3;
    const int v_kr   = (((lane >> 3) & 1) << 3) + (lane & 7);
    const int v_col  = (lane >> 4) << 3;

    for (int kt = 0; kt < 8; kt++) {
        if (kt + 1 < 8) { stageKV((kt + 1) & 1, kt + 1); cpa_wait<1>(); }
        else            { cpa_wait<0>(); }
        __syncthreads();

        unsigned sKH = sKV + (unsigned)((kt & 1) * 2 * TILE_H) * 2;
        unsigned sVH = sKH + (unsigned)TILE_H * 2;

        // ---- S = Q K^T ----
        float s[8][4];
#pragma unroll
        for (int i = 0; i < 8; i++)
#pragma unroll
            for (int j = 0; j < 4; j++) s[i][j] = 0.f;

#pragma unroll
        for (int p = 0; p < 4; p++) {
#pragma unroll
            for (int ks = 0; ks < 4; ks++) {
                unsigned kb[4];
                unsigned off = (unsigned)((p * 16 + k_key) * ASTR + ks * 16 + k_kc) * 2;
                ldsm_x4(kb, sKH + off);
                mma16816h(s[2 * p],     qh[ks], &kb[0]);
                mma16816h(s[2 * p + 1], qh[ks], &kb[2]);
            }
        }

        // ---- online softmax ----
        float mx0 = -1e30f, mx1 = -1e30f;
#pragma unroll
        for (int nb = 0; nb < 8; nb++) {
            s[nb][0] *= QK_SCALE; s[nb][1] *= QK_SCALE;
            s[nb][2] *= QK_SCALE; s[nb][3] *= QK_SCALE;
            mx0 = fmaxf(mx0, fmaxf(s[nb][0], s[nb][1]));
            mx1 = fmaxf(mx1, fmaxf(s[nb][2], s[nb][3]));
        }
        mx0 = fmaxf(mx0, __shfl_xor_sync(0xffffffffu, mx0, 1));
        mx0 = fmaxf(mx0, __shfl_xor_sync(0xffffffffu, mx0, 2));
        mx1 = fmaxf(mx1, __shfl_xor_sync(0xffffffffu, mx1, 1));
        mx1 = fmaxf(mx1, __shfl_xor_sync(0xffffffffu, mx1, 2));

        float nm0 = fmaxf(m0, mx0);
        float nm1 = fmaxf(m1, mx1);
        float al0 = __expf(m0 - nm0);
        float al1 = __expf(m1 - nm1);
        m0 = nm0; m1 = nm1;

        float sum0 = 0.f, sum1 = 0.f;
#pragma unroll
        for (int nb = 0; nb < 8; nb++) {
            s[nb][0] = __expf(s[nb][0] - nm0);
            s[nb][1] = __expf(s[nb][1] - nm0);
            s[nb][2] = __expf(s[nb][2] - nm1);
            s[nb][3] = __expf(s[nb][3] - nm1);
            sum0 += s[nb][0] + s[nb][1];
            sum1 += s[nb][2] + s[nb][3];
        }
        sum0 += __shfl_xor_sync(0xffffffffu, sum0, 1);
        sum0 += __shfl_xor_sync(0xffffffffu, sum0, 2);
        sum1 += __shfl_xor_sync(0xffffffffu, sum1, 1);
        sum1 += __shfl_xor_sync(0xffffffffu, sum1, 2);
        l0 = l0 * al0 + sum0;
        l1 = l1 * al1 + sum1;

#pragma unroll
        for (int nb = 0; nb < 8; nb++) {
            oacc[nb][0] *= al0; oacc[nb][1] *= al0;
            oacc[nb][2] *= al1; oacc[nb][3] *= al1;
        }

        // ---- O += P V ----
#pragma unroll
        for (int kk = 0; kk < 4; kk++) {
            unsigned pa[4];
            pa[0] = pack_h2(s[2 * kk][0],     s[2 * kk][1]);
            pa[1] = pack_h2(s[2 * kk][2],     s[2 * kk][3]);
            pa[2] = pack_h2(s[2 * kk + 1][0], s[2 * kk + 1][1]);
            pa[3] = pack_h2(s[2 * kk + 1][2], s[2 * kk + 1][3]);
#pragma unroll
            for (int p = 0; p < 4; p++) {
                unsigned vb[4];
                unsigned off = (unsigned)((kk * 16 + v_kr) * ASTR + p * 16 + v_col) * 2;
                ldsm_x4t(vb, sVH + off);
                mma16816h(oacc[2 * p],     pa, &vb[0]);
                mma16816h(oacc[2 * p + 1], pa, &vb[2]);
            }
        }
        __syncthreads();
    }

    float i0 = 1.0f / (65536.0f * l0);
    float i1 = 1.0f / (65536.0f * l1);
    int r0  = tok0 + q0 + wm + (lane >> 2);
    int col = h * DHEAD + ((lane & 3) << 1);
#pragma unroll
    for (int nb = 0; nb < 8; nb++) {
        size_t p0 = (size_t)r0 * CDIM + col + nb * 8;
        size_t p1 = (size_t)(r0 + 8) * CDIM + col + nb * 8;
        *(unsigned*)(oh + p0) = pack_h2(oacc[nb][0] * i0, oacc[nb][1] * i0);
        *(unsigned*)(oh + p1) = pack_h2(oacc[nb][2] * i1, oacc[nb][3] * i1);
    }
}

// ------------- fused tail: final LN + out-head GEMV + postprocess ----------
// grid NTOK, 64 threads (2 warps)
__global__ void __launch_bounds__(64)
tail_kernel(const float* __restrict__ hbuf,
            const float* __restrict__ w,
            const float* __restrict__ bo,
            const int*   __restrict__ coords,
            const float* __restrict__ perturb,
            float* __restrict__ out)
{
    __shared__ float row[CDIM];
    __shared__ float ws[4];
    __shared__ float res[OUTC];

    int n = blockIdx.x;
    int tid = threadIdx.x;
    int warp = tid >> 5, lane = tid & 31;

    const float4* xr = (const float4*)(hbuf + (size_t)n * CDIM);
    float4 v0 = xr[tid];
    float4 v1 = xr[tid + 64];
    float s  = v0.x + v0.y + v0.z + v0.w + v1.x + v1.y + v1.z + v1.w;
    float s2 = v0.x * v0.x + v0.y * v0.y + v0.z * v0.z + v0.w * v0.w
             + v1.x * v1.x + v1.y * v1.y + v1.z * v1.z + v1.w * v1.w;
#pragma unroll
    for (int off = 16; off; off >>= 1) {
        s  += __shfl_xor_sync(0xffffffffu, s,  off);
        s2 += __shfl_xor_sync(0xffffffffu, s2, off);
    }
    if (lane == 0) { ws[warp] = s; ws[warp + 2] = s2; }
    __syncthreads();
    float ts  = ws[0] + ws[1];
    float ts2 = ws[2] + ws[3];
    float mean = ts * (1.0f / 512.0f);
    float var  = ts2 * (1.0f / 512.0f) - mean * mean;
    if (var < 0.f) var = 0.f;
    float r = rsqrtf(var + 1e-5f);

    *(float4*)(row + tid * 4) =
        make_float4((v0.x - mean) * r, (v0.y - mean) * r,
                    (v0.z - mean) * r, (v0.w - mean) * r);
    *(float4*)(row + 256 + tid * 4) =
        make_float4((v1.x - mean) * r, (v1.y - mean) * r,
                    (v1.z - mean) * r, (v1.w - mean) * r);
    __syncthreads();

    if (tid < OUTC) {
        float acc = bo[tid];
#pragma unroll 8
        for (int k = 0; k < CDIM; k++)
            acc += row[k] * w[k * OUTC + tid];
        res[tid] = acc;
    }
    __syncthreads();

    if (tid < NGAUSS) {
        int g = tid;
        int idx = n * NGAUSS + g;
#pragma unroll
        for (int j = 0; j < 3; j++) {
            float off = tanhf(res[g * 3 + j] + perturb[g * 3 + j]) * 4.8828125e-4f;
            float xb  = ((float)coords[n * 4 + 1 + j] + 0.5f) * 0.0625f;
            out[idx * 3 + j]          = xb + off;
            out[49152 + idx * 3 + j]  = res[12 + g * 3 + j];
            out[98304 + idx * 3 + j]  = res[24 + g * 3 + j];
        }
#pragma unroll
        for (int j = 0; j < 4; j++)
            out[147456 + idx * 4 + j] = res[36 + g * 4 + j];
        out[212992 + idx] = res[52 + g];
    }
}

// ------------------------------- launch ------------------------------------
extern "C" void kernel_launch(void* const* d_in, const int* in_sizes, int n_in,
                              void* d_out, int out_size)
{
    const float* feats   = (const float*)d_in[0];
    const int*   coords  = (const int*)  d_in[1];
    const float* emb_x   = (const float*)d_in[2];
    const float* emb_y   = (const float*)d_in[3];
    const float* emb_z   = (const float*)d_in[4];
    const float* w_in    = (const float*)d_in[5];
    const float* b_in    = (const float*)d_in[6];
    const float* ln1_g   = (const float*)d_in[7];
    const float* ln1_b   = (const float*)d_in[8];
    const float* w_qkv   = (const float*)d_in[9];
    const float* b_qkv   = (const float*)d_in[10];
    const float* w_o     = (const float*)d_in[11];
    const float* b_o     = (const float*)d_in[12];
    const float* ln2_g   = (const float*)d_in[13];
    const float* ln2_b   = (const float*)d_in[14];
    const float* w_m1    = (const float*)d_in[15];
    const float* b_m1    = (const float*)d_in[16];
    const float* w_m2    = (const float*)d_in[17];
    const float* b_m2    = (const float*)d_in[18];
    const float* w_out   = (const float*)d_in[19];
    const float* b_out   = (const float*)d_in[20];
    const float* perturb = (const float*)d_in[21];
    float* out = (float*)d_out;

    float *ph;
    __half *pah, *pqh, *poh, *pmh;
    __half *pwqh, *pwoh, *pw1h, *pw2h;
    cudaGetSymbolAddress((void**)&ph,   g_h);
    cudaGetSymbolAddress((void**)&pah,  g_ah);
    cudaGetSymbolAddress((void**)&pqh,  g_qh);
    cudaGetSymbolAddress((void**)&poh,  g_oh);
    cudaGetSymbolAddress((void**)&pmh,  g_mh);
    cudaGetSymbolAddress((void**)&pwqh, g_wqkv_h);
    cudaGetSymbolAddress((void**)&pwoh, g_wo_h);
    cudaGetSymbolAddress((void**)&pw1h, g_wm1_h);
    cudaGetSymbolAddress((void**)&pw2h, g_wm2_h);

    cudaFuncSetAttribute(attn_mma_kernel,
                         cudaFuncAttributeMaxDynamicSharedMemorySize, ATT_SMEM);
    cudaFuncSetAttribute(gemm_f16_kernel,
                         cudaFuncAttributeMaxDynamicSharedMemorySize, GSMEM_BYTES);

    {
        int n4q = LAYERS * CDIM * 3 * CDIM / 4;
        int n4o = LAYERS * CDIM * CDIM / 4;
        int n4m = LAYERS * CDIM * MLPDIM / 4;
        int tot = n4q + n4o + 2 * n4m;
        wcast_all_kernel<<<(tot + 255) / 256, 256>>>(
            w_qkv, pwqh, n4q, w_o, pwoh, n4o,
            w_m1, pw1h, n4m, w_m2, pw2h, n4m);
    }

    embed_kernel<<<NTOK, CDIM>>>(feats, coords, emb_x, emb_y, emb_z, w_in, b_in);

    for (int l = 0; l < LAYERS; l++) {
        ln_kernel<<<NTOK / 8, 256>>>(ph, ln1_g + l * CDIM, ln1_b + l * CDIM,
                                     pah, 1e-6f);
        gemm_f16_kernel<<<dim3(3 * CDIM / BN, NTOK / BM), 256, GSMEM_BYTES>>>(
            pah, pwqh + (size_t)l * CDIM * 3 * CDIM,
            b_qkv + l * 3 * CDIM, nullptr, pqh,
            NTOK, 3 * CDIM, CDIM, 3);
        attn_mma_kernel<<<dim3(8, HEADS, 8), 128, ATT_SMEM>>>(pqh, poh);
        gemm_f16_kernel<<<dim3(CDIM / BN, NTOK / BM), 256, GSMEM_BYTES>>>(
            poh, pwoh + (size_t)l * CDIM * CDIM,
            b_o + l * CDIM, ph, nullptr,
            NTOK, CDIM, CDIM, 1);
        ln_kernel<<<NTOK / 8, 256>>>(ph, ln2_g + l * CDIM, ln2_b + l * CDIM,
                                     pah, 1e-6f);
        gemm_f16_kernel<<<dim3(MLPDIM / BN, NTOK / BM), 256, GSMEM_BYTES>>>(
            pah, pw1h + (size_t)l * CDIM * MLPDIM,
            b_m1 + l * MLPDIM, nullptr, pmh,
            NTOK, MLPDIM, CDIM, 2);
        gemm_f16_kernel<<<dim3(CDIM / BN, NTOK / BM), 256, GSMEM_BYTES>>>(
            pmh, pw2h + (size_t)l * MLPDIM * CDIM,
            b_m2 + l * CDIM, ph, nullptr,
            NTOK, CDIM, MLPDIM, 1);
    }

    tail_kernel<<<NTOK, 64>>>(ph, w_out, b_out, coords, perturb, out);
}

// round 13
// speedup vs baseline: 2.2384x; 1.0239x over previous
#include <cuda_runtime.h>
#include <cuda_fp16.h>
#include <math.h>
#include <stdint.h>

// ---------------------------------------------------------------------------
// GSDecoder round 13: round-12 numerics + GEMM latency/wave fixes:
//  - 3-stage cp.async pipeline (prefetch distance 2)
//  - templated tile height: BM=128 (qkv, mlp1) / BM=64 (wo, mlp2 -> 256 blocks)
// ---------------------------------------------------------------------------

#define NTOK   4096
#define CDIM   512
#define HEADS  8
#define DHEAD  64
#define LAYERS 8
#define MLPDIM 2048
#define OUTC   56
#define NGAUSS 4

#define ASCALE     256.0f
#define INV_ASCALE 0.00390625f
#define QK_SCALE   1.9073486328125e-6f   // 1/(256*256) / 8

// ------------------------- scratch (device globals) ------------------------
__device__ float g_h  [NTOK * CDIM];

__device__ __half g_ah[NTOK * CDIM];
__device__ __half g_qh[NTOK * 3 * CDIM];
__device__ __half g_oh[NTOK * CDIM];
__device__ __half g_mh[NTOK * MLPDIM];

__device__ __half g_wqkv_h[LAYERS * CDIM * 3 * CDIM];
__device__ __half g_wo_h  [LAYERS * CDIM * CDIM];
__device__ __half g_wm1_h [LAYERS * CDIM * MLPDIM];
__device__ __half g_wm2_h [LAYERS * MLPDIM * CDIM];

// ------------------------------ helpers ------------------------------------
__device__ __forceinline__ float gelu_f(float x) {
    float x3 = x * x * x;
    return 0.5f * x * (1.0f + tanhf(0.7978845608028654f * (x + 0.044715f * x3)));
}

__device__ __forceinline__ void ldsm_x4(unsigned* r, unsigned addr) {
    asm volatile("ldmatrix.sync.aligned.m8n8.x4.shared.b16 {%0,%1,%2,%3}, [%4];"
                 : "=r"(r[0]), "=r"(r[1]), "=r"(r[2]), "=r"(r[3]) : "r"(addr));
}
__device__ __forceinline__ void ldsm_x4t(unsigned* r, unsigned addr) {
    asm volatile("ldmatrix.sync.aligned.m8n8.x4.trans.shared.b16 {%0,%1,%2,%3}, [%4];"
                 : "=r"(r[0]), "=r"(r[1]), "=r"(r[2]), "=r"(r[3]) : "r"(addr));
}
__device__ __forceinline__ void ldsm_x2t(unsigned* r, unsigned addr) {
    asm volatile("ldmatrix.sync.aligned.m8n8.x2.trans.shared.b16 {%0,%1}, [%2];"
                 : "=r"(r[0]), "=r"(r[1]) : "r"(addr));
}
__device__ __forceinline__ void mma16816h(float* c, const unsigned* a, const unsigned* b) {
    asm volatile("mma.sync.aligned.m16n8k16.row.col.f32.f16.f16.f32 "
                 "{%0,%1,%2,%3}, {%4,%5,%6,%7}, {%8,%9}, {%0,%1,%2,%3};"
                 : "+f"(c[0]), "+f"(c[1]), "+f"(c[2]), "+f"(c[3])
                 : "r"(a[0]), "r"(a[1]), "r"(a[2]), "r"(a[3]),
                   "r"(b[0]), "r"(b[1]));
}
__device__ __forceinline__ void cpa16(unsigned dst, const void* src) {
    asm volatile("cp.async.cg.shared.global [%0], [%1], 16;" :: "r"(dst), "l"(src));
}
__device__ __forceinline__ void cpa_commit() { asm volatile("cp.async.commit_group;"); }
template <int NWAIT>
__device__ __forceinline__ void cpa_wait() {
    asm volatile("cp.async.wait_group %0;" :: "n"(NWAIT));
}

__device__ __forceinline__ unsigned pack_h2(float x, float y) {
    __half2 H = __halves2half2(__float2half_rn(x * ASCALE), __float2half_rn(y * ASCALE));
    return *(unsigned*)&H;
}

// ----------------------- merged weight fp16 cast ---------------------------
__global__ void wcast_all_kernel(const float* __restrict__ s0, __half* __restrict__ d0, int n0,
                                 const float* __restrict__ s1, __half* __restrict__ d1, int n1,
                                 const float* __restrict__ s2, __half* __restrict__ d2, int n2,
                                 const float* __restrict__ s3, __half* __restrict__ d3, int n3)
{
    int i = blockIdx.x * 256 + threadIdx.x;
    const float* src; __half* dst;
    if (i < n0)                 { src = s0; dst = d0; }
    else if ((i -= n0) < n1)    { src = s1; dst = d1; }
    else if ((i -= n1) < n2)    { src = s2; dst = d2; }
    else if ((i -= n2) < n3)    { src = s3; dst = d3; }
    else return;
    float4 v = ((const float4*)src)[i];
    __half2 a = __halves2half2(__float2half_rn(v.x), __float2half_rn(v.y));
    __half2 b = __halves2half2(__float2half_rn(v.z), __float2half_rn(v.w));
    ((__half2*)dst)[i * 2]     = a;
    ((__half2*)dst)[i * 2 + 1] = b;
}

// ------------------------------ embed + PE ---------------------------------
__global__ void embed_kernel(const float* __restrict__ feats,
                             const int*   __restrict__ coords,
                             const float* __restrict__ ex,
                             const float* __restrict__ ey,
                             const float* __restrict__ ez,
                             const float* __restrict__ w_in,
                             const float* __restrict__ b_in)
{
    int n = blockIdx.x;
    int c = threadIdx.x;
    const float* f = feats + (size_t)n * 8;
    float acc = b_in[c];
#pragma unroll
    for (int l = 0; l < 8; l++) acc += f[l] * w_in[l * CDIM + c];

    int cx = coords[n * 4 + 1];
    int cy = coords[n * 4 + 2];
    int cz = coords[n * 4 + 3];
    float pe;
    if (c < 170)      pe = ex[cx * 170 + c];
    else if (c < 340) pe = ey[cy * 170 + (c - 170)];
    else              pe = ez[cz * 172 + (c - 340)];
    g_h[(size_t)n * CDIM + c] = acc + pe;
}

// ----------------------- warp-per-row layernorm ----------------------------
__global__ void __launch_bounds__(256)
ln_kernel(const float* __restrict__ x,
          const float* __restrict__ g,
          const float* __restrict__ b,
          __half* __restrict__ oh,
          float eps)
{
    int warp = threadIdx.x >> 5;
    int lane = threadIdx.x & 31;
    int n = blockIdx.x * 8 + warp;
    const float4* xr = (const float4*)(x + (size_t)n * CDIM);

    float4 v[4];
    float s = 0.f, s2 = 0.f;
#pragma unroll
    for (int k = 0; k < 4; k++) {
        v[k] = xr[lane + k * 32];
        s  += v[k].x + v[k].y + v[k].z + v[k].w;
        s2 += v[k].x * v[k].x + v[k].y * v[k].y
            + v[k].z * v[k].z + v[k].w * v[k].w;
    }
#pragma unroll
    for (int off = 16; off; off >>= 1) {
        s  += __shfl_xor_sync(0xffffffffu, s,  off);
        s2 += __shfl_xor_sync(0xffffffffu, s2, off);
    }
    float mean = s * (1.0f / 512.0f);
    float var  = s2 * (1.0f / 512.0f) - mean * mean;
    if (var < 0.f) var = 0.f;
    float r = rsqrtf(var + eps);

#pragma unroll
    for (int k = 0; k < 4; k++) {
        int c = (lane + k * 32) * 4;
        float4 gv = *(const float4*)(g + c);
        float4 bv = *(const float4*)(b + c);
        float o0 = (v[k].x - mean) * r * gv.x + bv.x;
        float o1 = (v[k].y - mean) * r * gv.y + bv.y;
        float o2 = (v[k].z - mean) * r * gv.z + bv.z;
        float o3 = (v[k].w - mean) * r * gv.w + bv.w;
        uint2 pk;
        pk.x = pack_h2(o0, o1);
        pk.y = pack_h2(o2, o3);
        *(uint2*)(oh + (size_t)n * CDIM + c) = pk;
    }
}

// ------- single-pass fp16 GEMM, 3-stage pipeline, templated tile height ----
// MB = 16-row m-blocks per warp (4 -> BM=128, 2 -> BM=64). BN=128, BK=32.
#define BN 128
#define BK2 32
#define ASTR2 40
#define BSTR2 136

template<int MB>
__global__ void __launch_bounds__(256, 2)
gemm_f16_kernel(const __half* __restrict__ Ah,
                const __half* __restrict__ Bh,
                const float* __restrict__ bias, float* __restrict__ Cf,
                __half* __restrict__ Ch,
                int M, int N, int K, int epi)
{
    constexpr int BMT  = 32 * MB;            // tile height
    constexpr int A_PL = BMT * ASTR2;        // halves
    constexpr int B_PL = 32 * BSTR2;
    constexpr int STG3 = A_PL + B_PL;

    extern __shared__ __align__(16) __half smemh[];

    const int tid  = threadIdx.x;
    const int wid  = tid >> 5;
    const int lane = tid & 31;
    const int n0 = blockIdx.x * BN;
    const int m0 = blockIdx.y * BMT;
    const int wm = (wid >> 2) * (16 * MB);
    const int wn = (wid & 3) * 32;

    float acc[MB][4][4];
#pragma unroll
    for (int i = 0; i < MB; i++)
#pragma unroll
        for (int j = 0; j < 4; j++)
#pragma unroll
            for (int k = 0; k < 4; k++) acc[i][j][k] = 0.f;

    const int a_row = tid >> 2,  a_off = (tid & 3) << 3;
    const int b_row = tid >> 3,  b_c = (tid & 7) << 4;

    auto stage = [&](int s, int k0) {
        __half* base = smemh + s * STG3;
        cpa16((unsigned)__cvta_generic_to_shared(base + a_row * ASTR2 + a_off),
              Ah + (size_t)(m0 + a_row) * K + k0 + a_off);
        if (MB == 4)
            cpa16((unsigned)__cvta_generic_to_shared(base + (a_row + 64) * ASTR2 + a_off),
                  Ah + (size_t)(m0 + a_row + 64) * K + k0 + a_off);
        __half* d = base + A_PL;
        cpa16((unsigned)__cvta_generic_to_shared(d + b_row * BSTR2 + b_c),
              Bh + (size_t)(k0 + b_row) * N + n0 + b_c);
        cpa16((unsigned)__cvta_generic_to_shared(d + b_row * BSTR2 + b_c + 8),
              Bh + (size_t)(k0 + b_row) * N + n0 + b_c + 8);
        cpa_commit();
    };

    const int KT = K / BK2;
    stage(0, 0);
    stage(1, BK2);
    int sbuf = 2;
    for (int kt = 0; kt < KT; kt++) {
        if (kt + 1 < KT) cpa_wait<1>();
        else             cpa_wait<0>();
        __syncthreads();

        int buf = kt % 3;
        if (kt + 2 < KT) {
            stage(sbuf, (kt + 2) * BK2);
            sbuf = (sbuf + 1) % 3;
        }

        __half* base = smemh + buf * STG3;
        unsigned aH = (unsigned)__cvta_generic_to_shared(
            base + (wm + (lane & 15)) * ASTR2 + ((lane >> 4) << 3));
        unsigned bH = (unsigned)__cvta_generic_to_shared(
            base + A_PL + (lane & 15) * BSTR2 + wn);

#pragma unroll
        for (int ks = 0; ks < 2; ks++) {
            unsigned bh[4][2];
#pragma unroll
            for (int nb = 0; nb < 4; nb++) {
                unsigned off = (unsigned)(ks * 16 * BSTR2) * 2 + nb * 16;
                ldsm_x2t(bh[nb], bH + off);
            }
#pragma unroll
            for (int mb = 0; mb < MB; mb++) {
                unsigned ah[4];
                unsigned off = (unsigned)(mb * 16 * ASTR2 + ks * 16) * 2;
                ldsm_x4(ah, aH + off);
#pragma unroll
                for (int nb = 0; nb < 4; nb++)
                    mma16816h(acc[mb][nb], ah, bh[nb]);
            }
        }
        __syncthreads();
    }

#pragma unroll
    for (int mb = 0; mb < MB; mb++) {
        int m = m0 + wm + mb * 16 + (lane >> 2);
#pragma unroll
        for (int nb = 0; nb < 4; nb++) {
            int n = n0 + wn + nb * 8 + ((lane & 3) << 1);
            float2 bv = *(const float2*)(bias + n);
            float c0 = acc[mb][nb][0] * INV_ASCALE + bv.x;
            float c1 = acc[mb][nb][1] * INV_ASCALE + bv.y;
            float c2 = acc[mb][nb][2] * INV_ASCALE + bv.x;
            float c3 = acc[mb][nb][3] * INV_ASCALE + bv.y;
            if (epi >= 2) {
                if (epi == 2) {
                    c0 = gelu_f(c0); c1 = gelu_f(c1);
                    c2 = gelu_f(c2); c3 = gelu_f(c3);
                }
                *(unsigned*)(Ch + (size_t)m * N + n)       = pack_h2(c0, c1);
                *(unsigned*)(Ch + (size_t)(m + 8) * N + n) = pack_h2(c2, c3);
            } else {
                float* p0 = Cf + (size_t)m * N + n;
                float* p1 = Cf + (size_t)(m + 8) * N + n;
                if (epi == 1) {
                    float2 r0 = *(float2*)p0;
                    float2 r1 = *(float2*)p1;
                    c0 += r0.x; c1 += r0.y; c2 += r1.x; c3 += r1.y;
                }
                *(float2*)p0 = make_float2(c0, c1);
                *(float2*)p1 = make_float2(c2, c3);
            }
        }
    }
}

#define GSMEM_128 (3 * (128 * ASTR2 + 32 * BSTR2) * 2)
#define GSMEM_64  (3 * (64 * ASTR2 + 32 * BSTR2) * 2)

// ---- flash attention: single-pass fp16, double-buffered K/V staging -------
#define ASTR 88
#define TILE_H (64 * ASTR)
#define AQH  0
#define AKV0 TILE_H
#define ATT_SMEM (5 * TILE_H * 2)

__global__ void __launch_bounds__(128)
attn_mma_kernel(const __half* __restrict__ qkvh,
                __half* __restrict__ oh)
{
    extern __shared__ __align__(16) __half sm[];
    const int tid  = threadIdx.x;
    const int wid  = tid >> 5;
    const int lane = tid & 31;
    const int qt = blockIdx.x, h = blockIdx.y, w = blockIdx.z;
    const int tok0 = w * 512;
    const int q0   = qt * 64;
    const int qoff = h * DHEAD;
    const int koff = CDIM + h * DHEAD;
    const int voff = 2 * CDIM + h * DHEAD;
    const int wm   = wid * 16;

    const unsigned sQH = (unsigned)__cvta_generic_to_shared(&sm[AQH]);
    const unsigned sKV = (unsigned)__cvta_generic_to_shared(&sm[AKV0]);

#pragma unroll
    for (int i = 0; i < 4; i++) {
        int id = tid + i * 128;
        int r = id >> 3, c = (id & 7) << 3;
        cpa16(sQH + (unsigned)(r * ASTR + c) * 2,
              qkvh + (size_t)(tok0 + q0 + r) * (3 * CDIM) + qoff + c);
    }
    cpa_commit();

    const int st_r = tid >> 3, st_c = (tid & 7) << 3;
    auto stageKV = [&](int buf, int kt) {
        unsigned base = sKV + (unsigned)(buf * 2 * TILE_H) * 2;
#pragma unroll
        for (int i = 0; i < 4; i++) {
            int r = st_r + i * 16;
            size_t rowb = (size_t)(tok0 + kt * 64 + r) * (3 * CDIM);
            unsigned doff = (unsigned)(r * ASTR + st_c) * 2;
            cpa16(base + doff, qkvh + rowb + koff + st_c);
            cpa16(base + (unsigned)TILE_H * 2 + doff, qkvh + rowb + voff + st_c);
        }
        cpa_commit();
    };

    stageKV(0, 0);
    cpa_wait<1>();
    __syncthreads();

    unsigned qh[4][4];
    {
        int row = wm + (lane & 15);
        int coloff = (lane >> 4) << 3;
#pragma unroll
        for (int ks = 0; ks < 4; ks++)
            ldsm_x4(qh[ks], sQH + (unsigned)(row * ASTR + ks * 16 + coloff) * 2);
    }

    float m0 = -1e30f, m1 = -1e30f, l0 = 0.f, l1 = 0.f;
    float oacc[8][4];
#pragma unroll
    for (int i = 0; i < 8; i++)
#pragma unroll
        for (int j = 0; j < 4; j++) oacc[i][j] = 0.f;

    const int k_key  = ((lane >> 4) << 3) + (lane & 7);
    const int k_kc   = ((lane >> 3) & 1) << 3;
    const int v_kr   = (((lane >> 3) & 1) << 3) + (lane & 7);
    const int v_col  = (lane >> 4) << 3;

    for (int kt = 0; kt < 8; kt++) {
        if (kt + 1 < 8) { stageKV((kt + 1) & 1, kt + 1); cpa_wait<1>(); }
        else            { cpa_wait<0>(); }
        __syncthreads();

        unsigned sKH = sKV + (unsigned)((kt & 1) * 2 * TILE_H) * 2;
        unsigned sVH = sKH + (unsigned)TILE_H * 2;

        float s[8][4];
#pragma unroll
        for (int i = 0; i < 8; i++)
#pragma unroll
            for (int j = 0; j < 4; j++) s[i][j] = 0.f;

#pragma unroll
        for (int p = 0; p < 4; p++) {
#pragma unroll
            for (int ks = 0; ks < 4; ks++) {
                unsigned kb[4];
                unsigned off = (unsigned)((p * 16 + k_key) * ASTR + ks * 16 + k_kc) * 2;
                ldsm_x4(kb, sKH + off);
                mma16816h(s[2 * p],     qh[ks], &kb[0]);
                mma16816h(s[2 * p + 1], qh[ks], &kb[2]);
            }
        }

        float mx0 = -1e30f, mx1 = -1e30f;
#pragma unroll
        for (int nb = 0; nb < 8; nb++) {
            s[nb][0] *= QK_SCALE; s[nb][1] *= QK_SCALE;
            s[nb][2] *= QK_SCALE; s[nb][3] *= QK_SCALE;
            mx0 = fmaxf(mx0, fmaxf(s[nb][0], s[nb][1]));
            mx1 = fmaxf(mx1, fmaxf(s[nb][2], s[nb][3]));
        }
        mx0 = fmaxf(mx0, __shfl_xor_sync(0xffffffffu, mx0, 1));
        mx0 = fmaxf(mx0, __shfl_xor_sync(0xffffffffu, mx0, 2));
        mx1 = fmaxf(mx1, __shfl_xor_sync(0xffffffffu, mx1, 1));
        mx1 = fmaxf(mx1, __shfl_xor_sync(0xffffffffu, mx1, 2));

        float nm0 = fmaxf(m0, mx0);
        float nm1 = fmaxf(m1, mx1);
        float al0 = __expf(m0 - nm0);
        float al1 = __expf(m1 - nm1);
        m0 = nm0; m1 = nm1;

        float sum0 = 0.f, sum1 = 0.f;
#pragma unroll
        for (int nb = 0; nb < 8; nb++) {
            s[nb][0] = __expf(s[nb][0] - nm0);
            s[nb][1] = __expf(s[nb][1] - nm0);
            s[nb][2] = __expf(s[nb][2] - nm1);
            s[nb][3] = __expf(s[nb][3] - nm1);
            sum0 += s[nb][0] + s[nb][1];
            sum1 += s[nb][2] + s[nb][3];
        }
        sum0 += __shfl_xor_sync(0xffffffffu, sum0, 1);
        sum0 += __shfl_xor_sync(0xffffffffu, sum0, 2);
        sum1 += __shfl_xor_sync(0xffffffffu, sum1, 1);
        sum1 += __shfl_xor_sync(0xffffffffu, sum1, 2);
        l0 = l0 * al0 + sum0;
        l1 = l1 * al1 + sum1;

#pragma unroll
        for (int nb = 0; nb < 8; nb++) {
            oacc[nb][0] *= al0; oacc[nb][1] *= al0;
            oacc[nb][2] *= al1; oacc[nb][3] *= al1;
        }

#pragma unroll
        for (int kk = 0; kk < 4; kk++) {
            unsigned pa[4];
            pa[0] = pack_h2(s[2 * kk][0],     s[2 * kk][1]);
            pa[1] = pack_h2(s[2 * kk][2],     s[2 * kk][3]);
            pa[2] = pack_h2(s[2 * kk + 1][0], s[2 * kk + 1][1]);
            pa[3] = pack_h2(s[2 * kk + 1][2], s[2 * kk + 1][3]);
#pragma unroll
            for (int p = 0; p < 4; p++) {
                unsigned vb[4];
                unsigned off = (unsigned)((kk * 16 + v_kr) * ASTR + p * 16 + v_col) * 2;
                ldsm_x4t(vb, sVH + off);
                mma16816h(oacc[2 * p],     pa, &vb[0]);
                mma16816h(oacc[2 * p + 1], pa, &vb[2]);
            }
        }
        __syncthreads();
    }

    float i0 = 1.0f / (65536.0f * l0);
    float i1 = 1.0f / (65536.0f * l1);
    int r0  = tok0 + q0 + wm + (lane >> 2);
    int col = h * DHEAD + ((lane & 3) << 1);
#pragma unroll
    for (int nb = 0; nb < 8; nb++) {
        size_t p0 = (size_t)r0 * CDIM + col + nb * 8;
        size_t p1 = (size_t)(r0 + 8) * CDIM + col + nb * 8;
        *(unsigned*)(oh + p0) = pack_h2(oacc[nb][0] * i0, oacc[nb][1] * i0);
        *(unsigned*)(oh + p1) = pack_h2(oacc[nb][2] * i1, oacc[nb][3] * i1);
    }
}

// ------------- fused tail: final LN + out-head GEMV + postprocess ----------
__global__ void __launch_bounds__(64)
tail_kernel(const float* __restrict__ hbuf,
            const float* __restrict__ w,
            const float* __restrict__ bo,
            const int*   __restrict__ coords,
            const float* __restrict__ perturb,
            float* __restrict__ out)
{
    __shared__ float row[CDIM];
    __shared__ float ws[4];
    __shared__ float res[OUTC];

    int n = blockIdx.x;
    int tid = threadIdx.x;
    int warp = tid >> 5, lane = tid & 31;

    const float4* xr = (const float4*)(hbuf + (size_t)n * CDIM);
    float4 v0 = xr[tid];
    float4 v1 = xr[tid + 64];
    float s  = v0.x + v0.y + v0.z + v0.w + v1.x + v1.y + v1.z + v1.w;
    float s2 = v0.x * v0.x + v0.y * v0.y + v0.z * v0.z + v0.w * v0.w
             + v1.x * v1.x + v1.y * v1.y + v1.z * v1.z + v1.w * v1.w;
#pragma unroll
    for (int off = 16; off; off >>= 1) {
        s  += __shfl_xor_sync(0xffffffffu, s,  off);
        s2 += __shfl_xor_sync(0xffffffffu, s2, off);
    }
    if (lane == 0) { ws[warp] = s; ws[warp + 2] = s2; }
    __syncthreads();
    float ts  = ws[0] + ws[1];
    float ts2 = ws[2] + ws[3];
    float mean = ts * (1.0f / 512.0f);
    float var  = ts2 * (1.0f / 512.0f) - mean * mean;
    if (var < 0.f) var = 0.f;
    float r = rsqrtf(var + 1e-5f);

    *(float4*)(row + tid * 4) =
        make_float4((v0.x - mean) * r, (v0.y - mean) * r,
                    (v0.z - mean) * r, (v0.w - mean) * r);
    *(float4*)(row + 256 + tid * 4) =
        make_float4((v1.x - mean) * r, (v1.y - mean) * r,
                    (v1.z - mean) * r, (v1.w - mean) * r);
    __syncthreads();

    if (tid < OUTC) {
        float acc = bo[tid];
#pragma unroll 8
        for (int k = 0; k < CDIM; k++)
            acc += row[k] * w[k * OUTC + tid];
        res[tid] = acc;
    }
    __syncthreads();

    if (tid < NGAUSS) {
        int g = tid;
        int idx = n * NGAUSS + g;
#pragma unroll
        for (int j = 0; j < 3; j++) {
            float off = tanhf(res[g * 3 + j] + perturb[g * 3 + j]) * 4.8828125e-4f;
            float xb  = ((float)coords[n * 4 + 1 + j] + 0.5f) * 0.0625f;
            out[idx * 3 + j]          = xb + off;
            out[49152 + idx * 3 + j]  = res[12 + g * 3 + j];
            out[98304 + idx * 3 + j]  = res[24 + g * 3 + j];
        }
#pragma unroll
        for (int j = 0; j < 4; j++)
            out[147456 + idx * 4 + j] = res[36 + g * 4 + j];
        out[212992 + idx] = res[52 + g];
    }
}

// ------------------------------- launch ------------------------------------
extern "C" void kernel_launch(void* const* d_in, const int* in_sizes, int n_in,
                              void* d_out, int out_size)
{
    const float* feats   = (const float*)d_in[0];
    const int*   coords  = (const int*)  d_in[1];
    const float* emb_x   = (const float*)d_in[2];
    const float* emb_y   = (const float*)d_in[3];
    const float* emb_z   = (const float*)d_in[4];
    const float* w_in    = (const float*)d_in[5];
    const float* b_in    = (const float*)d_in[6];
    const float* ln1_g   = (const float*)d_in[7];
    const float* ln1_b   = (const float*)d_in[8];
    const float* w_qkv   = (const float*)d_in[9];
    const float* b_qkv   = (const float*)d_in[10];
    const float* w_o     = (const float*)d_in[11];
    const float* b_o     = (const float*)d_in[12];
    const float* ln2_g   = (const float*)d_in[13];
    const float* ln2_b   = (const float*)d_in[14];
    const float* w_m1    = (const float*)d_in[15];
    const float* b_m1    = (const float*)d_in[16];
    const float* w_m2    = (const float*)d_in[17];
    const float* b_m2    = (const float*)d_in[18];
    const float* w_out   = (const float*)d_in[19];
    const float* b_out   = (const float*)d_in[20];
    const float* perturb = (const float*)d_in[21];
    float* out = (float*)d_out;

    float *ph;
    __half *pah, *pqh, *poh, *pmh;
    __half *pwqh, *pwoh, *pw1h, *pw2h;
    cudaGetSymbolAddress((void**)&ph,   g_h);
    cudaGetSymbolAddress((void**)&pah,  g_ah);
    cudaGetSymbolAddress((void**)&pqh,  g_qh);
    cudaGetSymbolAddress((void**)&poh,  g_oh);
    cudaGetSymbolAddress((void**)&pmh,  g_mh);
    cudaGetSymbolAddress((void**)&pwqh, g_wqkv_h);
    cudaGetSymbolAddress((void**)&pwoh, g_wo_h);
    cudaGetSymbolAddress((void**)&pw1h, g_wm1_h);
    cudaGetSymbolAddress((void**)&pw2h, g_wm2_h);

    cudaFuncSetAttribute(attn_mma_kernel,
                         cudaFuncAttributeMaxDynamicSharedMemorySize, ATT_SMEM);
    cudaFuncSetAttribute(gemm_f16_kernel<4>,
                         cudaFuncAttributeMaxDynamicSharedMemorySize, GSMEM_128);
    cudaFuncSetAttribute(gemm_f16_kernel<2>,
                         cudaFuncAttributeMaxDynamicSharedMemorySize, GSMEM_64);

    {
        int n4q = LAYERS * CDIM * 3 * CDIM / 4;
        int n4o = LAYERS * CDIM * CDIM / 4;
        int n4m = LAYERS * CDIM * MLPDIM / 4;
        int tot = n4q + n4o + 2 * n4m;
        wcast_all_kernel<<<(tot + 255) / 256, 256>>>(
            w_qkv, pwqh, n4q, w_o, pwoh, n4o,
            w_m1, pw1h, n4m, w_m2, pw2h, n4m);
    }

    embed_kernel<<<NTOK, CDIM>>>(feats, coords, emb_x, emb_y, emb_z, w_in, b_in);

    for (int l = 0; l < LAYERS; l++) {
        ln_kernel<<<NTOK / 8, 256>>>(ph, ln1_g + l * CDIM, ln1_b + l * CDIM,
                                     pah, 1e-6f);
        gemm_f16_kernel<4><<<dim3(3 * CDIM / BN, NTOK / 128), 256, GSMEM_128>>>(
            pah, pwqh + (size_t)l * CDIM * 3 * CDIM,
            b_qkv + l * 3 * CDIM, nullptr, pqh,
            NTOK, 3 * CDIM, CDIM, 3);
        attn_mma_kernel<<<dim3(8, HEADS, 8), 128, ATT_SMEM>>>(pqh, poh);
        gemm_f16_kernel<2><<<dim3(CDIM / BN, NTOK / 64), 256, GSMEM_64>>>(
            poh, pwoh + (size_t)l * CDIM * CDIM,
            b_o + l * CDIM, ph, nullptr,
            NTOK, CDIM, CDIM, 1);
        ln_kernel<<<NTOK / 8, 256>>>(ph, ln2_g + l * CDIM, ln2_b + l * CDIM,
                                     pah, 1e-6f);
        gemm_f16_kernel<4><<<dim3(MLPDIM / BN, NTOK / 128), 256, GSMEM_128>>>(
            pah, pw1h + (size_t)l * CDIM * MLPDIM,
            b_m1 + l * MLPDIM, nullptr, pmh,
            NTOK, MLPDIM, CDIM, 2);
        gemm_f16_kernel<2><<<dim3(CDIM / BN, NTOK / 64), 256, GSMEM_64>>>(
            pmh, pw2h + (size_t)l * MLPDIM * CDIM,
            b_m2 + l * CDIM, ph, nullptr,
            NTOK, CDIM, MLPDIM, 1);
    }

    tail_kernel<<<NTOK, 64>>>(ph, w_out, b_out, coords, perturb, out);
}